// round 1
// baseline (speedup 1.0000x reference)
#include <cuda_runtime.h>
#include <cstdint>

// ---------------- scratch (no allocations allowed) ----------------
#define S_LEN 4096
#define EMB   768
#define NHEAD 12
#define HDIM  64

__device__ float g_Q[NHEAD * S_LEN * HDIM];   // [H][S][D]
__device__ float g_K[NHEAD * S_LEN * HDIM];
__device__ float g_V[NHEAD * S_LEN * HDIM];
__device__ float g_att[S_LEN * EMB];          // [S][E] (head-concat)

// ---------------- SGEMM: C = A @ B^T + bias ----------------
// A [M,K] row-major, B [N,K] row-major, both K-contiguous (NT gemm).
// permute==1: write C[(h*M + m)*64 + d] with h=n/64, d=n%64 (head-major QKV)
// permute==0: write C[m*N + n]
#define TM 128
#define TN 128
#define TK 8

__global__ __launch_bounds__(256) void gemm_nt_bias(
    const float* __restrict__ A, const float* __restrict__ B,
    const float* __restrict__ bias, float* __restrict__ C,
    int M, int N, int K, int permute)
{
    __shared__ float As[TK][TM];
    __shared__ float Bs[TK][TN];

    const int tid = threadIdx.x;
    const int bm = blockIdx.y * TM;
    const int bn = blockIdx.x * TN;
    const int tx = tid & 15;       // 0..15 -> 8 cols each
    const int ty = tid >> 4;       // 0..15 -> 8 rows each

    const int lrow = tid >> 1;          // 0..127
    const int lcol = (tid & 1) * 4;     // 0 or 4

    const float* Aptr = A + (size_t)(bm + lrow) * K + lcol;
    const float* Bptr = B + (size_t)(bn + lrow) * K + lcol;

    float acc[8][8];
    #pragma unroll
    for (int i = 0; i < 8; i++)
        #pragma unroll
        for (int j = 0; j < 8; j++) acc[i][j] = 0.f;

    for (int k0 = 0; k0 < K; k0 += TK) {
        float4 av = *(const float4*)(Aptr + k0);
        float4 bv = *(const float4*)(Bptr + k0);
        As[lcol + 0][lrow] = av.x; As[lcol + 1][lrow] = av.y;
        As[lcol + 2][lrow] = av.z; As[lcol + 3][lrow] = av.w;
        Bs[lcol + 0][lrow] = bv.x; Bs[lcol + 1][lrow] = bv.y;
        Bs[lcol + 2][lrow] = bv.z; Bs[lcol + 3][lrow] = bv.w;
        __syncthreads();

        #pragma unroll
        for (int kk = 0; kk < TK; kk++) {
            float a[8], b[8];
            #pragma unroll
            for (int i = 0; i < 8; i++) a[i] = As[kk][ty * 8 + i];
            #pragma unroll
            for (int j = 0; j < 8; j++) b[j] = Bs[kk][tx * 8 + j];
            #pragma unroll
            for (int i = 0; i < 8; i++)
                #pragma unroll
                for (int j = 0; j < 8; j++) acc[i][j] += a[i] * b[j];
        }
        __syncthreads();
    }

    #pragma unroll
    for (int i = 0; i < 8; i++) {
        const int m = bm + ty * 8 + i;
        #pragma unroll
        for (int j = 0; j < 8; j++) {
            const int n = bn + tx * 8 + j;
            const float v = acc[i][j] + bias[n];
            if (permute) {
                const int h = n >> 6, d = n & 63;
                C[((size_t)h * M + m) * HDIM + d] = v;
            } else {
                C[(size_t)m * N + n] = v;
            }
        }
    }
}

// ---------------- Flash-style attention ----------------
// 1 thread = 1 query row. q[64], o[64] in registers. K/V tiles (64 rows) in smem.
// Streaming online softmax with branchy max-rescale.
__global__ __launch_bounds__(128) void attn_kernel(
    const float* __restrict__ Q, const float* __restrict__ K,
    const float* __restrict__ V, const unsigned char* __restrict__ mask,
    float* __restrict__ out)
{
    const int h = blockIdx.y;
    const int qi = blockIdx.x * 128 + threadIdx.x;

    const float* Qh = Q + (size_t)h * S_LEN * HDIM;
    const float* Kh = K + (size_t)h * S_LEN * HDIM;
    const float* Vh = V + (size_t)h * S_LEN * HDIM;

    __shared__ float Ks[64][HDIM];
    __shared__ float Vs[64][HDIM];
    __shared__ float madd[64];

    const float scale = rsqrtf((float)EMB);   // NOTE: reference scales by sqrt(embed_dim)

    float q[HDIM], o[HDIM];
    #pragma unroll
    for (int d = 0; d < HDIM; d += 4) {
        float4 t = *(const float4*)(Qh + (size_t)qi * HDIM + d);
        q[d + 0] = t.x * scale; q[d + 1] = t.y * scale;
        q[d + 2] = t.z * scale; q[d + 3] = t.w * scale;
    }
    #pragma unroll
    for (int d = 0; d < HDIM; d++) o[d] = 0.f;

    float m = -1e30f, l = 0.f;

    for (int k0 = 0; k0 < S_LEN; k0 += 64) {
        // cooperative tile load: 64x64 floats each, 128 threads x 8 float4
        #pragma unroll
        for (int i = 0; i < 8; i++) {
            const int idx = i * 512 + threadIdx.x * 4;   // 0..4092
            const int r = idx >> 6, c = idx & 63;
            *(float4*)&Ks[r][c] = *(const float4*)(Kh + (size_t)(k0 + r) * HDIM + c);
            *(float4*)&Vs[r][c] = *(const float4*)(Vh + (size_t)(k0 + r) * HDIM + c);
        }
        if (threadIdx.x < 64)
            madd[threadIdx.x] = mask[k0 + threadIdx.x] ? -1e30f : 0.f;
        __syncthreads();

        for (int j = 0; j < 64; j++) {
            float s = madd[j];
            #pragma unroll
            for (int d = 0; d < HDIM; d++) s += q[d] * Ks[j][d];

            if (s > m) {                      // rare (~ln(S) times per row)
                const float corr = __expf(m - s);
                m = s;
                l *= corr;
                #pragma unroll
                for (int d = 0; d < HDIM; d++) o[d] *= corr;
            }
            const float p = __expf(s - m);
            l += p;
            #pragma unroll
            for (int d = 0; d < HDIM; d++) o[d] += p * Vs[j][d];
        }
        __syncthreads();
    }

    const float inv = 1.0f / l;
    float* op = out + (size_t)qi * EMB + h * HDIM;
    #pragma unroll
    for (int d = 0; d < HDIM; d += 4) {
        float4 t;
        t.x = o[d + 0] * inv; t.y = o[d + 1] * inv;
        t.z = o[d + 2] * inv; t.w = o[d + 3] * inv;
        *(float4*)(op + d) = t;
    }
}

// ---------------- launch ----------------
extern "C" void kernel_launch(void* const* d_in, const int* in_sizes, int n_in,
                              void* d_out, int out_size)
{
    const float* x  = (const float*)d_in[0];
    const unsigned char* mask = (const unsigned char*)d_in[1];
    const float* Wq = (const float*)d_in[2];
    const float* bq = (const float*)d_in[3];
    const float* Wk = (const float*)d_in[4];
    const float* bk = (const float*)d_in[5];
    const float* Wv = (const float*)d_in[6];
    const float* bv = (const float*)d_in[7];
    const float* Wo = (const float*)d_in[8];
    const float* bo = (const float*)d_in[9];
    float* out = (float*)d_out;

    float *Qb, *Kb, *Vb, *Ab;
    cudaGetSymbolAddress((void**)&Qb, g_Q);
    cudaGetSymbolAddress((void**)&Kb, g_K);
    cudaGetSymbolAddress((void**)&Vb, g_V);
    cudaGetSymbolAddress((void**)&Ab, g_att);

    dim3 ggrid(EMB / TN, S_LEN / TM);   // (6, 32)
    gemm_nt_bias<<<ggrid, 256>>>(x, Wq, bq, Qb, S_LEN, EMB, EMB, 1);
    gemm_nt_bias<<<ggrid, 256>>>(x, Wk, bk, Kb, S_LEN, EMB, EMB, 1);
    gemm_nt_bias<<<ggrid, 256>>>(x, Wv, bv, Vb, S_LEN, EMB, EMB, 1);

    dim3 agrid(S_LEN / 128, NHEAD);     // (32, 12)
    attn_kernel<<<agrid, 128>>>(Qb, Kb, Vb, mask, Ab);

    gemm_nt_bias<<<ggrid, 256>>>(Ab, Wo, bo, out, S_LEN, EMB, EMB, 0);
}

// round 2
// speedup vs baseline: 2.1082x; 2.1082x over previous
#include <cuda_runtime.h>
#include <cuda_bf16.h>
#include <cstdint>

#define S_LEN 4096
#define EMB   768
#define NHEAD 12
#define HDIM  64

// ---------------- scratch (no allocations allowed) ----------------
__device__ __nv_bfloat16 g_Qhi[NHEAD * S_LEN * HDIM];   // [H][S][D]
__device__ __nv_bfloat16 g_Qlo[NHEAD * S_LEN * HDIM];
__device__ __nv_bfloat16 g_Khi[NHEAD * S_LEN * HDIM];   // [H][S][D]
__device__ __nv_bfloat16 g_Klo[NHEAD * S_LEN * HDIM];
__device__ __nv_bfloat16 g_Vhi[NHEAD * HDIM * S_LEN];   // [H][D][S]  (transposed!)
__device__ __nv_bfloat16 g_Vlo[NHEAD * HDIM * S_LEN];
__device__ float g_att[S_LEN * EMB];                    // [S][E] head-concat, fp32

// ---------------- SGEMM: C = A @ B^T + bias ----------------
// mode 0: C[m*N+n] fp32
// mode 1: bf16 split to Chi/Clo at [(n>>6)*M + m]*64 + (n&63)   (Q/K head-major)
// mode 2: bf16 split to Chi/Clo at n*M + m                      (V transposed)
#define TM 128
#define TN 128
#define TK 8

__global__ __launch_bounds__(256) void gemm_nt_bias(
    const float* __restrict__ A, const float* __restrict__ B,
    const float* __restrict__ bias, float* __restrict__ C,
    __nv_bfloat16* __restrict__ Chi, __nv_bfloat16* __restrict__ Clo,
    int M, int N, int K, int mode)
{
    __shared__ float As[TK][TM];
    __shared__ float Bs[TK][TN];

    const int tid = threadIdx.x;
    const int bm = blockIdx.y * TM;
    const int bn = blockIdx.x * TN;
    const int tx = tid & 15;
    const int ty = tid >> 4;

    const int lrow = tid >> 1;
    const int lcol = (tid & 1) * 4;

    const float* Aptr = A + (size_t)(bm + lrow) * K + lcol;
    const float* Bptr = B + (size_t)(bn + lrow) * K + lcol;

    float acc[8][8];
    #pragma unroll
    for (int i = 0; i < 8; i++)
        #pragma unroll
        for (int j = 0; j < 8; j++) acc[i][j] = 0.f;

    for (int k0 = 0; k0 < K; k0 += TK) {
        float4 av = *(const float4*)(Aptr + k0);
        float4 bv = *(const float4*)(Bptr + k0);
        As[lcol + 0][lrow] = av.x; As[lcol + 1][lrow] = av.y;
        As[lcol + 2][lrow] = av.z; As[lcol + 3][lrow] = av.w;
        Bs[lcol + 0][lrow] = bv.x; Bs[lcol + 1][lrow] = bv.y;
        Bs[lcol + 2][lrow] = bv.z; Bs[lcol + 3][lrow] = bv.w;
        __syncthreads();

        #pragma unroll
        for (int kk = 0; kk < TK; kk++) {
            float a[8], b[8];
            #pragma unroll
            for (int i = 0; i < 8; i++) a[i] = As[kk][ty * 8 + i];
            #pragma unroll
            for (int j = 0; j < 8; j++) b[j] = Bs[kk][tx * 8 + j];
            #pragma unroll
            for (int i = 0; i < 8; i++)
                #pragma unroll
                for (int j = 0; j < 8; j++) acc[i][j] += a[i] * b[j];
        }
        __syncthreads();
    }

    #pragma unroll
    for (int i = 0; i < 8; i++) {
        const int m = bm + ty * 8 + i;
        #pragma unroll
        for (int j = 0; j < 8; j++) {
            const int n = bn + tx * 8 + j;
            const float v = acc[i][j] + bias[n];
            if (mode == 0) {
                C[(size_t)m * N + n] = v;
            } else {
                __nv_bfloat16 hi = __float2bfloat16(v);
                __nv_bfloat16 lo = __float2bfloat16(v - __bfloat162float(hi));
                size_t idx;
                if (mode == 1) idx = ((size_t)(n >> 6) * M + m) * HDIM + (n & 63);
                else           idx = (size_t)n * M + m;
                Chi[idx] = hi;
                Clo[idx] = lo;
            }
        }
    }
}

// ---------------- tensor-core flash attention (bf16 split, fp32 accum) ----
__device__ __forceinline__ void mma16816(float* c, const uint32_t* a,
                                         uint32_t b0, uint32_t b1)
{
    asm volatile(
        "mma.sync.aligned.m16n8k16.row.col.f32.bf16.bf16.f32 "
        "{%0,%1,%2,%3},{%4,%5,%6,%7},{%8,%9},{%0,%1,%2,%3};"
        : "+f"(c[0]), "+f"(c[1]), "+f"(c[2]), "+f"(c[3])
        : "r"(a[0]), "r"(a[1]), "r"(a[2]), "r"(a[3]), "r"(b0), "r"(b1));
}

__global__ __launch_bounds__(256) void attn_mma(
    const __nv_bfloat16* __restrict__ Qhi, const __nv_bfloat16* __restrict__ Qlo,
    const __nv_bfloat16* __restrict__ Khi, const __nv_bfloat16* __restrict__ Klo,
    const __nv_bfloat16* __restrict__ Vhi, const __nv_bfloat16* __restrict__ Vlo,
    const unsigned char* __restrict__ mask, float* __restrict__ out)
{
    const int h   = blockIdx.y;
    const int q0  = blockIdx.x * 128;
    const int tid = threadIdx.x;
    const int wid = tid >> 5;
    const int lane = tid & 31;
    const int lq = lane >> 2;    // 0..7
    const int lk = lane & 3;     // 0..3

    __shared__ __nv_bfloat16 sKh[64][72];
    __shared__ __nv_bfloat16 sKl[64][72];
    __shared__ __nv_bfloat16 sVh[64][72];   // [d][key]
    __shared__ __nv_bfloat16 sVl[64][72];
    __shared__ float smadd[64];

    const size_t hoff = (size_t)h * S_LEN * HDIM;
    const float scale = rsqrtf((float)EMB);

    // ---- Q fragments (resident for whole kernel) ----
    const int qr = q0 + wid * 16 + lq;        // first of the 2 rows this thread owns
    uint32_t aQh[4][4], aQl[4][4];
    {
        const __nv_bfloat16* Qhp = Qhi + hoff;
        const __nv_bfloat16* Qlp = Qlo + hoff;
        #pragma unroll
        for (int kc = 0; kc < 4; kc++) {
            const int c = kc * 16 + lk * 2;
            aQh[kc][0] = *(const uint32_t*)&Qhp[(size_t)qr * 64 + c];
            aQh[kc][1] = *(const uint32_t*)&Qhp[(size_t)(qr + 8) * 64 + c];
            aQh[kc][2] = *(const uint32_t*)&Qhp[(size_t)qr * 64 + c + 8];
            aQh[kc][3] = *(const uint32_t*)&Qhp[(size_t)(qr + 8) * 64 + c + 8];
            aQl[kc][0] = *(const uint32_t*)&Qlp[(size_t)qr * 64 + c];
            aQl[kc][1] = *(const uint32_t*)&Qlp[(size_t)(qr + 8) * 64 + c];
            aQl[kc][2] = *(const uint32_t*)&Qlp[(size_t)qr * 64 + c + 8];
            aQl[kc][3] = *(const uint32_t*)&Qlp[(size_t)(qr + 8) * 64 + c + 8];
        }
    }

    float o[8][4];
    #pragma unroll
    for (int j = 0; j < 8; j++)
        #pragma unroll
        for (int i = 0; i < 4; i++) o[j][i] = 0.f;
    float mrow0 = -1e30f, mrow1 = -1e30f;
    float lrow0 = 0.f,    lrow1 = 0.f;

    const int trow = tid >> 2;            // 0..63
    const int tcol = (tid & 3) * 16;      // half offset

    for (int k0 = 0; k0 < S_LEN; k0 += 64) {
        // ---- cooperative tile load ----
        {
            const __nv_bfloat16* kh = Khi + hoff + (size_t)(k0 + trow) * 64 + tcol;
            const __nv_bfloat16* kl = Klo + hoff + (size_t)(k0 + trow) * 64 + tcol;
            const __nv_bfloat16* vh = Vhi + hoff + (size_t)trow * S_LEN + k0 + tcol;
            const __nv_bfloat16* vl = Vlo + hoff + (size_t)trow * S_LEN + k0 + tcol;
            *(uint4*)&sKh[trow][tcol]     = *(const uint4*)kh;
            *(uint4*)&sKh[trow][tcol + 8] = *(const uint4*)(kh + 8);
            *(uint4*)&sKl[trow][tcol]     = *(const uint4*)kl;
            *(uint4*)&sKl[trow][tcol + 8] = *(const uint4*)(kl + 8);
            *(uint4*)&sVh[trow][tcol]     = *(const uint4*)vh;
            *(uint4*)&sVh[trow][tcol + 8] = *(const uint4*)(vh + 8);
            *(uint4*)&sVl[trow][tcol]     = *(const uint4*)vl;
            *(uint4*)&sVl[trow][tcol + 8] = *(const uint4*)(vl + 8);
            if (tid < 64) smadd[tid] = mask[k0 + tid] ? -1e30f : 0.f;
        }
        __syncthreads();

        // ---- S = Q K^T (bf16 split, fp32 accum) ----
        float s[8][4];
        #pragma unroll
        for (int j = 0; j < 8; j++) {
            s[j][0] = s[j][1] = s[j][2] = s[j][3] = 0.f;
            #pragma unroll
            for (int kc = 0; kc < 4; kc++) {
                const int d = kc * 16 + lk * 2;
                uint32_t bh0 = *(const uint32_t*)&sKh[j * 8 + lq][d];
                uint32_t bh1 = *(const uint32_t*)&sKh[j * 8 + lq][d + 8];
                uint32_t bl0 = *(const uint32_t*)&sKl[j * 8 + lq][d];
                uint32_t bl1 = *(const uint32_t*)&sKl[j * 8 + lq][d + 8];
                mma16816(s[j], aQh[kc], bh0, bh1);
                mma16816(s[j], aQh[kc], bl0, bl1);
                mma16816(s[j], aQl[kc], bh0, bh1);
            }
        }

        // ---- scale + mask ----
        #pragma unroll
        for (int j = 0; j < 8; j++) {
            const float m0 = smadd[j * 8 + lk * 2];
            const float m1 = smadd[j * 8 + lk * 2 + 1];
            s[j][0] = s[j][0] * scale + m0;
            s[j][1] = s[j][1] * scale + m1;
            s[j][2] = s[j][2] * scale + m0;
            s[j][3] = s[j][3] * scale + m1;
        }

        // ---- online softmax ----
        float rm0 = -1e30f, rm1 = -1e30f;
        #pragma unroll
        for (int j = 0; j < 8; j++) {
            rm0 = fmaxf(rm0, fmaxf(s[j][0], s[j][1]));
            rm1 = fmaxf(rm1, fmaxf(s[j][2], s[j][3]));
        }
        rm0 = fmaxf(rm0, __shfl_xor_sync(0xffffffffu, rm0, 1));
        rm0 = fmaxf(rm0, __shfl_xor_sync(0xffffffffu, rm0, 2));
        rm1 = fmaxf(rm1, __shfl_xor_sync(0xffffffffu, rm1, 1));
        rm1 = fmaxf(rm1, __shfl_xor_sync(0xffffffffu, rm1, 2));

        const float mn0 = fmaxf(mrow0, rm0);
        const float mn1 = fmaxf(mrow1, rm1);
        const float corr0 = __expf(mrow0 - mn0);
        const float corr1 = __expf(mrow1 - mn1);
        mrow0 = mn0; mrow1 = mn1;

        float ps0 = 0.f, ps1 = 0.f;
        #pragma unroll
        for (int j = 0; j < 8; j++) {
            s[j][0] = __expf(s[j][0] - mn0);
            s[j][1] = __expf(s[j][1] - mn0);
            s[j][2] = __expf(s[j][2] - mn1);
            s[j][3] = __expf(s[j][3] - mn1);
            ps0 += s[j][0] + s[j][1];
            ps1 += s[j][2] + s[j][3];
        }
        ps0 += __shfl_xor_sync(0xffffffffu, ps0, 1);
        ps0 += __shfl_xor_sync(0xffffffffu, ps0, 2);
        ps1 += __shfl_xor_sync(0xffffffffu, ps1, 1);
        ps1 += __shfl_xor_sync(0xffffffffu, ps1, 2);
        lrow0 = lrow0 * corr0 + ps0;
        lrow1 = lrow1 * corr1 + ps1;

        #pragma unroll
        for (int j = 0; j < 8; j++) {
            o[j][0] *= corr0; o[j][1] *= corr0;
            o[j][2] *= corr1; o[j][3] *= corr1;
        }

        // ---- P fragments (bf16 split, C-frag regs re-serve as A-frags) ----
        uint32_t ph[4][4], pl[4][4];
        #pragma unroll
        for (int kc = 0; kc < 4; kc++) {
            #pragma unroll
            for (int half = 0; half < 2; half++) {   // S chunk 2kc, 2kc+1
                const int j = 2 * kc + half;
                __nv_bfloat162 h01 = __floats2bfloat162_rn(s[j][0], s[j][1]);
                __nv_bfloat162 h23 = __floats2bfloat162_rn(s[j][2], s[j][3]);
                float r0 = s[j][0] - __bfloat162float(h01.x);
                float r1 = s[j][1] - __bfloat162float(h01.y);
                float r2 = s[j][2] - __bfloat162float(h23.x);
                float r3 = s[j][3] - __bfloat162float(h23.y);
                __nv_bfloat162 l01 = __floats2bfloat162_rn(r0, r1);
                __nv_bfloat162 l23 = __floats2bfloat162_rn(r2, r3);
                ph[kc][2 * half + 0] = *(uint32_t*)&h01;
                ph[kc][2 * half + 1] = *(uint32_t*)&h23;
                pl[kc][2 * half + 0] = *(uint32_t*)&l01;
                pl[kc][2 * half + 1] = *(uint32_t*)&l23;
            }
        }

        // ---- O += P V (bf16 split) ----
        #pragma unroll
        for (int j = 0; j < 8; j++) {          // d chunk
            #pragma unroll
            for (int kc = 0; kc < 4; kc++) {   // key chunk
                const int ky = kc * 16 + lk * 2;
                uint32_t bh0 = *(const uint32_t*)&sVh[j * 8 + lq][ky];
                uint32_t bh1 = *(const uint32_t*)&sVh[j * 8 + lq][ky + 8];
                uint32_t bl0 = *(const uint32_t*)&sVl[j * 8 + lq][ky];
                uint32_t bl1 = *(const uint32_t*)&sVl[j * 8 + lq][ky + 8];
                mma16816(o[j], ph[kc], bh0, bh1);
                mma16816(o[j], ph[kc], bl0, bl1);
                mma16816(o[j], pl[kc], bh0, bh1);
            }
        }
        __syncthreads();
    }

    // ---- epilogue ----
    const float inv0 = 1.0f / lrow0;
    const float inv1 = 1.0f / lrow1;
    #pragma unroll
    for (int j = 0; j < 8; j++) {
        float2 v0 = make_float2(o[j][0] * inv0, o[j][1] * inv0);
        float2 v1 = make_float2(o[j][2] * inv1, o[j][3] * inv1);
        const int d = h * 64 + j * 8 + lk * 2;
        *(float2*)&out[(size_t)qr * EMB + d]       = v0;
        *(float2*)&out[(size_t)(qr + 8) * EMB + d] = v1;
    }
}

// ---------------- launch ----------------
extern "C" void kernel_launch(void* const* d_in, const int* in_sizes, int n_in,
                              void* d_out, int out_size)
{
    const float* x  = (const float*)d_in[0];
    const unsigned char* mask = (const unsigned char*)d_in[1];
    const float* Wq = (const float*)d_in[2];
    const float* bq = (const float*)d_in[3];
    const float* Wk = (const float*)d_in[4];
    const float* bk = (const float*)d_in[5];
    const float* Wv = (const float*)d_in[6];
    const float* bv = (const float*)d_in[7];
    const float* Wo = (const float*)d_in[8];
    const float* bo = (const float*)d_in[9];
    float* out = (float*)d_out;

    __nv_bfloat16 *Qh, *Ql, *Kh, *Kl, *Vh, *Vl;
    float* Ab;
    cudaGetSymbolAddress((void**)&Qh, g_Qhi);
    cudaGetSymbolAddress((void**)&Ql, g_Qlo);
    cudaGetSymbolAddress((void**)&Kh, g_Khi);
    cudaGetSymbolAddress((void**)&Kl, g_Klo);
    cudaGetSymbolAddress((void**)&Vh, g_Vhi);
    cudaGetSymbolAddress((void**)&Vl, g_Vlo);
    cudaGetSymbolAddress((void**)&Ab, g_att);

    dim3 ggrid(EMB / TN, S_LEN / TM);   // (6, 32)
    gemm_nt_bias<<<ggrid, 256>>>(x, Wq, bq, nullptr, Qh, Ql, S_LEN, EMB, EMB, 1);
    gemm_nt_bias<<<ggrid, 256>>>(x, Wk, bk, nullptr, Kh, Kl, S_LEN, EMB, EMB, 1);
    gemm_nt_bias<<<ggrid, 256>>>(x, Wv, bv, nullptr, Vh, Vl, S_LEN, EMB, EMB, 2);

    dim3 agrid(S_LEN / 128, NHEAD);     // (32, 12)
    attn_mma<<<agrid, 256>>>(Qh, Ql, Kh, Kl, Vh, Vl, mask, Ab);

    gemm_nt_bias<<<ggrid, 256>>>(Ab, Wo, bo, out, nullptr, nullptr, S_LEN, EMB, EMB, 0);
}

// round 3
// speedup vs baseline: 2.6714x; 1.2671x over previous
#include <cuda_runtime.h>
#include <cuda_bf16.h>
#include <cstdint>

#define S_LEN 4096
#define EMB   768
#define NHEAD 12
#define HDIM  64

// ---------------- scratch (no allocations allowed) ----------------
__device__ __nv_bfloat16 g_xh[S_LEN * EMB];
__device__ __nv_bfloat16 g_xl[S_LEN * EMB];
__device__ __nv_bfloat16 g_wh[4][EMB * EMB];
__device__ __nv_bfloat16 g_wl[4][EMB * EMB];
__device__ __nv_bfloat16 g_Qhi[NHEAD * S_LEN * HDIM];   // [H][S][D]
__device__ __nv_bfloat16 g_Qlo[NHEAD * S_LEN * HDIM];
__device__ __nv_bfloat16 g_Khi[NHEAD * S_LEN * HDIM];
__device__ __nv_bfloat16 g_Klo[NHEAD * S_LEN * HDIM];
__device__ __nv_bfloat16 g_Vhi[NHEAD * HDIM * S_LEN];   // [H][D][S] (transposed)
__device__ __nv_bfloat16 g_Vlo[NHEAD * HDIM * S_LEN];
__device__ __nv_bfloat16 g_ath[S_LEN * EMB];            // attn out hi
__device__ __nv_bfloat16 g_atl[S_LEN * EMB];            // attn out lo

__device__ __forceinline__ void fsplit(float v, __nv_bfloat16& h, __nv_bfloat16& l)
{
    h = __float2bfloat16(v);
    l = __float2bfloat16(v - __bfloat162float(h));
}

// ---------------- fp32 -> bf16 hi/lo split ----------------
__global__ __launch_bounds__(256) void split_kernel(
    const float* __restrict__ in, __nv_bfloat16* __restrict__ hi,
    __nv_bfloat16* __restrict__ lo, int n4)
{
    const int i = blockIdx.x * 256 + threadIdx.x;
    if (i >= n4) return;
    float4 v = ((const float4*)in)[i];
    __nv_bfloat16 h0, h1, h2, h3, l0, l1, l2, l3;
    fsplit(v.x, h0, l0); fsplit(v.y, h1, l1);
    fsplit(v.z, h2, l2); fsplit(v.w, h3, l3);
    __nv_bfloat162* hp = (__nv_bfloat162*)(hi + i * 4);
    __nv_bfloat162* lp = (__nv_bfloat162*)(lo + i * 4);
    hp[0] = __nv_bfloat162{h0, h1}; hp[1] = __nv_bfloat162{h2, h3};
    lp[0] = __nv_bfloat162{l0, l1}; lp[1] = __nv_bfloat162{l2, l3};
}

// ---------------- mma helper ----------------
__device__ __forceinline__ void mma16816(float* c, const uint32_t* a,
                                         uint32_t b0, uint32_t b1)
{
    asm volatile(
        "mma.sync.aligned.m16n8k16.row.col.f32.bf16.bf16.f32 "
        "{%0,%1,%2,%3},{%4,%5,%6,%7},{%8,%9},{%0,%1,%2,%3};"
        : "+f"(c[0]), "+f"(c[1]), "+f"(c[2]), "+f"(c[3])
        : "r"(a[0]), "r"(a[1]), "r"(a[2]), "r"(a[3]), "r"(b0), "r"(b1));
}

// ---------------- bf16-split tensor-core GEMM (NT) ----------------
// C[m,n] = sum_k A[m,k]*B[n,k] + bias[n],  M=4096, N=768, K=768
// mode 0: fp32 C[m*768+n]
// mode 1: bf16 hi/lo at ((n>>6)*4096 + m)*64 + (n&63)   (Q/K head-major)
// mode 2: bf16 hi/lo at n*4096 + m                      (V transposed)
__global__ __launch_bounds__(128) void gemm_bf16split(
    const __nv_bfloat16* __restrict__ Ah, const __nv_bfloat16* __restrict__ Al,
    const __nv_bfloat16* __restrict__ Bh, const __nv_bfloat16* __restrict__ Bl,
    const float* __restrict__ bias, float* __restrict__ Cf,
    __nv_bfloat16* __restrict__ Chi, __nv_bfloat16* __restrict__ Clo, int mode)
{
    __shared__ __nv_bfloat16 sAh[128][40];
    __shared__ __nv_bfloat16 sAl[128][40];
    __shared__ __nv_bfloat16 sBh[64][40];
    __shared__ __nv_bfloat16 sBl[64][40];

    const int tid = threadIdx.x;
    const int wid = tid >> 5;
    const int lane = tid & 31;
    const int lq = lane >> 2;
    const int lk = lane & 3;
    const int bm = blockIdx.y * 128;
    const int bn = blockIdx.x * 64;

    float acc[2][8][4];
    #pragma unroll
    for (int mi = 0; mi < 2; mi++)
        #pragma unroll
        for (int ni = 0; ni < 8; ni++)
            #pragma unroll
            for (int i = 0; i < 4; i++) acc[mi][ni][i] = 0.f;

    const int brow = tid >> 1;
    const int bcol = (tid & 1) * 16;

    for (int k0 = 0; k0 < EMB; k0 += 32) {
        const __nv_bfloat16* ah = Ah + (size_t)(bm + tid) * EMB + k0;
        const __nv_bfloat16* al = Al + (size_t)(bm + tid) * EMB + k0;
        #pragma unroll
        for (int i = 0; i < 4; i++) {
            *(uint4*)&sAh[tid][i * 8] = *(const uint4*)(ah + i * 8);
            *(uint4*)&sAl[tid][i * 8] = *(const uint4*)(al + i * 8);
        }
        const __nv_bfloat16* bh = Bh + (size_t)(bn + brow) * EMB + k0 + bcol;
        const __nv_bfloat16* bl = Bl + (size_t)(bn + brow) * EMB + k0 + bcol;
        *(uint4*)&sBh[brow][bcol]     = *(const uint4*)bh;
        *(uint4*)&sBh[brow][bcol + 8] = *(const uint4*)(bh + 8);
        *(uint4*)&sBl[brow][bcol]     = *(const uint4*)bl;
        *(uint4*)&sBl[brow][bcol + 8] = *(const uint4*)(bl + 8);
        __syncthreads();

        #pragma unroll
        for (int ks = 0; ks < 32; ks += 16) {
            uint32_t fah[2][4], fal[2][4];
            #pragma unroll
            for (int mi = 0; mi < 2; mi++) {
                const int r = wid * 32 + mi * 16 + lq;
                const int c = ks + lk * 2;
                fah[mi][0] = *(const uint32_t*)&sAh[r][c];
                fah[mi][1] = *(const uint32_t*)&sAh[r + 8][c];
                fah[mi][2] = *(const uint32_t*)&sAh[r][c + 8];
                fah[mi][3] = *(const uint32_t*)&sAh[r + 8][c + 8];
                fal[mi][0] = *(const uint32_t*)&sAl[r][c];
                fal[mi][1] = *(const uint32_t*)&sAl[r + 8][c];
                fal[mi][2] = *(const uint32_t*)&sAl[r][c + 8];
                fal[mi][3] = *(const uint32_t*)&sAl[r + 8][c + 8];
            }
            #pragma unroll
            for (int ni = 0; ni < 8; ni++) {
                const int br = ni * 8 + lq;
                const int c = ks + lk * 2;
                uint32_t bh0 = *(const uint32_t*)&sBh[br][c];
                uint32_t bh1 = *(const uint32_t*)&sBh[br][c + 8];
                uint32_t bl0 = *(const uint32_t*)&sBl[br][c];
                uint32_t bl1 = *(const uint32_t*)&sBl[br][c + 8];
                #pragma unroll
                for (int mi = 0; mi < 2; mi++) {
                    mma16816(acc[mi][ni], fah[mi], bh0, bh1);
                    mma16816(acc[mi][ni], fah[mi], bl0, bl1);
                    mma16816(acc[mi][ni], fal[mi], bh0, bh1);
                }
            }
        }
        __syncthreads();
    }

    // ---- epilogue ----
    #pragma unroll
    for (int mi = 0; mi < 2; mi++) {
        const int r = bm + wid * 32 + mi * 16 + lq;
        #pragma unroll
        for (int ni = 0; ni < 8; ni++) {
            const int c = bn + ni * 8 + lk * 2;
            const float b0 = bias[c], b1 = bias[c + 1];
            float v0 = acc[mi][ni][0] + b0;
            float v1 = acc[mi][ni][1] + b1;
            float v2 = acc[mi][ni][2] + b0;
            float v3 = acc[mi][ni][3] + b1;
            if (mode == 0) {
                *(float2*)&Cf[(size_t)r * EMB + c]       = make_float2(v0, v1);
                *(float2*)&Cf[(size_t)(r + 8) * EMB + c] = make_float2(v2, v3);
            } else if (mode == 1) {
                const int h = c >> 6, d = c & 63;
                const size_t i0 = ((size_t)h * S_LEN + r) * HDIM + d;
                const size_t i1 = ((size_t)h * S_LEN + r + 8) * HDIM + d;
                __nv_bfloat16 h0, h1, h2, h3, l0, l1, l2, l3;
                fsplit(v0, h0, l0); fsplit(v1, h1, l1);
                fsplit(v2, h2, l2); fsplit(v3, h3, l3);
                *(__nv_bfloat162*)&Chi[i0] = __nv_bfloat162{h0, h1};
                *(__nv_bfloat162*)&Clo[i0] = __nv_bfloat162{l0, l1};
                *(__nv_bfloat162*)&Chi[i1] = __nv_bfloat162{h2, h3};
                *(__nv_bfloat162*)&Clo[i1] = __nv_bfloat162{l2, l3};
            } else {
                __nv_bfloat16 h0, h1, h2, h3, l0, l1, l2, l3;
                fsplit(v0, h0, l0); fsplit(v1, h1, l1);
                fsplit(v2, h2, l2); fsplit(v3, h3, l3);
                Chi[(size_t)c * S_LEN + r] = h0;       Clo[(size_t)c * S_LEN + r] = l0;
                Chi[(size_t)(c + 1) * S_LEN + r] = h1; Clo[(size_t)(c + 1) * S_LEN + r] = l1;
                Chi[(size_t)c * S_LEN + r + 8] = h2;   Clo[(size_t)c * S_LEN + r + 8] = l2;
                Chi[(size_t)(c + 1) * S_LEN + r + 8] = h3; Clo[(size_t)(c + 1) * S_LEN + r + 8] = l3;
            }
        }
    }
}

// ---------------- tensor-core flash attention (bf16 split) ----------------
// 128 threads, 64 queries/block -> 3 CTAs/SM
__global__ __launch_bounds__(128) void attn_mma(
    const __nv_bfloat16* __restrict__ Qhi, const __nv_bfloat16* __restrict__ Qlo,
    const __nv_bfloat16* __restrict__ Khi, const __nv_bfloat16* __restrict__ Klo,
    const __nv_bfloat16* __restrict__ Vhi, const __nv_bfloat16* __restrict__ Vlo,
    const unsigned char* __restrict__ mask,
    __nv_bfloat16* __restrict__ Ohi, __nv_bfloat16* __restrict__ Olo)
{
    const int h   = blockIdx.y;
    const int q0  = blockIdx.x * 64;
    const int tid = threadIdx.x;
    const int wid = tid >> 5;
    const int lane = tid & 31;
    const int lq = lane >> 2;
    const int lk = lane & 3;

    __shared__ __nv_bfloat16 sKh[64][72];
    __shared__ __nv_bfloat16 sKl[64][72];
    __shared__ __nv_bfloat16 sVh[64][72];   // [d][key]
    __shared__ __nv_bfloat16 sVl[64][72];
    __shared__ float smadd[64];

    const size_t hoff = (size_t)h * S_LEN * HDIM;
    const float scale = rsqrtf((float)EMB);

    const int qr = q0 + wid * 16 + lq;
    uint32_t aQh[4][4], aQl[4][4];
    {
        const __nv_bfloat16* Qhp = Qhi + hoff;
        const __nv_bfloat16* Qlp = Qlo + hoff;
        #pragma unroll
        for (int kc = 0; kc < 4; kc++) {
            const int c = kc * 16 + lk * 2;
            aQh[kc][0] = *(const uint32_t*)&Qhp[(size_t)qr * 64 + c];
            aQh[kc][1] = *(const uint32_t*)&Qhp[(size_t)(qr + 8) * 64 + c];
            aQh[kc][2] = *(const uint32_t*)&Qhp[(size_t)qr * 64 + c + 8];
            aQh[kc][3] = *(const uint32_t*)&Qhp[(size_t)(qr + 8) * 64 + c + 8];
            aQl[kc][0] = *(const uint32_t*)&Qlp[(size_t)qr * 64 + c];
            aQl[kc][1] = *(const uint32_t*)&Qlp[(size_t)(qr + 8) * 64 + c];
            aQl[kc][2] = *(const uint32_t*)&Qlp[(size_t)qr * 64 + c + 8];
            aQl[kc][3] = *(const uint32_t*)&Qlp[(size_t)(qr + 8) * 64 + c + 8];
        }
    }

    float o[8][4];
    #pragma unroll
    for (int j = 0; j < 8; j++)
        #pragma unroll
        for (int i = 0; i < 4; i++) o[j][i] = 0.f;
    float mrow0 = -1e30f, mrow1 = -1e30f;
    float lrow0 = 0.f,    lrow1 = 0.f;

    const int trow = tid >> 1;            // 0..63
    const int tcol = (tid & 1) * 32;      // 32 halves each

    for (int k0 = 0; k0 < S_LEN; k0 += 64) {
        {
            const __nv_bfloat16* kh = Khi + hoff + (size_t)(k0 + trow) * 64 + tcol;
            const __nv_bfloat16* kl = Klo + hoff + (size_t)(k0 + trow) * 64 + tcol;
            const __nv_bfloat16* vh = Vhi + hoff + (size_t)trow * S_LEN + k0 + tcol;
            const __nv_bfloat16* vl = Vlo + hoff + (size_t)trow * S_LEN + k0 + tcol;
            #pragma unroll
            for (int i = 0; i < 4; i++) {
                *(uint4*)&sKh[trow][tcol + i * 8] = *(const uint4*)(kh + i * 8);
                *(uint4*)&sKl[trow][tcol + i * 8] = *(const uint4*)(kl + i * 8);
                *(uint4*)&sVh[trow][tcol + i * 8] = *(const uint4*)(vh + i * 8);
                *(uint4*)&sVl[trow][tcol + i * 8] = *(const uint4*)(vl + i * 8);
            }
            if (tid < 64) smadd[tid] = mask[k0 + tid] ? -1e30f : 0.f;
        }
        __syncthreads();

        // ---- S = Q K^T ----
        float s[8][4];
        #pragma unroll
        for (int j = 0; j < 8; j++) {
            s[j][0] = s[j][1] = s[j][2] = s[j][3] = 0.f;
            #pragma unroll
            for (int kc = 0; kc < 4; kc++) {
                const int d = kc * 16 + lk * 2;
                uint32_t bh0 = *(const uint32_t*)&sKh[j * 8 + lq][d];
                uint32_t bh1 = *(const uint32_t*)&sKh[j * 8 + lq][d + 8];
                uint32_t bl0 = *(const uint32_t*)&sKl[j * 8 + lq][d];
                uint32_t bl1 = *(const uint32_t*)&sKl[j * 8 + lq][d + 8];
                mma16816(s[j], aQh[kc], bh0, bh1);
                mma16816(s[j], aQh[kc], bl0, bl1);
                mma16816(s[j], aQl[kc], bh0, bh1);
            }
        }

        #pragma unroll
        for (int j = 0; j < 8; j++) {
            const float m0 = smadd[j * 8 + lk * 2];
            const float m1 = smadd[j * 8 + lk * 2 + 1];
            s[j][0] = s[j][0] * scale + m0;
            s[j][1] = s[j][1] * scale + m1;
            s[j][2] = s[j][2] * scale + m0;
            s[j][3] = s[j][3] * scale + m1;
        }

        // ---- online softmax ----
        float rm0 = -1e30f, rm1 = -1e30f;
        #pragma unroll
        for (int j = 0; j < 8; j++) {
            rm0 = fmaxf(rm0, fmaxf(s[j][0], s[j][1]));
            rm1 = fmaxf(rm1, fmaxf(s[j][2], s[j][3]));
        }
        rm0 = fmaxf(rm0, __shfl_xor_sync(0xffffffffu, rm0, 1));
        rm0 = fmaxf(rm0, __shfl_xor_sync(0xffffffffu, rm0, 2));
        rm1 = fmaxf(rm1, __shfl_xor_sync(0xffffffffu, rm1, 1));
        rm1 = fmaxf(rm1, __shfl_xor_sync(0xffffffffu, rm1, 2));

        const float mn0 = fmaxf(mrow0, rm0);
        const float mn1 = fmaxf(mrow1, rm1);
        const float corr0 = __expf(mrow0 - mn0);
        const float corr1 = __expf(mrow1 - mn1);
        mrow0 = mn0; mrow1 = mn1;

        float ps0 = 0.f, ps1 = 0.f;
        #pragma unroll
        for (int j = 0; j < 8; j++) {
            s[j][0] = __expf(s[j][0] - mn0);
            s[j][1] = __expf(s[j][1] - mn0);
            s[j][2] = __expf(s[j][2] - mn1);
            s[j][3] = __expf(s[j][3] - mn1);
            ps0 += s[j][0] + s[j][1];
            ps1 += s[j][2] + s[j][3];
        }
        ps0 += __shfl_xor_sync(0xffffffffu, ps0, 1);
        ps0 += __shfl_xor_sync(0xffffffffu, ps0, 2);
        ps1 += __shfl_xor_sync(0xffffffffu, ps1, 1);
        ps1 += __shfl_xor_sync(0xffffffffu, ps1, 2);
        lrow0 = lrow0 * corr0 + ps0;
        lrow1 = lrow1 * corr1 + ps1;

        #pragma unroll
        for (int j = 0; j < 8; j++) {
            o[j][0] *= corr0; o[j][1] *= corr0;
            o[j][2] *= corr1; o[j][3] *= corr1;
        }

        // ---- P fragments (bf16 split) ----
        uint32_t ph[4][4], pl[4][4];
        #pragma unroll
        for (int kc = 0; kc < 4; kc++) {
            #pragma unroll
            for (int half = 0; half < 2; half++) {
                const int j = 2 * kc + half;
                __nv_bfloat162 h01 = __floats2bfloat162_rn(s[j][0], s[j][1]);
                __nv_bfloat162 h23 = __floats2bfloat162_rn(s[j][2], s[j][3]);
                float r0 = s[j][0] - __bfloat162float(h01.x);
                float r1 = s[j][1] - __bfloat162float(h01.y);
                float r2 = s[j][2] - __bfloat162float(h23.x);
                float r3 = s[j][3] - __bfloat162float(h23.y);
                __nv_bfloat162 l01 = __floats2bfloat162_rn(r0, r1);
                __nv_bfloat162 l23 = __floats2bfloat162_rn(r2, r3);
                ph[kc][2 * half + 0] = *(uint32_t*)&h01;
                ph[kc][2 * half + 1] = *(uint32_t*)&h23;
                pl[kc][2 * half + 0] = *(uint32_t*)&l01;
                pl[kc][2 * half + 1] = *(uint32_t*)&l23;
            }
        }

        // ---- O += P V ----
        #pragma unroll
        for (int j = 0; j < 8; j++) {
            #pragma unroll
            for (int kc = 0; kc < 4; kc++) {
                const int ky = kc * 16 + lk * 2;
                uint32_t bh0 = *(const uint32_t*)&sVh[j * 8 + lq][ky];
                uint32_t bh1 = *(const uint32_t*)&sVh[j * 8 + lq][ky + 8];
                uint32_t bl0 = *(const uint32_t*)&sVl[j * 8 + lq][ky];
                uint32_t bl1 = *(const uint32_t*)&sVl[j * 8 + lq][ky + 8];
                mma16816(o[j], ph[kc], bh0, bh1);
                mma16816(o[j], ph[kc], bl0, bl1);
                mma16816(o[j], pl[kc], bh0, bh1);
            }
        }
        __syncthreads();
    }

    // ---- epilogue: write bf16 hi/lo of attention output ----
    const float inv0 = 1.0f / lrow0;
    const float inv1 = 1.0f / lrow1;
    #pragma unroll
    for (int j = 0; j < 8; j++) {
        const float v0 = o[j][0] * inv0, v1 = o[j][1] * inv0;
        const float v2 = o[j][2] * inv1, v3 = o[j][3] * inv1;
        const int c = h * 64 + j * 8 + lk * 2;
        const size_t i0 = (size_t)qr * EMB + c;
        const size_t i1 = (size_t)(qr + 8) * EMB + c;
        __nv_bfloat16 h0, h1, h2, h3, l0, l1, l2, l3;
        fsplit(v0, h0, l0); fsplit(v1, h1, l1);
        fsplit(v2, h2, l2); fsplit(v3, h3, l3);
        *(__nv_bfloat162*)&Ohi[i0] = __nv_bfloat162{h0, h1};
        *(__nv_bfloat162*)&Olo[i0] = __nv_bfloat162{l0, l1};
        *(__nv_bfloat162*)&Ohi[i1] = __nv_bfloat162{h2, h3};
        *(__nv_bfloat162*)&Olo[i1] = __nv_bfloat162{l2, l3};
    }
}

// ---------------- launch ----------------
extern "C" void kernel_launch(void* const* d_in, const int* in_sizes, int n_in,
                              void* d_out, int out_size)
{
    const float* x  = (const float*)d_in[0];
    const unsigned char* mask = (const unsigned char*)d_in[1];
    const float* Wq = (const float*)d_in[2];
    const float* bq = (const float*)d_in[3];
    const float* Wk = (const float*)d_in[4];
    const float* bk = (const float*)d_in[5];
    const float* Wv = (const float*)d_in[6];
    const float* bv = (const float*)d_in[7];
    const float* Wo = (const float*)d_in[8];
    const float* bo = (const float*)d_in[9];
    float* out = (float*)d_out;

    __nv_bfloat16 *xh, *xl, *wh, *wl;
    __nv_bfloat16 *Qh, *Ql, *Kh, *Kl, *Vh, *Vl, *ath, *atl;
    cudaGetSymbolAddress((void**)&xh, g_xh);
    cudaGetSymbolAddress((void**)&xl, g_xl);
    cudaGetSymbolAddress((void**)&wh, g_wh);
    cudaGetSymbolAddress((void**)&wl, g_wl);
    cudaGetSymbolAddress((void**)&Qh, g_Qhi);
    cudaGetSymbolAddress((void**)&Ql, g_Qlo);
    cudaGetSymbolAddress((void**)&Kh, g_Khi);
    cudaGetSymbolAddress((void**)&Kl, g_Klo);
    cudaGetSymbolAddress((void**)&Vh, g_Vhi);
    cudaGetSymbolAddress((void**)&Vl, g_Vlo);
    cudaGetSymbolAddress((void**)&ath, g_ath);
    cudaGetSymbolAddress((void**)&atl, g_atl);

    const int nx4 = S_LEN * EMB / 4;
    const int nw4 = EMB * EMB / 4;
    const int WW = EMB * EMB;
    split_kernel<<<(nx4 + 255) / 256, 256>>>(x, xh, xl, nx4);
    split_kernel<<<(nw4 + 255) / 256, 256>>>(Wq, wh + 0 * WW, wl + 0 * WW, nw4);
    split_kernel<<<(nw4 + 255) / 256, 256>>>(Wk, wh + 1 * WW, wl + 1 * WW, nw4);
    split_kernel<<<(nw4 + 255) / 256, 256>>>(Wv, wh + 2 * WW, wl + 2 * WW, nw4);
    split_kernel<<<(nw4 + 255) / 256, 256>>>(Wo, wh + 3 * WW, wl + 3 * WW, nw4);

    dim3 ggrid(EMB / 64, S_LEN / 128);   // (12, 32)
    gemm_bf16split<<<ggrid, 128>>>(xh, xl, wh + 0 * WW, wl + 0 * WW, bq,
                                   nullptr, Qh, Ql, 1);
    gemm_bf16split<<<ggrid, 128>>>(xh, xl, wh + 1 * WW, wl + 1 * WW, bk,
                                   nullptr, Kh, Kl, 1);
    gemm_bf16split<<<ggrid, 128>>>(xh, xl, wh + 2 * WW, wl + 2 * WW, bv,
                                   nullptr, Vh, Vl, 2);

    dim3 agrid(S_LEN / 64, NHEAD);       // (64, 12)
    attn_mma<<<agrid, 128>>>(Qh, Ql, Kh, Kl, Vh, Vl, mask, ath, atl);

    gemm_bf16split<<<ggrid, 128>>>(ath, atl, wh + 3 * WW, wl + 3 * WW, bo,
                                   out, nullptr, nullptr, 0);
}

// round 4
// speedup vs baseline: 2.9769x; 1.1143x over previous
#include <cuda_runtime.h>
#include <cuda_bf16.h>
#include <cstdint>

#define S_LEN 4096
#define EMB   768
#define NHEAD 12
#define HDIM  64

// ---------------- scratch (no allocations allowed) ----------------
__device__ __nv_bfloat16 g_xh[S_LEN * EMB];
__device__ __nv_bfloat16 g_xl[S_LEN * EMB];
__device__ __nv_bfloat16 g_wh[4][EMB * EMB];
__device__ __nv_bfloat16 g_wl[4][EMB * EMB];
__device__ __nv_bfloat16 g_Qhi[NHEAD * S_LEN * HDIM];   // [H][S][D]
__device__ __nv_bfloat16 g_Qlo[NHEAD * S_LEN * HDIM];
__device__ __nv_bfloat16 g_Khi[NHEAD * S_LEN * HDIM];
__device__ __nv_bfloat16 g_Klo[NHEAD * S_LEN * HDIM];
__device__ __nv_bfloat16 g_Vhi[NHEAD * HDIM * S_LEN];   // [H][D][S] (transposed)
__device__ __nv_bfloat16 g_Vlo[NHEAD * HDIM * S_LEN];
__device__ __nv_bfloat16 g_ath[S_LEN * EMB];            // attn out hi
__device__ __nv_bfloat16 g_atl[S_LEN * EMB];            // attn out lo

__device__ __forceinline__ void fsplit(float v, __nv_bfloat16& h, __nv_bfloat16& l)
{
    h = __float2bfloat16(v);
    l = __float2bfloat16(v - __bfloat162float(h));
}

__device__ __forceinline__ uint32_t smem_u32(const void* p)
{
    return (uint32_t)__cvta_generic_to_shared(p);
}

__device__ __forceinline__ void cp16(uint32_t saddr, const void* g)
{
    asm volatile("cp.async.cg.shared.global [%0], [%1], 16;" :: "r"(saddr), "l"(g));
}
#define CP_COMMIT() asm volatile("cp.async.commit_group;")
#define CP_WAIT0()  asm volatile("cp.async.wait_group 0;")

__device__ __forceinline__ void ldsm_x4(uint32_t& r0, uint32_t& r1,
                                        uint32_t& r2, uint32_t& r3, uint32_t addr)
{
    asm volatile("ldmatrix.sync.aligned.m8n8.x4.shared.b16 {%0,%1,%2,%3}, [%4];"
                 : "=r"(r0), "=r"(r1), "=r"(r2), "=r"(r3) : "r"(addr));
}

__device__ __forceinline__ void mma16816(float* c, const uint32_t* a,
                                         uint32_t b0, uint32_t b1)
{
    asm volatile(
        "mma.sync.aligned.m16n8k16.row.col.f32.bf16.bf16.f32 "
        "{%0,%1,%2,%3},{%4,%5,%6,%7},{%8,%9},{%0,%1,%2,%3};"
        : "+f"(c[0]), "+f"(c[1]), "+f"(c[2]), "+f"(c[3])
        : "r"(a[0]), "r"(a[1]), "r"(a[2]), "r"(a[3]), "r"(b0), "r"(b1));
}

// ---------------- fp32 -> bf16 hi/lo split ----------------
__global__ __launch_bounds__(256) void split_kernel(
    const float* __restrict__ in, __nv_bfloat16* __restrict__ hi,
    __nv_bfloat16* __restrict__ lo, int n4)
{
    const int i = blockIdx.x * 256 + threadIdx.x;
    if (i >= n4) return;
    float4 v = ((const float4*)in)[i];
    __nv_bfloat16 h0, h1, h2, h3, l0, l1, l2, l3;
    fsplit(v.x, h0, l0); fsplit(v.y, h1, l1);
    fsplit(v.z, h2, l2); fsplit(v.w, h3, l3);
    __nv_bfloat162* hp = (__nv_bfloat162*)(hi + i * 4);
    __nv_bfloat162* lp = (__nv_bfloat162*)(lo + i * 4);
    hp[0] = __nv_bfloat162{h0, h1}; hp[1] = __nv_bfloat162{h2, h3};
    lp[0] = __nv_bfloat162{l0, l1}; lp[1] = __nv_bfloat162{l2, l3};
}

// one launch splits all 4 weight matrices (blockIdx.y selects matrix)
__global__ __launch_bounds__(256) void split_w_kernel(
    const float* __restrict__ w0, const float* __restrict__ w1,
    const float* __restrict__ w2, const float* __restrict__ w3,
    __nv_bfloat16* __restrict__ hi, __nv_bfloat16* __restrict__ lo, int n4)
{
    const int i = blockIdx.x * 256 + threadIdx.x;
    if (i >= n4) return;
    const float* src = (blockIdx.y == 0) ? w0 : (blockIdx.y == 1) ? w1
                     : (blockIdx.y == 2) ? w2 : w3;
    const size_t off = (size_t)blockIdx.y * (EMB * EMB);
    float4 v = ((const float4*)src)[i];
    __nv_bfloat16 h0, h1, h2, h3, l0, l1, l2, l3;
    fsplit(v.x, h0, l0); fsplit(v.y, h1, l1);
    fsplit(v.z, h2, l2); fsplit(v.w, h3, l3);
    __nv_bfloat162* hp = (__nv_bfloat162*)(hi + off + i * 4);
    __nv_bfloat162* lp = (__nv_bfloat162*)(lo + off + i * 4);
    hp[0] = __nv_bfloat162{h0, h1}; hp[1] = __nv_bfloat162{h2, h3};
    lp[0] = __nv_bfloat162{l0, l1}; lp[1] = __nv_bfloat162{l2, l3};
}

// ---------------- bf16-split tensor-core GEMM (NT), ldmatrix + cp.async ----
// C[m,n] = sum_k A[m,k]*B[n,k] + bias[n],  M=4096, N=768, K=768
// mode 0: fp32 C[m*768+n]
// mode 1: bf16 hi/lo at ((n>>6)*4096 + m)*64 + (n&63)   (Q/K head-major)
// mode 2: bf16 hi/lo at n*4096 + m                      (V transposed)
__global__ __launch_bounds__(128) void gemm_bf16split(
    const __nv_bfloat16* __restrict__ Ah, const __nv_bfloat16* __restrict__ Al,
    const __nv_bfloat16* __restrict__ Bh, const __nv_bfloat16* __restrict__ Bl,
    const float* __restrict__ bias, float* __restrict__ Cf,
    __nv_bfloat16* __restrict__ Chi, __nv_bfloat16* __restrict__ Clo, int mode)
{
    __shared__ __nv_bfloat16 sAh[128][40];
    __shared__ __nv_bfloat16 sAl[128][40];
    __shared__ __nv_bfloat16 sBh[64][40];
    __shared__ __nv_bfloat16 sBl[64][40];

    const int tid = threadIdx.x;
    const int wid = tid >> 5;
    const int lane = tid & 31;
    const int lq = lane >> 2;
    const int lk = lane & 3;
    const int bm = blockIdx.y * 128;
    const int bn = blockIdx.x * 64;

    float acc[2][8][4];
    #pragma unroll
    for (int mi = 0; mi < 2; mi++)
        #pragma unroll
        for (int ni = 0; ni < 8; ni++)
            #pragma unroll
            for (int i = 0; i < 4; i++) acc[mi][ni][i] = 0.f;

    // ldmatrix lane selectors
    const int rselA = lane & 15;
    const int cselA = (lane >> 4) << 3;
    const int rselB = (lane & 7) + ((lane >> 4) << 3);
    const int cselB = ((lane >> 3) & 1) << 3;
    const uint32_t baseAh = smem_u32(&sAh[wid * 32 + rselA][cselA]);
    const uint32_t baseAl = smem_u32(&sAl[wid * 32 + rselA][cselA]);
    const uint32_t baseBh = smem_u32(&sBh[rselB][cselB]);
    const uint32_t baseBl = smem_u32(&sBl[rselB][cselB]);
    const int ROWB = 40 * 2;   // row stride bytes

    const int brow = tid >> 1;
    const int bcol = (tid & 1) * 16;

    for (int k0 = 0; k0 < EMB; k0 += 32) {
        const __nv_bfloat16* ah = Ah + (size_t)(bm + tid) * EMB + k0;
        const __nv_bfloat16* al = Al + (size_t)(bm + tid) * EMB + k0;
        #pragma unroll
        for (int i = 0; i < 4; i++) {
            cp16(smem_u32(&sAh[tid][i * 8]), ah + i * 8);
            cp16(smem_u32(&sAl[tid][i * 8]), al + i * 8);
        }
        const __nv_bfloat16* bh = Bh + (size_t)(bn + brow) * EMB + k0 + bcol;
        const __nv_bfloat16* bl = Bl + (size_t)(bn + brow) * EMB + k0 + bcol;
        cp16(smem_u32(&sBh[brow][bcol]), bh);
        cp16(smem_u32(&sBh[brow][bcol + 8]), bh + 8);
        cp16(smem_u32(&sBl[brow][bcol]), bl);
        cp16(smem_u32(&sBl[brow][bcol + 8]), bl + 8);
        CP_COMMIT();
        CP_WAIT0();
        __syncthreads();

        #pragma unroll
        for (int ks = 0; ks < 32; ks += 16) {
            uint32_t fah[2][4], fal[2][4];
            #pragma unroll
            for (int mi = 0; mi < 2; mi++) {
                const uint32_t off = (uint32_t)(mi * 16 * ROWB + ks * 2);
                ldsm_x4(fah[mi][0], fah[mi][1], fah[mi][2], fah[mi][3], baseAh + off);
                ldsm_x4(fal[mi][0], fal[mi][1], fal[mi][2], fal[mi][3], baseAl + off);
            }
            #pragma unroll
            for (int nip = 0; nip < 4; nip++) {
                const uint32_t off = (uint32_t)(nip * 16 * ROWB + ks * 2);
                uint32_t h0, h1, h2, h3, l0, l1, l2, l3;
                ldsm_x4(h0, h1, h2, h3, baseBh + off);
                ldsm_x4(l0, l1, l2, l3, baseBl + off);
                #pragma unroll
                for (int mi = 0; mi < 2; mi++) {
                    mma16816(acc[mi][2 * nip],     fah[mi], h0, h1);
                    mma16816(acc[mi][2 * nip],     fah[mi], l0, l1);
                    mma16816(acc[mi][2 * nip],     fal[mi], h0, h1);
                    mma16816(acc[mi][2 * nip + 1], fah[mi], h2, h3);
                    mma16816(acc[mi][2 * nip + 1], fah[mi], l2, l3);
                    mma16816(acc[mi][2 * nip + 1], fal[mi], h2, h3);
                }
            }
        }
        __syncthreads();
    }

    // ---- epilogue ----
    #pragma unroll
    for (int mi = 0; mi < 2; mi++) {
        const int r = bm + wid * 32 + mi * 16 + lq;
        #pragma unroll
        for (int ni = 0; ni < 8; ni++) {
            const int c = bn + ni * 8 + lk * 2;
            const float b0 = bias[c], b1 = bias[c + 1];
            float v0 = acc[mi][ni][0] + b0;
            float v1 = acc[mi][ni][1] + b1;
            float v2 = acc[mi][ni][2] + b0;
            float v3 = acc[mi][ni][3] + b1;
            if (mode == 0) {
                *(float2*)&Cf[(size_t)r * EMB + c]       = make_float2(v0, v1);
                *(float2*)&Cf[(size_t)(r + 8) * EMB + c] = make_float2(v2, v3);
            } else if (mode == 1) {
                const int h = c >> 6, d = c & 63;
                const size_t i0 = ((size_t)h * S_LEN + r) * HDIM + d;
                const size_t i1 = ((size_t)h * S_LEN + r + 8) * HDIM + d;
                __nv_bfloat16 h0, h1, h2, h3, l0, l1, l2, l3;
                fsplit(v0, h0, l0); fsplit(v1, h1, l1);
                fsplit(v2, h2, l2); fsplit(v3, h3, l3);
                *(__nv_bfloat162*)&Chi[i0] = __nv_bfloat162{h0, h1};
                *(__nv_bfloat162*)&Clo[i0] = __nv_bfloat162{l0, l1};
                *(__nv_bfloat162*)&Chi[i1] = __nv_bfloat162{h2, h3};
                *(__nv_bfloat162*)&Clo[i1] = __nv_bfloat162{l2, l3};
            } else {
                __nv_bfloat16 h0, h1, h2, h3, l0, l1, l2, l3;
                fsplit(v0, h0, l0); fsplit(v1, h1, l1);
                fsplit(v2, h2, l2); fsplit(v3, h3, l3);
                Chi[(size_t)c * S_LEN + r] = h0;           Clo[(size_t)c * S_LEN + r] = l0;
                Chi[(size_t)(c + 1) * S_LEN + r] = h1;     Clo[(size_t)(c + 1) * S_LEN + r] = l1;
                Chi[(size_t)c * S_LEN + r + 8] = h2;       Clo[(size_t)c * S_LEN + r + 8] = l2;
                Chi[(size_t)(c + 1) * S_LEN + r + 8] = h3; Clo[(size_t)(c + 1) * S_LEN + r + 8] = l3;
            }
        }
    }
}

// ---------------- tensor-core flash attention (bf16 split) ----------------
// 128 threads, 64 queries/block; ldmatrix B-frags + cp.async tile loads
__global__ __launch_bounds__(128) void attn_mma(
    const __nv_bfloat16* __restrict__ Qhi, const __nv_bfloat16* __restrict__ Qlo,
    const __nv_bfloat16* __restrict__ Khi, const __nv_bfloat16* __restrict__ Klo,
    const __nv_bfloat16* __restrict__ Vhi, const __nv_bfloat16* __restrict__ Vlo,
    const unsigned char* __restrict__ mask,
    __nv_bfloat16* __restrict__ Ohi, __nv_bfloat16* __restrict__ Olo)
{
    const int h   = blockIdx.y;
    const int q0  = blockIdx.x * 64;
    const int tid = threadIdx.x;
    const int wid = tid >> 5;
    const int lane = tid & 31;
    const int lq = lane >> 2;
    const int lk = lane & 3;

    __shared__ __nv_bfloat16 sKh[64][72];
    __shared__ __nv_bfloat16 sKl[64][72];
    __shared__ __nv_bfloat16 sVh[64][72];   // [d][key]
    __shared__ __nv_bfloat16 sVl[64][72];
    __shared__ float smadd[64];

    const size_t hoff = (size_t)h * S_LEN * HDIM;
    const float scale = rsqrtf((float)EMB);

    const int qr = q0 + wid * 16 + lq;
    uint32_t aQh[4][4], aQl[4][4];
    {
        const __nv_bfloat16* Qhp = Qhi + hoff;
        const __nv_bfloat16* Qlp = Qlo + hoff;
        #pragma unroll
        for (int kc = 0; kc < 4; kc++) {
            const int c = kc * 16 + lk * 2;
            aQh[kc][0] = *(const uint32_t*)&Qhp[(size_t)qr * 64 + c];
            aQh[kc][1] = *(const uint32_t*)&Qhp[(size_t)(qr + 8) * 64 + c];
            aQh[kc][2] = *(const uint32_t*)&Qhp[(size_t)qr * 64 + c + 8];
            aQh[kc][3] = *(const uint32_t*)&Qhp[(size_t)(qr + 8) * 64 + c + 8];
            aQl[kc][0] = *(const uint32_t*)&Qlp[(size_t)qr * 64 + c];
            aQl[kc][1] = *(const uint32_t*)&Qlp[(size_t)(qr + 8) * 64 + c];
            aQl[kc][2] = *(const uint32_t*)&Qlp[(size_t)qr * 64 + c + 8];
            aQl[kc][3] = *(const uint32_t*)&Qlp[(size_t)(qr + 8) * 64 + c + 8];
        }
    }

    // ldmatrix lane selectors (B-frags): two 8-row groups x two k-halves
    const int rsel = (lane & 7) + ((lane >> 4) << 3);
    const int csel = ((lane >> 3) & 1) << 3;
    const uint32_t baseKh = smem_u32(&sKh[rsel][csel]);
    const uint32_t baseKl = smem_u32(&sKl[rsel][csel]);
    const uint32_t baseVh = smem_u32(&sVh[rsel][csel]);
    const uint32_t baseVl = smem_u32(&sVl[rsel][csel]);
    const int ROWB = 72 * 2;   // row stride bytes

    float o[8][4];
    #pragma unroll
    for (int j = 0; j < 8; j++)
        #pragma unroll
        for (int i = 0; i < 4; i++) o[j][i] = 0.f;
    float mrow0 = -1e30f, mrow1 = -1e30f;
    float lrow0 = 0.f,    lrow1 = 0.f;

    const int trow = tid >> 1;            // 0..63
    const int tcol = (tid & 1) * 32;      // 32 halves each

    for (int k0 = 0; k0 < S_LEN; k0 += 64) {
        {
            const __nv_bfloat16* kh = Khi + hoff + (size_t)(k0 + trow) * 64 + tcol;
            const __nv_bfloat16* kl = Klo + hoff + (size_t)(k0 + trow) * 64 + tcol;
            const __nv_bfloat16* vh = Vhi + hoff + (size_t)trow * S_LEN + k0 + tcol;
            const __nv_bfloat16* vl = Vlo + hoff + (size_t)trow * S_LEN + k0 + tcol;
            #pragma unroll
            for (int i = 0; i < 4; i++) {
                cp16(smem_u32(&sKh[trow][tcol + i * 8]), kh + i * 8);
                cp16(smem_u32(&sKl[trow][tcol + i * 8]), kl + i * 8);
                cp16(smem_u32(&sVh[trow][tcol + i * 8]), vh + i * 8);
                cp16(smem_u32(&sVl[trow][tcol + i * 8]), vl + i * 8);
            }
            if (tid < 64) smadd[tid] = mask[k0 + tid] ? -1e30f : 0.f;
            CP_COMMIT();
            CP_WAIT0();
        }
        __syncthreads();

        // ---- S = Q K^T ----
        float s[8][4];
        #pragma unroll
        for (int j = 0; j < 8; j++)
            s[j][0] = s[j][1] = s[j][2] = s[j][3] = 0.f;

        #pragma unroll
        for (int jp = 0; jp < 4; jp++) {
            #pragma unroll
            for (int kc = 0; kc < 4; kc++) {
                const uint32_t off = (uint32_t)(jp * 16 * ROWB + kc * 32);
                uint32_t h0, h1, h2, h3, l0, l1, l2, l3;
                ldsm_x4(h0, h1, h2, h3, baseKh + off);
                ldsm_x4(l0, l1, l2, l3, baseKl + off);
                mma16816(s[2 * jp],     aQh[kc], h0, h1);
                mma16816(s[2 * jp],     aQh[kc], l0, l1);
                mma16816(s[2 * jp],     aQl[kc], h0, h1);
                mma16816(s[2 * jp + 1], aQh[kc], h2, h3);
                mma16816(s[2 * jp + 1], aQh[kc], l2, l3);
                mma16816(s[2 * jp + 1], aQl[kc], h2, h3);
            }
        }

        #pragma unroll
        for (int j = 0; j < 8; j++) {
            const float m0 = smadd[j * 8 + lk * 2];
            const float m1 = smadd[j * 8 + lk * 2 + 1];
            s[j][0] = s[j][0] * scale + m0;
            s[j][1] = s[j][1] * scale + m1;
            s[j][2] = s[j][2] * scale + m0;
            s[j][3] = s[j][3] * scale + m1;
        }

        // ---- online softmax ----
        float rm0 = -1e30f, rm1 = -1e30f;
        #pragma unroll
        for (int j = 0; j < 8; j++) {
            rm0 = fmaxf(rm0, fmaxf(s[j][0], s[j][1]));
            rm1 = fmaxf(rm1, fmaxf(s[j][2], s[j][3]));
        }
        rm0 = fmaxf(rm0, __shfl_xor_sync(0xffffffffu, rm0, 1));
        rm0 = fmaxf(rm0, __shfl_xor_sync(0xffffffffu, rm0, 2));
        rm1 = fmaxf(rm1, __shfl_xor_sync(0xffffffffu, rm1, 1));
        rm1 = fmaxf(rm1, __shfl_xor_sync(0xffffffffu, rm1, 2));

        const float mn0 = fmaxf(mrow0, rm0);
        const float mn1 = fmaxf(mrow1, rm1);
        const float corr0 = __expf(mrow0 - mn0);
        const float corr1 = __expf(mrow1 - mn1);
        mrow0 = mn0; mrow1 = mn1;

        float ps0 = 0.f, ps1 = 0.f;
        #pragma unroll
        for (int j = 0; j < 8; j++) {
            s[j][0] = __expf(s[j][0] - mn0);
            s[j][1] = __expf(s[j][1] - mn0);
            s[j][2] = __expf(s[j][2] - mn1);
            s[j][3] = __expf(s[j][3] - mn1);
            ps0 += s[j][0] + s[j][1];
            ps1 += s[j][2] + s[j][3];
        }
        ps0 += __shfl_xor_sync(0xffffffffu, ps0, 1);
        ps0 += __shfl_xor_sync(0xffffffffu, ps0, 2);
        ps1 += __shfl_xor_sync(0xffffffffu, ps1, 1);
        ps1 += __shfl_xor_sync(0xffffffffu, ps1, 2);
        lrow0 = lrow0 * corr0 + ps0;
        lrow1 = lrow1 * corr1 + ps1;

        #pragma unroll
        for (int j = 0; j < 8; j++) {
            o[j][0] *= corr0; o[j][1] *= corr0;
            o[j][2] *= corr1; o[j][3] *= corr1;
        }

        // ---- P fragments (bf16 split) ----
        uint32_t ph[4][4], pl[4][4];
        #pragma unroll
        for (int kc = 0; kc < 4; kc++) {
            #pragma unroll
            for (int half = 0; half < 2; half++) {
                const int j = 2 * kc + half;
                __nv_bfloat162 h01 = __floats2bfloat162_rn(s[j][0], s[j][1]);
                __nv_bfloat162 h23 = __floats2bfloat162_rn(s[j][2], s[j][3]);
                float r0 = s[j][0] - __bfloat162float(h01.x);
                float r1 = s[j][1] - __bfloat162float(h01.y);
                float r2 = s[j][2] - __bfloat162float(h23.x);
                float r3 = s[j][3] - __bfloat162float(h23.y);
                __nv_bfloat162 l01 = __floats2bfloat162_rn(r0, r1);
                __nv_bfloat162 l23 = __floats2bfloat162_rn(r2, r3);
                ph[kc][2 * half + 0] = *(uint32_t*)&h01;
                ph[kc][2 * half + 1] = *(uint32_t*)&h23;
                pl[kc][2 * half + 0] = *(uint32_t*)&l01;
                pl[kc][2 * half + 1] = *(uint32_t*)&l23;
            }
        }

        // ---- O += P V ----
        #pragma unroll
        for (int jp = 0; jp < 4; jp++) {
            #pragma unroll
            for (int kc = 0; kc < 4; kc++) {
                const uint32_t off = (uint32_t)(jp * 16 * ROWB + kc * 32);
                uint32_t h0, h1, h2, h3, l0, l1, l2, l3;
                ldsm_x4(h0, h1, h2, h3, baseVh + off);
                ldsm_x4(l0, l1, l2, l3, baseVl + off);
                mma16816(o[2 * jp],     ph[kc], h0, h1);
                mma16816(o[2 * jp],     ph[kc], l0, l1);
                mma16816(o[2 * jp],     pl[kc], h0, h1);
                mma16816(o[2 * jp + 1], ph[kc], h2, h3);
                mma16816(o[2 * jp + 1], ph[kc], l2, l3);
                mma16816(o[2 * jp + 1], pl[kc], h2, h3);
            }
        }
        __syncthreads();
    }

    // ---- epilogue: write bf16 hi/lo of attention output ----
    const float inv0 = 1.0f / lrow0;
    const float inv1 = 1.0f / lrow1;
    #pragma unroll
    for (int j = 0; j < 8; j++) {
        const float v0 = o[j][0] * inv0, v1 = o[j][1] * inv0;
        const float v2 = o[j][2] * inv1, v3 = o[j][3] * inv1;
        const int c = h * 64 + j * 8 + lk * 2;
        const size_t i0 = (size_t)qr * EMB + c;
        const size_t i1 = (size_t)(qr + 8) * EMB + c;
        __nv_bfloat16 h0, h1, h2, h3, l0, l1, l2, l3;
        fsplit(v0, h0, l0); fsplit(v1, h1, l1);
        fsplit(v2, h2, l2); fsplit(v3, h3, l3);
        *(__nv_bfloat162*)&Ohi[i0] = __nv_bfloat162{h0, h1};
        *(__nv_bfloat162*)&Olo[i0] = __nv_bfloat162{l0, l1};
        *(__nv_bfloat162*)&Ohi[i1] = __nv_bfloat162{h2, h3};
        *(__nv_bfloat162*)&Olo[i1] = __nv_bfloat162{l2, l3};
    }
}

// ---------------- launch ----------------
extern "C" void kernel_launch(void* const* d_in, const int* in_sizes, int n_in,
                              void* d_out, int out_size)
{
    const float* x  = (const float*)d_in[0];
    const unsigned char* mask = (const unsigned char*)d_in[1];
    const float* Wq = (const float*)d_in[2];
    const float* bq = (const float*)d_in[3];
    const float* Wk = (const float*)d_in[4];
    const float* bk = (const float*)d_in[5];
    const float* Wv = (const float*)d_in[6];
    const float* bv = (const float*)d_in[7];
    const float* Wo = (const float*)d_in[8];
    const float* bo = (const float*)d_in[9];
    float* out = (float*)d_out;

    __nv_bfloat16 *xh, *xl, *wh, *wl;
    __nv_bfloat16 *Qh, *Ql, *Kh, *Kl, *Vh, *Vl, *ath, *atl;
    cudaGetSymbolAddress((void**)&xh, g_xh);
    cudaGetSymbolAddress((void**)&xl, g_xl);
    cudaGetSymbolAddress((void**)&wh, g_wh);
    cudaGetSymbolAddress((void**)&wl, g_wl);
    cudaGetSymbolAddress((void**)&Qh, g_Qhi);
    cudaGetSymbolAddress((void**)&Ql, g_Qlo);
    cudaGetSymbolAddress((void**)&Kh, g_Khi);
    cudaGetSymbolAddress((void**)&Kl, g_Klo);
    cudaGetSymbolAddress((void**)&Vh, g_Vhi);
    cudaGetSymbolAddress((void**)&Vl, g_Vlo);
    cudaGetSymbolAddress((void**)&ath, g_ath);
    cudaGetSymbolAddress((void**)&atl, g_atl);

    const int nx4 = S_LEN * EMB / 4;
    const int nw4 = EMB * EMB / 4;
    const int WW = EMB * EMB;
    split_kernel<<<(nx4 + 255) / 256, 256>>>(x, xh, xl, nx4);
    dim3 wgrid((nw4 + 255) / 256, 4);
    split_w_kernel<<<wgrid, 256>>>(Wq, Wk, Wv, Wo, wh, wl, nw4);

    dim3 ggrid(EMB / 64, S_LEN / 128);   // (12, 32)
    gemm_bf16split<<<ggrid, 128>>>(xh, xl, wh + 0 * WW, wl + 0 * WW, bq,
                                   nullptr, Qh, Ql, 1);
    gemm_bf16split<<<ggrid, 128>>>(xh, xl, wh + 1 * WW, wl + 1 * WW, bk,
                                   nullptr, Kh, Kl, 1);
    gemm_bf16split<<<ggrid, 128>>>(xh, xl, wh + 2 * WW, wl + 2 * WW, bv,
                                   nullptr, Vh, Vl, 2);

    dim3 agrid(S_LEN / 64, NHEAD);       // (64, 12)
    attn_mma<<<agrid, 128>>>(Qh, Ql, Kh, Kl, Vh, Vl, mask, ath, atl);

    gemm_bf16split<<<ggrid, 128>>>(ath, atl, wh + 3 * WW, wl + 3 * WW, bo,
                                   out, nullptr, nullptr, 0);
}

// round 5
// speedup vs baseline: 3.1371x; 1.0538x over previous
#include <cuda_runtime.h>
#include <cuda_bf16.h>
#include <cstdint>

#define S_LEN 4096
#define EMB   768
#define NHEAD 12
#define HDIM  64
#define WW    (EMB * EMB)

// ---------------- scratch (no allocations allowed) ----------------
__device__ __nv_bfloat16 g_xh[S_LEN * EMB];
__device__ __nv_bfloat16 g_xl[S_LEN * EMB];
__device__ __nv_bfloat16 g_wh[4][EMB * EMB];
__device__ __nv_bfloat16 g_wl[4][EMB * EMB];
__device__ __nv_bfloat16 g_Qhi[NHEAD * S_LEN * HDIM];   // [H][S][D]
__device__ __nv_bfloat16 g_Qlo[NHEAD * S_LEN * HDIM];
__device__ __nv_bfloat16 g_Khi[NHEAD * S_LEN * HDIM];
__device__ __nv_bfloat16 g_Klo[NHEAD * S_LEN * HDIM];
__device__ __nv_bfloat16 g_Vhi[NHEAD * HDIM * S_LEN];   // [H][D][S] (transposed)
__device__ __nv_bfloat16 g_Vlo[NHEAD * HDIM * S_LEN];
__device__ __nv_bfloat16 g_ath[S_LEN * EMB];            // attn out hi
__device__ __nv_bfloat16 g_atl[S_LEN * EMB];            // attn out lo

__device__ __forceinline__ void fsplit(float v, __nv_bfloat16& h, __nv_bfloat16& l)
{
    h = __float2bfloat16(v);
    l = __float2bfloat16(v - __bfloat162float(h));
}

__device__ __forceinline__ uint32_t smem_u32(const void* p)
{
    return (uint32_t)__cvta_generic_to_shared(p);
}

__device__ __forceinline__ void cp16(uint32_t saddr, const void* g)
{
    asm volatile("cp.async.cg.shared.global [%0], [%1], 16;" :: "r"(saddr), "l"(g));
}
#define CP_COMMIT() asm volatile("cp.async.commit_group;")
#define CP_WAIT1()  asm volatile("cp.async.wait_group 1;")
#define CP_WAIT0()  asm volatile("cp.async.wait_group 0;")

__device__ __forceinline__ void ldsm_x4(uint32_t& r0, uint32_t& r1,
                                        uint32_t& r2, uint32_t& r3, uint32_t addr)
{
    asm volatile("ldmatrix.sync.aligned.m8n8.x4.shared.b16 {%0,%1,%2,%3}, [%4];"
                 : "=r"(r0), "=r"(r1), "=r"(r2), "=r"(r3) : "r"(addr));
}

__device__ __forceinline__ void mma16816(float* c, const uint32_t* a,
                                         uint32_t b0, uint32_t b1)
{
    asm volatile(
        "mma.sync.aligned.m16n8k16.row.col.f32.bf16.bf16.f32 "
        "{%0,%1,%2,%3},{%4,%5,%6,%7},{%8,%9},{%0,%1,%2,%3};"
        : "+f"(c[0]), "+f"(c[1]), "+f"(c[2]), "+f"(c[3])
        : "r"(a[0]), "r"(a[1]), "r"(a[2]), "r"(a[3]), "r"(b0), "r"(b1));
}

// ---------------- fp32 -> bf16 hi/lo split ----------------
__global__ __launch_bounds__(256) void split_kernel(
    const float* __restrict__ in, __nv_bfloat16* __restrict__ hi,
    __nv_bfloat16* __restrict__ lo, int n4)
{
    const int i = blockIdx.x * 256 + threadIdx.x;
    if (i >= n4) return;
    float4 v = ((const float4*)in)[i];
    __nv_bfloat16 h0, h1, h2, h3, l0, l1, l2, l3;
    fsplit(v.x, h0, l0); fsplit(v.y, h1, l1);
    fsplit(v.z, h2, l2); fsplit(v.w, h3, l3);
    __nv_bfloat162* hp = (__nv_bfloat162*)(hi + i * 4);
    __nv_bfloat162* lp = (__nv_bfloat162*)(lo + i * 4);
    hp[0] = __nv_bfloat162{h0, h1}; hp[1] = __nv_bfloat162{h2, h3};
    lp[0] = __nv_bfloat162{l0, l1}; lp[1] = __nv_bfloat162{l2, l3};
}

__global__ __launch_bounds__(256) void split_w_kernel(
    const float* __restrict__ w0, const float* __restrict__ w1,
    const float* __restrict__ w2, const float* __restrict__ w3,
    __nv_bfloat16* __restrict__ hi, __nv_bfloat16* __restrict__ lo, int n4)
{
    const int i = blockIdx.x * 256 + threadIdx.x;
    if (i >= n4) return;
    const float* src = (blockIdx.y == 0) ? w0 : (blockIdx.y == 1) ? w1
                     : (blockIdx.y == 2) ? w2 : w3;
    const size_t off = (size_t)blockIdx.y * WW;
    float4 v = ((const float4*)src)[i];
    __nv_bfloat16 h0, h1, h2, h3, l0, l1, l2, l3;
    fsplit(v.x, h0, l0); fsplit(v.y, h1, l1);
    fsplit(v.z, h2, l2); fsplit(v.w, h3, l3);
    __nv_bfloat162* hp = (__nv_bfloat162*)(hi + off + i * 4);
    __nv_bfloat162* lp = (__nv_bfloat162*)(lo + off + i * 4);
    hp[0] = __nv_bfloat162{h0, h1}; hp[1] = __nv_bfloat162{h2, h3};
    lp[0] = __nv_bfloat162{l0, l1}; lp[1] = __nv_bfloat162{l2, l3};
}

// ================= pipelined bf16-split GEMM core =================
// smem layout (dynamic, 61440 B):
//   sAh[2][128][40] @0 (10240/stage)  sAl @20480
//   sBh[2][64][40]  @40960 (5120/st)  sBl @51200
#define GA_ST 10240
#define GB_ST 5120
#define G_SMEM 61440

__device__ __forceinline__ void gemm_load_stage(
    char* sm, int s, int k0,
    const __nv_bfloat16* __restrict__ Ah, const __nv_bfloat16* __restrict__ Al,
    const __nv_bfloat16* __restrict__ Bh, const __nv_bfloat16* __restrict__ Bl,
    int bm, int bn, int tid)
{
    const __nv_bfloat16* ah = Ah + (size_t)(bm + tid) * EMB + k0;
    const __nv_bfloat16* al = Al + (size_t)(bm + tid) * EMB + k0;
    uint32_t dA = smem_u32(sm) + s * GA_ST + tid * 80;
    #pragma unroll
    for (int i = 0; i < 4; i++) {
        cp16(dA + i * 16, ah + i * 8);
        cp16(dA + 20480 + i * 16, al + i * 8);
    }
    const int brow = tid >> 1;
    const int bcol = (tid & 1) * 16;
    const __nv_bfloat16* bh = Bh + (size_t)(bn + brow) * EMB + k0 + bcol;
    const __nv_bfloat16* bl = Bl + (size_t)(bn + brow) * EMB + k0 + bcol;
    uint32_t dB = smem_u32(sm) + 40960 + s * GB_ST + brow * 80 + bcol * 2;
    cp16(dB, bh);           cp16(dB + 16, bh + 8);
    cp16(dB + 10240, bl);   cp16(dB + 10240 + 16, bl + 8);
}

__device__ __forceinline__ void gemm_mainloop(
    char* sm,
    const __nv_bfloat16* __restrict__ Ah, const __nv_bfloat16* __restrict__ Al,
    const __nv_bfloat16* __restrict__ Bh, const __nv_bfloat16* __restrict__ Bl,
    int bm, int bn, int tid, int wid, int lane, float acc[2][8][4])
{
    #pragma unroll
    for (int mi = 0; mi < 2; mi++)
        #pragma unroll
        for (int ni = 0; ni < 8; ni++)
            #pragma unroll
            for (int i = 0; i < 4; i++) acc[mi][ni][i] = 0.f;

    const int rselA = lane & 15;
    const int cselA = (lane >> 4) << 3;
    const int rselB = (lane & 7) + ((lane >> 4) << 3);
    const int cselB = ((lane >> 3) & 1) << 3;
    const uint32_t base = smem_u32(sm);
    const uint32_t bAh = base + ((wid * 32 + rselA) * 40 + cselA) * 2;
    const uint32_t bBh = base + 40960 + (rselB * 40 + cselB) * 2;

    gemm_load_stage(sm, 0, 0, Ah, Al, Bh, Bl, bm, bn, tid);
    CP_COMMIT();

    const int NIT = EMB / 32;  // 24
    #pragma unroll 1
    for (int it = 0; it < NIT; it++) {
        const int cur = it & 1;
        if (it + 1 < NIT) {
            gemm_load_stage(sm, cur ^ 1, (it + 1) * 32, Ah, Al, Bh, Bl, bm, bn, tid);
            CP_COMMIT();
            CP_WAIT1();
        } else {
            CP_WAIT0();
        }
        __syncthreads();

        const uint32_t cAh = bAh + cur * GA_ST;
        const uint32_t cAl = cAh + 20480;
        const uint32_t cBh = bBh + cur * GB_ST;
        const uint32_t cBl = cBh + 10240;

        #pragma unroll
        for (int ks = 0; ks < 32; ks += 16) {
            uint32_t fah[2][4], fal[2][4];
            #pragma unroll
            for (int mi = 0; mi < 2; mi++) {
                const uint32_t off = (uint32_t)(mi * 16 * 80 + ks * 2);
                ldsm_x4(fah[mi][0], fah[mi][1], fah[mi][2], fah[mi][3], cAh + off);
                ldsm_x4(fal[mi][0], fal[mi][1], fal[mi][2], fal[mi][3], cAl + off);
            }
            #pragma unroll
            for (int nip = 0; nip < 4; nip++) {
                const uint32_t off = (uint32_t)(nip * 16 * 80 + ks * 2);
                uint32_t h0, h1, h2, h3, l0, l1, l2, l3;
                ldsm_x4(h0, h1, h2, h3, cBh + off);
                ldsm_x4(l0, l1, l2, l3, cBl + off);
                #pragma unroll
                for (int mi = 0; mi < 2; mi++) {
                    mma16816(acc[mi][2 * nip],     fah[mi], h0, h1);
                    mma16816(acc[mi][2 * nip],     fah[mi], l0, l1);
                    mma16816(acc[mi][2 * nip],     fal[mi], h0, h1);
                    mma16816(acc[mi][2 * nip + 1], fah[mi], h2, h3);
                    mma16816(acc[mi][2 * nip + 1], fah[mi], l2, l3);
                    mma16816(acc[mi][2 * nip + 1], fal[mi], h2, h3);
                }
            }
        }
        __syncthreads();
    }
}

// QKV projection: grid (12, 32, 3); z selects weight/bias/output
__global__ __launch_bounds__(128) void gemm_qkv(
    const __nv_bfloat16* __restrict__ xh, const __nv_bfloat16* __restrict__ xl,
    const __nv_bfloat16* __restrict__ wh, const __nv_bfloat16* __restrict__ wl,
    const float* __restrict__ bq, const float* __restrict__ bk,
    const float* __restrict__ bv,
    __nv_bfloat16* __restrict__ Qh, __nv_bfloat16* __restrict__ Ql,
    __nv_bfloat16* __restrict__ Kh, __nv_bfloat16* __restrict__ Kl,
    __nv_bfloat16* __restrict__ Vh, __nv_bfloat16* __restrict__ Vl)
{
    extern __shared__ char sm[];
    const int z = blockIdx.z;
    const int tid = threadIdx.x;
    const int wid = tid >> 5;
    const int lane = tid & 31;
    const int lq = lane >> 2;
    const int lk = lane & 3;
    const int bm = blockIdx.y * 128;
    const int bn = blockIdx.x * 64;

    const __nv_bfloat16* Bh = wh + (size_t)z * WW;
    const __nv_bfloat16* Bl = wl + (size_t)z * WW;
    const float* bias = (z == 0) ? bq : (z == 1) ? bk : bv;
    __nv_bfloat16* Chi = (z == 0) ? Qh : (z == 1) ? Kh : Vh;
    __nv_bfloat16* Clo = (z == 0) ? Ql : (z == 1) ? Kl : Vl;

    float acc[2][8][4];
    gemm_mainloop(sm, xh, xl, Bh, Bl, bm, bn, tid, wid, lane, acc);

    #pragma unroll
    for (int mi = 0; mi < 2; mi++) {
        const int r = bm + wid * 32 + mi * 16 + lq;
        #pragma unroll
        for (int ni = 0; ni < 8; ni++) {
            const int c = bn + ni * 8 + lk * 2;
            const float b0 = bias[c], b1 = bias[c + 1];
            float v0 = acc[mi][ni][0] + b0;
            float v1 = acc[mi][ni][1] + b1;
            float v2 = acc[mi][ni][2] + b0;
            float v3 = acc[mi][ni][3] + b1;
            __nv_bfloat16 h0, h1, h2, h3, l0, l1, l2, l3;
            fsplit(v0, h0, l0); fsplit(v1, h1, l1);
            fsplit(v2, h2, l2); fsplit(v3, h3, l3);
            if (z < 2) {
                const int hh = c >> 6, d = c & 63;
                const size_t i0 = ((size_t)hh * S_LEN + r) * HDIM + d;
                const size_t i1 = ((size_t)hh * S_LEN + r + 8) * HDIM + d;
                *(__nv_bfloat162*)&Chi[i0] = __nv_bfloat162{h0, h1};
                *(__nv_bfloat162*)&Clo[i0] = __nv_bfloat162{l0, l1};
                *(__nv_bfloat162*)&Chi[i1] = __nv_bfloat162{h2, h3};
                *(__nv_bfloat162*)&Clo[i1] = __nv_bfloat162{l2, l3};
            } else {
                Chi[(size_t)c * S_LEN + r] = h0;           Clo[(size_t)c * S_LEN + r] = l0;
                Chi[(size_t)(c + 1) * S_LEN + r] = h1;     Clo[(size_t)(c + 1) * S_LEN + r] = l1;
                Chi[(size_t)c * S_LEN + r + 8] = h2;       Clo[(size_t)c * S_LEN + r + 8] = l2;
                Chi[(size_t)(c + 1) * S_LEN + r + 8] = h3; Clo[(size_t)(c + 1) * S_LEN + r + 8] = l3;
            }
        }
    }
}

// Output projection: fp32 result
__global__ __launch_bounds__(128) void gemm_out(
    const __nv_bfloat16* __restrict__ Ah, const __nv_bfloat16* __restrict__ Al,
    const __nv_bfloat16* __restrict__ Bh, const __nv_bfloat16* __restrict__ Bl,
    const float* __restrict__ bias, float* __restrict__ Cf)
{
    extern __shared__ char sm[];
    const int tid = threadIdx.x;
    const int wid = tid >> 5;
    const int lane = tid & 31;
    const int lq = lane >> 2;
    const int lk = lane & 3;
    const int bm = blockIdx.y * 128;
    const int bn = blockIdx.x * 64;

    float acc[2][8][4];
    gemm_mainloop(sm, Ah, Al, Bh, Bl, bm, bn, tid, wid, lane, acc);

    #pragma unroll
    for (int mi = 0; mi < 2; mi++) {
        const int r = bm + wid * 32 + mi * 16 + lq;
        #pragma unroll
        for (int ni = 0; ni < 8; ni++) {
            const int c = bn + ni * 8 + lk * 2;
            const float b0 = bias[c], b1 = bias[c + 1];
            *(float2*)&Cf[(size_t)r * EMB + c] =
                make_float2(acc[mi][ni][0] + b0, acc[mi][ni][1] + b1);
            *(float2*)&Cf[(size_t)(r + 8) * EMB + c] =
                make_float2(acc[mi][ni][2] + b0, acc[mi][ni][3] + b1);
        }
    }
}

// ================= pipelined flash attention =================
// smem (dynamic, 74240 B):
//   sKh[2][64][72] @0 (9216/st)   sKl @18432
//   sVh @36864                    sVl @55296
//   smadd[2][64] f32 @73728
#define AT_ST 9216
#define A_SMEM 74240

__global__ __launch_bounds__(128) void attn_mma(
    const __nv_bfloat16* __restrict__ Qhi, const __nv_bfloat16* __restrict__ Qlo,
    const __nv_bfloat16* __restrict__ Khi, const __nv_bfloat16* __restrict__ Klo,
    const __nv_bfloat16* __restrict__ Vhi, const __nv_bfloat16* __restrict__ Vlo,
    const unsigned char* __restrict__ mask,
    __nv_bfloat16* __restrict__ Ohi, __nv_bfloat16* __restrict__ Olo)
{
    extern __shared__ char sm[];
    const int h   = blockIdx.y;
    const int q0  = blockIdx.x * 64;
    const int tid = threadIdx.x;
    const int wid = tid >> 5;
    const int lane = tid & 31;
    const int lq = lane >> 2;
    const int lk = lane & 3;

    const size_t hoff = (size_t)h * S_LEN * HDIM;
    const float scale = rsqrtf((float)EMB);

    const int qr = q0 + wid * 16 + lq;
    uint32_t aQh[4][4], aQl[4][4];
    {
        const __nv_bfloat16* Qhp = Qhi + hoff;
        const __nv_bfloat16* Qlp = Qlo + hoff;
        #pragma unroll
        for (int kc = 0; kc < 4; kc++) {
            const int c = kc * 16 + lk * 2;
            aQh[kc][0] = *(const uint32_t*)&Qhp[(size_t)qr * 64 + c];
            aQh[kc][1] = *(const uint32_t*)&Qhp[(size_t)(qr + 8) * 64 + c];
            aQh[kc][2] = *(const uint32_t*)&Qhp[(size_t)qr * 64 + c + 8];
            aQh[kc][3] = *(const uint32_t*)&Qhp[(size_t)(qr + 8) * 64 + c + 8];
            aQl[kc][0] = *(const uint32_t*)&Qlp[(size_t)qr * 64 + c];
            aQl[kc][1] = *(const uint32_t*)&Qlp[(size_t)(qr + 8) * 64 + c];
            aQl[kc][2] = *(const uint32_t*)&Qlp[(size_t)qr * 64 + c + 8];
            aQl[kc][3] = *(const uint32_t*)&Qlp[(size_t)(qr + 8) * 64 + c + 8];
        }
    }

    const int rsel = (lane & 7) + ((lane >> 4) << 3);
    const int csel = ((lane >> 3) & 1) << 3;
    const uint32_t base = smem_u32(sm);
    const uint32_t bK = base + (rsel * 72 + csel) * 2;
    float* smadd = (float*)(sm + 73728);

    const int trow = tid >> 1;
    const int tcol = (tid & 1) * 32;

    // tile loader
    auto load_tile = [&](int s, int k0) {
        const __nv_bfloat16* kh = Khi + hoff + (size_t)(k0 + trow) * 64 + tcol;
        const __nv_bfloat16* kl = Klo + hoff + (size_t)(k0 + trow) * 64 + tcol;
        const __nv_bfloat16* vh = Vhi + hoff + (size_t)trow * S_LEN + k0 + tcol;
        const __nv_bfloat16* vl = Vlo + hoff + (size_t)trow * S_LEN + k0 + tcol;
        const uint32_t d = base + s * AT_ST + (trow * 72 + tcol) * 2;
        #pragma unroll
        for (int i = 0; i < 4; i++) {
            cp16(d + i * 16,         kh + i * 8);
            cp16(d + 18432 + i * 16, kl + i * 8);
            cp16(d + 36864 + i * 16, vh + i * 8);
            cp16(d + 55296 + i * 16, vl + i * 8);
        }
        if (tid < 64) smadd[s * 64 + tid] = mask[k0 + tid] ? -1e30f : 0.f;
    };

    float o[8][4];
    #pragma unroll
    for (int j = 0; j < 8; j++)
        #pragma unroll
        for (int i = 0; i < 4; i++) o[j][i] = 0.f;
    float mrow0 = -1e30f, mrow1 = -1e30f;
    float lrow0 = 0.f,    lrow1 = 0.f;

    load_tile(0, 0);
    CP_COMMIT();

    const int NIT = S_LEN / 64;  // 64
    #pragma unroll 1
    for (int it = 0; it < NIT; it++) {
        const int cur = it & 1;
        if (it + 1 < NIT) {
            load_tile(cur ^ 1, (it + 1) * 64);
            CP_COMMIT();
            CP_WAIT1();
        } else {
            CP_WAIT0();
        }
        __syncthreads();

        const uint32_t cK = bK + cur * AT_ST;
        const uint32_t cKl = cK + 18432;
        const uint32_t cV = cK + 36864;
        const uint32_t cVl = cK + 55296;
        const float* md = smadd + cur * 64;

        // ---- S = Q K^T ----
        float s[8][4];
        #pragma unroll
        for (int j = 0; j < 8; j++)
            s[j][0] = s[j][1] = s[j][2] = s[j][3] = 0.f;

        #pragma unroll
        for (int jp = 0; jp < 4; jp++) {
            #pragma unroll
            for (int kc = 0; kc < 4; kc++) {
                const uint32_t off = (uint32_t)(jp * 16 * 144 + kc * 32);
                uint32_t h0, h1, h2, h3, l0, l1, l2, l3;
                ldsm_x4(h0, h1, h2, h3, cK + off);
                ldsm_x4(l0, l1, l2, l3, cKl + off);
                mma16816(s[2 * jp],     aQh[kc], h0, h1);
                mma16816(s[2 * jp],     aQh[kc], l0, l1);
                mma16816(s[2 * jp],     aQl[kc], h0, h1);
                mma16816(s[2 * jp + 1], aQh[kc], h2, h3);
                mma16816(s[2 * jp + 1], aQh[kc], l2, l3);
                mma16816(s[2 * jp + 1], aQl[kc], h2, h3);
            }
        }

        #pragma unroll
        for (int j = 0; j < 8; j++) {
            const float m0 = md[j * 8 + lk * 2];
            const float m1 = md[j * 8 + lk * 2 + 1];
            s[j][0] = s[j][0] * scale + m0;
            s[j][1] = s[j][1] * scale + m1;
            s[j][2] = s[j][2] * scale + m0;
            s[j][3] = s[j][3] * scale + m1;
        }

        // ---- online softmax ----
        float rm0 = -1e30f, rm1 = -1e30f;
        #pragma unroll
        for (int j = 0; j < 8; j++) {
            rm0 = fmaxf(rm0, fmaxf(s[j][0], s[j][1]));
            rm1 = fmaxf(rm1, fmaxf(s[j][2], s[j][3]));
        }
        rm0 = fmaxf(rm0, __shfl_xor_sync(0xffffffffu, rm0, 1));
        rm0 = fmaxf(rm0, __shfl_xor_sync(0xffffffffu, rm0, 2));
        rm1 = fmaxf(rm1, __shfl_xor_sync(0xffffffffu, rm1, 1));
        rm1 = fmaxf(rm1, __shfl_xor_sync(0xffffffffu, rm1, 2));

        const float mn0 = fmaxf(mrow0, rm0);
        const float mn1 = fmaxf(mrow1, rm1);
        const float corr0 = __expf(mrow0 - mn0);
        const float corr1 = __expf(mrow1 - mn1);
        mrow0 = mn0; mrow1 = mn1;

        float ps0 = 0.f, ps1 = 0.f;
        #pragma unroll
        for (int j = 0; j < 8; j++) {
            s[j][0] = __expf(s[j][0] - mn0);
            s[j][1] = __expf(s[j][1] - mn0);
            s[j][2] = __expf(s[j][2] - mn1);
            s[j][3] = __expf(s[j][3] - mn1);
            ps0 += s[j][0] + s[j][1];
            ps1 += s[j][2] + s[j][3];
        }
        ps0 += __shfl_xor_sync(0xffffffffu, ps0, 1);
        ps0 += __shfl_xor_sync(0xffffffffu, ps0, 2);
        ps1 += __shfl_xor_sync(0xffffffffu, ps1, 1);
        ps1 += __shfl_xor_sync(0xffffffffu, ps1, 2);
        lrow0 = lrow0 * corr0 + ps0;
        lrow1 = lrow1 * corr1 + ps1;

        #pragma unroll
        for (int j = 0; j < 8; j++) {
            o[j][0] *= corr0; o[j][1] *= corr0;
            o[j][2] *= corr1; o[j][3] *= corr1;
        }

        // ---- P fragments (bf16 split) ----
        uint32_t ph[4][4], pl[4][4];
        #pragma unroll
        for (int kc = 0; kc < 4; kc++) {
            #pragma unroll
            for (int half = 0; half < 2; half++) {
                const int j = 2 * kc + half;
                __nv_bfloat162 h01 = __floats2bfloat162_rn(s[j][0], s[j][1]);
                __nv_bfloat162 h23 = __floats2bfloat162_rn(s[j][2], s[j][3]);
                float r0 = s[j][0] - __bfloat162float(h01.x);
                float r1 = s[j][1] - __bfloat162float(h01.y);
                float r2 = s[j][2] - __bfloat162float(h23.x);
                float r3 = s[j][3] - __bfloat162float(h23.y);
                __nv_bfloat162 l01 = __floats2bfloat162_rn(r0, r1);
                __nv_bfloat162 l23 = __floats2bfloat162_rn(r2, r3);
                ph[kc][2 * half + 0] = *(uint32_t*)&h01;
                ph[kc][2 * half + 1] = *(uint32_t*)&h23;
                pl[kc][2 * half + 0] = *(uint32_t*)&l01;
                pl[kc][2 * half + 1] = *(uint32_t*)&l23;
            }
        }

        // ---- O += P V ----
        #pragma unroll
        for (int jp = 0; jp < 4; jp++) {
            #pragma unroll
            for (int kc = 0; kc < 4; kc++) {
                const uint32_t off = (uint32_t)(jp * 16 * 144 + kc * 32);
                uint32_t h0, h1, h2, h3, l0, l1, l2, l3;
                ldsm_x4(h0, h1, h2, h3, cV + off);
                ldsm_x4(l0, l1, l2, l3, cVl + off);
                mma16816(o[2 * jp],     ph[kc], h0, h1);
                mma16816(o[2 * jp],     ph[kc], l0, l1);
                mma16816(o[2 * jp],     pl[kc], h0, h1);
                mma16816(o[2 * jp + 1], ph[kc], h2, h3);
                mma16816(o[2 * jp + 1], ph[kc], l2, l3);
                mma16816(o[2 * jp + 1], pl[kc], h2, h3);
            }
        }
        __syncthreads();
    }

    // ---- epilogue ----
    const float inv0 = 1.0f / lrow0;
    const float inv1 = 1.0f / lrow1;
    #pragma unroll
    for (int j = 0; j < 8; j++) {
        const float v0 = o[j][0] * inv0, v1 = o[j][1] * inv0;
        const float v2 = o[j][2] * inv1, v3 = o[j][3] * inv1;
        const int c = h * 64 + j * 8 + lk * 2;
        const size_t i0 = (size_t)qr * EMB + c;
        const size_t i1 = (size_t)(qr + 8) * EMB + c;
        __nv_bfloat16 h0, h1, h2, h3, l0, l1, l2, l3;
        fsplit(v0, h0, l0); fsplit(v1, h1, l1);
        fsplit(v2, h2, l2); fsplit(v3, h3, l3);
        *(__nv_bfloat162*)&Ohi[i0] = __nv_bfloat162{h0, h1};
        *(__nv_bfloat162*)&Olo[i0] = __nv_bfloat162{l0, l1};
        *(__nv_bfloat162*)&Ohi[i1] = __nv_bfloat162{h2, h3};
        *(__nv_bfloat162*)&Olo[i1] = __nv_bfloat162{l2, l3};
    }
}

// ---------------- launch ----------------
extern "C" void kernel_launch(void* const* d_in, const int* in_sizes, int n_in,
                              void* d_out, int out_size)
{
    const float* x  = (const float*)d_in[0];
    const unsigned char* mask = (const unsigned char*)d_in[1];
    const float* Wq = (const float*)d_in[2];
    const float* bq = (const float*)d_in[3];
    const float* Wk = (const float*)d_in[4];
    const float* bk = (const float*)d_in[5];
    const float* Wv = (const float*)d_in[6];
    const float* bv = (const float*)d_in[7];
    const float* Wo = (const float*)d_in[8];
    const float* bo = (const float*)d_in[9];
    float* out = (float*)d_out;

    __nv_bfloat16 *xh, *xl, *wh, *wl;
    __nv_bfloat16 *Qh, *Ql, *Kh, *Kl, *Vh, *Vl, *ath, *atl;
    cudaGetSymbolAddress((void**)&xh, g_xh);
    cudaGetSymbolAddress((void**)&xl, g_xl);
    cudaGetSymbolAddress((void**)&wh, g_wh);
    cudaGetSymbolAddress((void**)&wl, g_wl);
    cudaGetSymbolAddress((void**)&Qh, g_Qhi);
    cudaGetSymbolAddress((void**)&Ql, g_Qlo);
    cudaGetSymbolAddress((void**)&Kh, g_Khi);
    cudaGetSymbolAddress((void**)&Kl, g_Klo);
    cudaGetSymbolAddress((void**)&Vh, g_Vhi);
    cudaGetSymbolAddress((void**)&Vl, g_Vlo);
    cudaGetSymbolAddress((void**)&ath, g_ath);
    cudaGetSymbolAddress((void**)&atl, g_atl);

    cudaFuncSetAttribute(gemm_qkv, cudaFuncAttributeMaxDynamicSharedMemorySize, G_SMEM);
    cudaFuncSetAttribute(gemm_out, cudaFuncAttributeMaxDynamicSharedMemorySize, G_SMEM);
    cudaFuncSetAttribute(attn_mma, cudaFuncAttributeMaxDynamicSharedMemorySize, A_SMEM);

    const int nx4 = S_LEN * EMB / 4;
    const int nw4 = WW / 4;
    split_kernel<<<(nx4 + 255) / 256, 256>>>(x, xh, xl, nx4);
    dim3 wgrid((nw4 + 255) / 256, 4);
    split_w_kernel<<<wgrid, 256>>>(Wq, Wk, Wv, Wo, wh, wl, nw4);

    dim3 qgrid(EMB / 64, S_LEN / 128, 3);   // (12, 32, 3)
    gemm_qkv<<<qgrid, 128, G_SMEM>>>(xh, xl, wh, wl, bq, bk, bv,
                                     Qh, Ql, Kh, Kl, Vh, Vl);

    dim3 agrid(S_LEN / 64, NHEAD);          // (64, 12)
    attn_mma<<<agrid, 128, A_SMEM>>>(Qh, Ql, Kh, Kl, Vh, Vl, mask, ath, atl);

    dim3 ogrid(EMB / 64, S_LEN / 128);      // (12, 32)
    gemm_out<<<ogrid, 128, G_SMEM>>>(ath, atl, wh + 3 * WW, wl + 3 * WW, bo, out);
}

// round 6
// speedup vs baseline: 4.2348x; 1.3499x over previous
#include <cuda_runtime.h>
#include <cuda_bf16.h>
#include <cuda_fp16.h>
#include <cstdint>

#define S_LEN 4096
#define EMB   768
#define NHEAD 12
#define HDIM  64
#define WW    (EMB * EMB)

// ---------------- scratch (no allocations allowed) ----------------
__device__ __nv_bfloat16 g_xh[S_LEN * EMB];
__device__ __nv_bfloat16 g_xl[S_LEN * EMB];
__device__ __nv_bfloat16 g_wh[4][EMB * EMB];
__device__ __nv_bfloat16 g_wl[4][EMB * EMB];
__device__ __half g_Qhf[NHEAD * S_LEN * HDIM];   // [H][S][D] fp16 split hi
__device__ __half g_Qlf[NHEAD * S_LEN * HDIM];   // fp16 split lo
__device__ __half g_Khf[NHEAD * S_LEN * HDIM];   // [H][S][D] fp16 (rounded)
__device__ __half g_Vhf[NHEAD * HDIM * S_LEN];   // [H][D][S] fp16 (rounded, transposed)
__device__ __nv_bfloat16 g_ath[S_LEN * EMB];     // attn out hi (bf16 split)
__device__ __nv_bfloat16 g_atl[S_LEN * EMB];

__device__ __forceinline__ void fsplit(float v, __nv_bfloat16& h, __nv_bfloat16& l)
{
    h = __float2bfloat16(v);
    l = __float2bfloat16(v - __bfloat162float(h));
}

__device__ __forceinline__ uint32_t smem_u32(const void* p)
{
    return (uint32_t)__cvta_generic_to_shared(p);
}

__device__ __forceinline__ void cp16(uint32_t saddr, const void* g)
{
    asm volatile("cp.async.cg.shared.global [%0], [%1], 16;" :: "r"(saddr), "l"(g));
}
#define CP_COMMIT() asm volatile("cp.async.commit_group;")
#define CP_WAIT1()  asm volatile("cp.async.wait_group 1;")
#define CP_WAIT0()  asm volatile("cp.async.wait_group 0;")

__device__ __forceinline__ void ldsm_x4(uint32_t& r0, uint32_t& r1,
                                        uint32_t& r2, uint32_t& r3, uint32_t addr)
{
    asm volatile("ldmatrix.sync.aligned.m8n8.x4.shared.b16 {%0,%1,%2,%3}, [%4];"
                 : "=r"(r0), "=r"(r1), "=r"(r2), "=r"(r3) : "r"(addr));
}

// bf16 mma (projections)
__device__ __forceinline__ void mma_bf(float* c, const uint32_t* a,
                                       uint32_t b0, uint32_t b1)
{
    asm volatile(
        "mma.sync.aligned.m16n8k16.row.col.f32.bf16.bf16.f32 "
        "{%0,%1,%2,%3},{%4,%5,%6,%7},{%8,%9},{%0,%1,%2,%3};"
        : "+f"(c[0]), "+f"(c[1]), "+f"(c[2]), "+f"(c[3])
        : "r"(a[0]), "r"(a[1]), "r"(a[2]), "r"(a[3]), "r"(b0), "r"(b1));
}

// fp16 mma (attention)
__device__ __forceinline__ void mma_f16(float* c, const uint32_t* a,
                                        uint32_t b0, uint32_t b1)
{
    asm volatile(
        "mma.sync.aligned.m16n8k16.row.col.f32.f16.f16.f32 "
        "{%0,%1,%2,%3},{%4,%5,%6,%7},{%8,%9},{%0,%1,%2,%3};"
        : "+f"(c[0]), "+f"(c[1]), "+f"(c[2]), "+f"(c[3])
        : "r"(a[0]), "r"(a[1]), "r"(a[2]), "r"(a[3]), "r"(b0), "r"(b1));
}

__device__ __forceinline__ float ex2(float x)
{
    float r;
    asm("ex2.approx.f32 %0, %1;" : "=f"(r) : "f"(x));
    return r;
}

// ---------------- fp32 -> bf16 hi/lo split ----------------
__global__ __launch_bounds__(256) void split_kernel(
    const float* __restrict__ in, __nv_bfloat16* __restrict__ hi,
    __nv_bfloat16* __restrict__ lo, int n4)
{
    const int i = blockIdx.x * 256 + threadIdx.x;
    if (i >= n4) return;
    float4 v = ((const float4*)in)[i];
    __nv_bfloat16 h0, h1, h2, h3, l0, l1, l2, l3;
    fsplit(v.x, h0, l0); fsplit(v.y, h1, l1);
    fsplit(v.z, h2, l2); fsplit(v.w, h3, l3);
    __nv_bfloat162* hp = (__nv_bfloat162*)(hi + i * 4);
    __nv_bfloat162* lp = (__nv_bfloat162*)(lo + i * 4);
    hp[0] = __nv_bfloat162{h0, h1}; hp[1] = __nv_bfloat162{h2, h3};
    lp[0] = __nv_bfloat162{l0, l1}; lp[1] = __nv_bfloat162{l2, l3};
}

__global__ __launch_bounds__(256) void split_w_kernel(
    const float* __restrict__ w0, const float* __restrict__ w1,
    const float* __restrict__ w2, const float* __restrict__ w3,
    __nv_bfloat16* __restrict__ hi, __nv_bfloat16* __restrict__ lo, int n4)
{
    const int i = blockIdx.x * 256 + threadIdx.x;
    if (i >= n4) return;
    const float* src = (blockIdx.y == 0) ? w0 : (blockIdx.y == 1) ? w1
                     : (blockIdx.y == 2) ? w2 : w3;
    const size_t off = (size_t)blockIdx.y * WW;
    float4 v = ((const float4*)src)[i];
    __nv_bfloat16 h0, h1, h2, h3, l0, l1, l2, l3;
    fsplit(v.x, h0, l0); fsplit(v.y, h1, l1);
    fsplit(v.z, h2, l2); fsplit(v.w, h3, l3);
    __nv_bfloat162* hp = (__nv_bfloat162*)(hi + off + i * 4);
    __nv_bfloat162* lp = (__nv_bfloat162*)(lo + off + i * 4);
    hp[0] = __nv_bfloat162{h0, h1}; hp[1] = __nv_bfloat162{h2, h3};
    lp[0] = __nv_bfloat162{l0, l1}; lp[1] = __nv_bfloat162{l2, l3};
}

// ================= pipelined bf16-split GEMM core =================
#define GA_ST 10240
#define GB_ST 5120
#define G_SMEM 61440

__device__ __forceinline__ void gemm_load_stage(
    char* sm, int s, int k0,
    const __nv_bfloat16* __restrict__ Ah, const __nv_bfloat16* __restrict__ Al,
    const __nv_bfloat16* __restrict__ Bh, const __nv_bfloat16* __restrict__ Bl,
    int bm, int bn, int tid)
{
    const __nv_bfloat16* ah = Ah + (size_t)(bm + tid) * EMB + k0;
    const __nv_bfloat16* al = Al + (size_t)(bm + tid) * EMB + k0;
    uint32_t dA = smem_u32(sm) + s * GA_ST + tid * 80;
    #pragma unroll
    for (int i = 0; i < 4; i++) {
        cp16(dA + i * 16, ah + i * 8);
        cp16(dA + 20480 + i * 16, al + i * 8);
    }
    const int brow = tid >> 1;
    const int bcol = (tid & 1) * 16;
    const __nv_bfloat16* bh = Bh + (size_t)(bn + brow) * EMB + k0 + bcol;
    const __nv_bfloat16* bl = Bl + (size_t)(bn + brow) * EMB + k0 + bcol;
    uint32_t dB = smem_u32(sm) + 40960 + s * GB_ST + brow * 80 + bcol * 2;
    cp16(dB, bh);           cp16(dB + 16, bh + 8);
    cp16(dB + 10240, bl);   cp16(dB + 10240 + 16, bl + 8);
}

__device__ __forceinline__ void gemm_mainloop(
    char* sm,
    const __nv_bfloat16* __restrict__ Ah, const __nv_bfloat16* __restrict__ Al,
    const __nv_bfloat16* __restrict__ Bh, const __nv_bfloat16* __restrict__ Bl,
    int bm, int bn, int tid, int wid, int lane, float acc[2][8][4])
{
    #pragma unroll
    for (int mi = 0; mi < 2; mi++)
        #pragma unroll
        for (int ni = 0; ni < 8; ni++)
            #pragma unroll
            for (int i = 0; i < 4; i++) acc[mi][ni][i] = 0.f;

    const int rselA = lane & 15;
    const int cselA = (lane >> 4) << 3;
    const int rselB = (lane & 7) + ((lane >> 4) << 3);
    const int cselB = ((lane >> 3) & 1) << 3;
    const uint32_t base = smem_u32(sm);
    const uint32_t bAh = base + ((wid * 32 + rselA) * 40 + cselA) * 2;
    const uint32_t bBh = base + 40960 + (rselB * 40 + cselB) * 2;

    gemm_load_stage(sm, 0, 0, Ah, Al, Bh, Bl, bm, bn, tid);
    CP_COMMIT();

    const int NIT = EMB / 32;  // 24
    #pragma unroll 1
    for (int it = 0; it < NIT; it++) {
        const int cur = it & 1;
        if (it + 1 < NIT) {
            gemm_load_stage(sm, cur ^ 1, (it + 1) * 32, Ah, Al, Bh, Bl, bm, bn, tid);
            CP_COMMIT();
            CP_WAIT1();
        } else {
            CP_WAIT0();
        }
        __syncthreads();

        const uint32_t cAh = bAh + cur * GA_ST;
        const uint32_t cAl = cAh + 20480;
        const uint32_t cBh = bBh + cur * GB_ST;
        const uint32_t cBl = cBh + 10240;

        #pragma unroll
        for (int ks = 0; ks < 32; ks += 16) {
            uint32_t fah[2][4], fal[2][4];
            #pragma unroll
            for (int mi = 0; mi < 2; mi++) {
                const uint32_t off = (uint32_t)(mi * 16 * 80 + ks * 2);
                ldsm_x4(fah[mi][0], fah[mi][1], fah[mi][2], fah[mi][3], cAh + off);
                ldsm_x4(fal[mi][0], fal[mi][1], fal[mi][2], fal[mi][3], cAl + off);
            }
            #pragma unroll
            for (int nip = 0; nip < 4; nip++) {
                const uint32_t off = (uint32_t)(nip * 16 * 80 + ks * 2);
                uint32_t h0, h1, h2, h3, l0, l1, l2, l3;
                ldsm_x4(h0, h1, h2, h3, cBh + off);
                ldsm_x4(l0, l1, l2, l3, cBl + off);
                #pragma unroll
                for (int mi = 0; mi < 2; mi++) {
                    mma_bf(acc[mi][2 * nip],     fah[mi], h0, h1);
                    mma_bf(acc[mi][2 * nip],     fah[mi], l0, l1);
                    mma_bf(acc[mi][2 * nip],     fal[mi], h0, h1);
                    mma_bf(acc[mi][2 * nip + 1], fah[mi], h2, h3);
                    mma_bf(acc[mi][2 * nip + 1], fah[mi], l2, l3);
                    mma_bf(acc[mi][2 * nip + 1], fal[mi], h2, h3);
                }
            }
        }
        __syncthreads();
    }
}

// QKV projection: grid (12, 32, 3); z: 0=Q (fp16 split), 1=K (fp16), 2=V (fp16, T)
__global__ __launch_bounds__(128) void gemm_qkv(
    const __nv_bfloat16* __restrict__ xh, const __nv_bfloat16* __restrict__ xl,
    const __nv_bfloat16* __restrict__ wh, const __nv_bfloat16* __restrict__ wl,
    const float* __restrict__ bq, const float* __restrict__ bk,
    const float* __restrict__ bv,
    __half* __restrict__ Qh, __half* __restrict__ Ql,
    __half* __restrict__ Kh, __half* __restrict__ Vh)
{
    extern __shared__ char sm[];
    const int z = blockIdx.z;
    const int tid = threadIdx.x;
    const int wid = tid >> 5;
    const int lane = tid & 31;
    const int lq = lane >> 2;
    const int lk = lane & 3;
    const int bm = blockIdx.y * 128;
    const int bn = blockIdx.x * 64;

    const __nv_bfloat16* Bh = wh + (size_t)z * WW;
    const __nv_bfloat16* Bl = wl + (size_t)z * WW;
    const float* bias = (z == 0) ? bq : (z == 1) ? bk : bv;

    float acc[2][8][4];
    gemm_mainloop(sm, xh, xl, Bh, Bl, bm, bn, tid, wid, lane, acc);

    #pragma unroll
    for (int mi = 0; mi < 2; mi++) {
        const int r = bm + wid * 32 + mi * 16 + lq;
        #pragma unroll
        for (int ni = 0; ni < 8; ni++) {
            const int c = bn + ni * 8 + lk * 2;
            const float b0 = bias[c], b1 = bias[c + 1];
            float v0 = acc[mi][ni][0] + b0;
            float v1 = acc[mi][ni][1] + b1;
            float v2 = acc[mi][ni][2] + b0;
            float v3 = acc[mi][ni][3] + b1;
            const int hh = c >> 6, d = c & 63;
            const size_t i0 = ((size_t)hh * S_LEN + r) * HDIM + d;
            const size_t i1 = ((size_t)hh * S_LEN + r + 8) * HDIM + d;
            if (z == 0) {
                __half2 h01 = __floats2half2_rn(v0, v1);
                __half2 h23 = __floats2half2_rn(v2, v3);
                float2 f01 = __half22float2(h01);
                float2 f23 = __half22float2(h23);
                __half2 l01 = __floats2half2_rn(v0 - f01.x, v1 - f01.y);
                __half2 l23 = __floats2half2_rn(v2 - f23.x, v3 - f23.y);
                *(__half2*)&Qh[i0] = h01;  *(__half2*)&Ql[i0] = l01;
                *(__half2*)&Qh[i1] = h23;  *(__half2*)&Ql[i1] = l23;
            } else if (z == 1) {
                *(__half2*)&Kh[i0] = __floats2half2_rn(v0, v1);
                *(__half2*)&Kh[i1] = __floats2half2_rn(v2, v3);
            } else {
                Vh[(size_t)c * S_LEN + r]           = __float2half_rn(v0);
                Vh[(size_t)(c + 1) * S_LEN + r]     = __float2half_rn(v1);
                Vh[(size_t)c * S_LEN + r + 8]       = __float2half_rn(v2);
                Vh[(size_t)(c + 1) * S_LEN + r + 8] = __float2half_rn(v3);
            }
        }
    }
}

// Output projection: fp32 result
__global__ __launch_bounds__(128) void gemm_out(
    const __nv_bfloat16* __restrict__ Ah, const __nv_bfloat16* __restrict__ Al,
    const __nv_bfloat16* __restrict__ Bh, const __nv_bfloat16* __restrict__ Bl,
    const float* __restrict__ bias, float* __restrict__ Cf)
{
    extern __shared__ char sm[];
    const int tid = threadIdx.x;
    const int wid = tid >> 5;
    const int lane = tid & 31;
    const int lq = lane >> 2;
    const int lk = lane & 3;
    const int bm = blockIdx.y * 128;
    const int bn = blockIdx.x * 64;

    float acc[2][8][4];
    gemm_mainloop(sm, Ah, Al, Bh, Bl, bm, bn, tid, wid, lane, acc);

    #pragma unroll
    for (int mi = 0; mi < 2; mi++) {
        const int r = bm + wid * 32 + mi * 16 + lq;
        #pragma unroll
        for (int ni = 0; ni < 8; ni++) {
            const int c = bn + ni * 8 + lk * 2;
            const float b0 = bias[c], b1 = bias[c + 1];
            *(float2*)&Cf[(size_t)r * EMB + c] =
                make_float2(acc[mi][ni][0] + b0, acc[mi][ni][1] + b1);
            *(float2*)&Cf[(size_t)(r + 8) * EMB + c] =
                make_float2(acc[mi][ni][2] + b0, acc[mi][ni][3] + b1);
        }
    }
}

// ================= fp16 2-term flash attention, 3-stage pipeline =========
// smem (dynamic): K[3][64][72] @0 (9216/st), V[3][64][72] @27648,
//                 mask[3][64] f32 @55296 -> total 56064
#define AT_ST 9216
#define A_V_OFF 27648
#define A_M_OFF 55296
#define A_SMEM 56064

__global__ __launch_bounds__(128) void attn_mma(
    const __half* __restrict__ Qhf, const __half* __restrict__ Qlf,
    const __half* __restrict__ Khf, const __half* __restrict__ Vhf,
    const unsigned char* __restrict__ mask,
    __nv_bfloat16* __restrict__ Ohi, __nv_bfloat16* __restrict__ Olo)
{
    extern __shared__ char sm[];
    const int h   = blockIdx.y;
    const int q0  = blockIdx.x * 64;
    const int tid = threadIdx.x;
    const int wid = tid >> 5;
    const int lane = tid & 31;
    const int lq = lane >> 2;
    const int lk = lane & 3;

    const size_t hoff = (size_t)h * S_LEN * HDIM;
    // base-2 softmax: s2 = (q.k) * scale2, p = 2^(s2-m2)
    const float scale2 = 1.4426950408889634f * rsqrtf((float)EMB);

    const int qr = q0 + wid * 16 + lq;
    uint32_t aQh[4][4], aQl[4][4];
    {
        const __half* Qhp = Qhf + hoff;
        const __half* Qlp = Qlf + hoff;
        #pragma unroll
        for (int kc = 0; kc < 4; kc++) {
            const int c = kc * 16 + lk * 2;
            aQh[kc][0] = *(const uint32_t*)&Qhp[(size_t)qr * 64 + c];
            aQh[kc][1] = *(const uint32_t*)&Qhp[(size_t)(qr + 8) * 64 + c];
            aQh[kc][2] = *(const uint32_t*)&Qhp[(size_t)qr * 64 + c + 8];
            aQh[kc][3] = *(const uint32_t*)&Qhp[(size_t)(qr + 8) * 64 + c + 8];
            aQl[kc][0] = *(const uint32_t*)&Qlp[(size_t)qr * 64 + c];
            aQl[kc][1] = *(const uint32_t*)&Qlp[(size_t)(qr + 8) * 64 + c];
            aQl[kc][2] = *(const uint32_t*)&Qlp[(size_t)qr * 64 + c + 8];
            aQl[kc][3] = *(const uint32_t*)&Qlp[(size_t)(qr + 8) * 64 + c + 8];
        }
    }

    const int rsel = (lane & 7) + ((lane >> 4) << 3);
    const int csel = ((lane >> 3) & 1) << 3;
    const uint32_t base = smem_u32(sm);
    const uint32_t bK = base + (rsel * 72 + csel) * 2;
    float* smadd = (float*)(sm + A_M_OFF);

    const int trow = tid >> 1;
    const int tcol = (tid & 1) * 32;

    auto load_tile = [&](int s, int k0) {
        const __half* kh = Khf + hoff + (size_t)(k0 + trow) * 64 + tcol;
        const __half* vh = Vhf + hoff + (size_t)trow * S_LEN + k0 + tcol;
        const uint32_t d = base + s * AT_ST + (trow * 72 + tcol) * 2;
        #pragma unroll
        for (int i = 0; i < 4; i++) {
            cp16(d + i * 16,           kh + i * 8);
            cp16(d + A_V_OFF + i * 16, vh + i * 8);
        }
        if (tid < 64) smadd[s * 64 + tid] = mask[k0 + tid] ? -1e30f : 0.f;
    };

    float o[8][4];
    #pragma unroll
    for (int j = 0; j < 8; j++)
        #pragma unroll
        for (int i = 0; i < 4; i++) o[j][i] = 0.f;
    float mrow0 = -1e30f, mrow1 = -1e30f;
    float lrow0 = 0.f,    lrow1 = 0.f;

    load_tile(0, 0);
    CP_COMMIT();
    load_tile(1, 64);
    CP_COMMIT();

    const int NIT = S_LEN / 64;  // 64
    int cur = 0, nxt = 2;
    #pragma unroll 1
    for (int it = 0; it < NIT; it++) {
        CP_WAIT1();
        __syncthreads();
        // prefetch 2 tiles ahead into the stage all warps just finished with
        if (it + 2 < NIT) {
            load_tile(nxt, (it + 2) * 64);
            CP_COMMIT();
        }

        const uint32_t cK = bK + cur * AT_ST;
        const uint32_t cV = cK + A_V_OFF;
        const float* md = smadd + cur * 64;

        // ---- S = Q K^T  (2 fp16 mmas per fragment pair) ----
        float s[8][4];
        #pragma unroll
        for (int j = 0; j < 8; j++)
            s[j][0] = s[j][1] = s[j][2] = s[j][3] = 0.f;

        #pragma unroll
        for (int jp = 0; jp < 4; jp++) {
            #pragma unroll
            for (int kc = 0; kc < 4; kc++) {
                const uint32_t off = (uint32_t)(jp * 2304 + kc * 32);
                uint32_t h0, h1, h2, h3;
                ldsm_x4(h0, h1, h2, h3, cK + off);
                mma_f16(s[2 * jp],     aQh[kc], h0, h1);
                mma_f16(s[2 * jp],     aQl[kc], h0, h1);
                mma_f16(s[2 * jp + 1], aQh[kc], h2, h3);
                mma_f16(s[2 * jp + 1], aQl[kc], h2, h3);
            }
        }

        #pragma unroll
        for (int j = 0; j < 8; j++) {
            const float m0 = md[j * 8 + lk * 2];
            const float m1 = md[j * 8 + lk * 2 + 1];
            s[j][0] = s[j][0] * scale2 + m0;
            s[j][1] = s[j][1] * scale2 + m1;
            s[j][2] = s[j][2] * scale2 + m0;
            s[j][3] = s[j][3] * scale2 + m1;
        }

        // ---- online softmax (base 2) ----
        float rm0 = -1e30f, rm1 = -1e30f;
        #pragma unroll
        for (int j = 0; j < 8; j++) {
            rm0 = fmaxf(rm0, fmaxf(s[j][0], s[j][1]));
            rm1 = fmaxf(rm1, fmaxf(s[j][2], s[j][3]));
        }
        rm0 = fmaxf(rm0, __shfl_xor_sync(0xffffffffu, rm0, 1));
        rm0 = fmaxf(rm0, __shfl_xor_sync(0xffffffffu, rm0, 2));
        rm1 = fmaxf(rm1, __shfl_xor_sync(0xffffffffu, rm1, 1));
        rm1 = fmaxf(rm1, __shfl_xor_sync(0xffffffffu, rm1, 2));

        const float mn0 = fmaxf(mrow0, rm0);
        const float mn1 = fmaxf(mrow1, rm1);
        const float corr0 = ex2(mrow0 - mn0);
        const float corr1 = ex2(mrow1 - mn1);
        mrow0 = mn0; mrow1 = mn1;

        float ps0 = 0.f, ps1 = 0.f;
        #pragma unroll
        for (int j = 0; j < 8; j++) {
            s[j][0] = ex2(s[j][0] - mn0);
            s[j][1] = ex2(s[j][1] - mn0);
            s[j][2] = ex2(s[j][2] - mn1);
            s[j][3] = ex2(s[j][3] - mn1);
            ps0 += s[j][0] + s[j][1];
            ps1 += s[j][2] + s[j][3];
        }
        ps0 += __shfl_xor_sync(0xffffffffu, ps0, 1);
        ps0 += __shfl_xor_sync(0xffffffffu, ps0, 2);
        ps1 += __shfl_xor_sync(0xffffffffu, ps1, 1);
        ps1 += __shfl_xor_sync(0xffffffffu, ps1, 2);
        lrow0 = lrow0 * corr0 + ps0;
        lrow1 = lrow1 * corr1 + ps1;

        #pragma unroll
        for (int j = 0; j < 8; j++) {
            o[j][0] *= corr0; o[j][1] *= corr0;
            o[j][2] *= corr1; o[j][3] *= corr1;
        }

        // ---- P fragments (fp16 split) ----
        uint32_t ph[4][4], pl[4][4];
        #pragma unroll
        for (int kc = 0; kc < 4; kc++) {
            #pragma unroll
            for (int half = 0; half < 2; half++) {
                const int j = 2 * kc + half;
                __half2 h01 = __floats2half2_rn(s[j][0], s[j][1]);
                __half2 h23 = __floats2half2_rn(s[j][2], s[j][3]);
                float2 f01 = __half22float2(h01);
                float2 f23 = __half22float2(h23);
                __half2 l01 = __floats2half2_rn(s[j][0] - f01.x, s[j][1] - f01.y);
                __half2 l23 = __floats2half2_rn(s[j][2] - f23.x, s[j][3] - f23.y);
                ph[kc][2 * half + 0] = *(uint32_t*)&h01;
                ph[kc][2 * half + 1] = *(uint32_t*)&h23;
                pl[kc][2 * half + 0] = *(uint32_t*)&l01;
                pl[kc][2 * half + 1] = *(uint32_t*)&l23;
            }
        }

        // ---- O += P V  (2 fp16 mmas per fragment pair) ----
        #pragma unroll
        for (int jp = 0; jp < 4; jp++) {
            #pragma unroll
            for (int kc = 0; kc < 4; kc++) {
                const uint32_t off = (uint32_t)(jp * 2304 + kc * 32);
                uint32_t h0, h1, h2, h3;
                ldsm_x4(h0, h1, h2, h3, cV + off);
                mma_f16(o[2 * jp],     ph[kc], h0, h1);
                mma_f16(o[2 * jp],     pl[kc], h0, h1);
                mma_f16(o[2 * jp + 1], ph[kc], h2, h3);
                mma_f16(o[2 * jp + 1], pl[kc], h2, h3);
            }
        }

        cur = (cur == 2) ? 0 : cur + 1;
        nxt = (nxt == 2) ? 0 : nxt + 1;
    }

    // ---- epilogue: bf16 hi/lo attention output ----
    const float inv0 = 1.0f / lrow0;
    const float inv1 = 1.0f / lrow1;
    #pragma unroll
    for (int j = 0; j < 8; j++) {
        const float v0 = o[j][0] * inv0, v1 = o[j][1] * inv0;
        const float v2 = o[j][2] * inv1, v3 = o[j][3] * inv1;
        const int c = h * 64 + j * 8 + lk * 2;
        const size_t i0 = (size_t)qr * EMB + c;
        const size_t i1 = (size_t)(qr + 8) * EMB + c;
        __nv_bfloat16 h0, h1, h2, h3, l0, l1, l2, l3;
        fsplit(v0, h0, l0); fsplit(v1, h1, l1);
        fsplit(v2, h2, l2); fsplit(v3, h3, l3);
        *(__nv_bfloat162*)&Ohi[i0] = __nv_bfloat162{h0, h1};
        *(__nv_bfloat162*)&Olo[i0] = __nv_bfloat162{l0, l1};
        *(__nv_bfloat162*)&Ohi[i1] = __nv_bfloat162{h2, h3};
        *(__nv_bfloat162*)&Olo[i1] = __nv_bfloat162{l2, l3};
    }
}

// ---------------- launch ----------------
extern "C" void kernel_launch(void* const* d_in, const int* in_sizes, int n_in,
                              void* d_out, int out_size)
{
    const float* x  = (const float*)d_in[0];
    const unsigned char* mask = (const unsigned char*)d_in[1];
    const float* Wq = (const float*)d_in[2];
    const float* bq = (const float*)d_in[3];
    const float* Wk = (const float*)d_in[4];
    const float* bk = (const float*)d_in[5];
    const float* Wv = (const float*)d_in[6];
    const float* bv = (const float*)d_in[7];
    const float* Wo = (const float*)d_in[8];
    const float* bo = (const float*)d_in[9];
    float* out = (float*)d_out;

    __nv_bfloat16 *xh, *xl, *wh, *wl, *ath, *atl;
    __half *Qh, *Ql, *Kh, *Vh;
    cudaGetSymbolAddress((void**)&xh, g_xh);
    cudaGetSymbolAddress((void**)&xl, g_xl);
    cudaGetSymbolAddress((void**)&wh, g_wh);
    cudaGetSymbolAddress((void**)&wl, g_wl);
    cudaGetSymbolAddress((void**)&Qh, g_Qhf);
    cudaGetSymbolAddress((void**)&Ql, g_Qlf);
    cudaGetSymbolAddress((void**)&Kh, g_Khf);
    cudaGetSymbolAddress((void**)&Vh, g_Vhf);
    cudaGetSymbolAddress((void**)&ath, g_ath);
    cudaGetSymbolAddress((void**)&atl, g_atl);

    cudaFuncSetAttribute(gemm_qkv, cudaFuncAttributeMaxDynamicSharedMemorySize, G_SMEM);
    cudaFuncSetAttribute(gemm_out, cudaFuncAttributeMaxDynamicSharedMemorySize, G_SMEM);
    cudaFuncSetAttribute(attn_mma, cudaFuncAttributeMaxDynamicSharedMemorySize, A_SMEM);

    const int nx4 = S_LEN * EMB / 4;
    const int nw4 = WW / 4;
    split_kernel<<<(nx4 + 255) / 256, 256>>>(x, xh, xl, nx4);
    dim3 wgrid((nw4 + 255) / 256, 4);
    split_w_kernel<<<wgrid, 256>>>(Wq, Wk, Wv, Wo, wh, wl, nw4);

    dim3 qgrid(EMB / 64, S_LEN / 128, 3);   // (12, 32, 3)
    gemm_qkv<<<qgrid, 128, G_SMEM>>>(xh, xl, wh, wl, bq, bk, bv,
                                     Qh, Ql, Kh, Vh);

    dim3 agrid(S_LEN / 64, NHEAD);          // (64, 12)
    attn_mma<<<agrid, 128, A_SMEM>>>(Qh, Ql, Kh, Vh, mask, ath, atl);

    dim3 ogrid(EMB / 64, S_LEN / 128);      // (12, 32)
    gemm_out<<<ogrid, 128, G_SMEM>>>(ath, atl, wh + 3 * WW, wl + 3 * WW, bo, out);
}

// round 7
// speedup vs baseline: 5.2319x; 1.2355x over previous
#include <cuda_runtime.h>
#include <cuda_bf16.h>
#include <cuda_fp16.h>
#include <cstdint>

#define S_LEN 4096
#define EMB   768
#define NHEAD 12
#define HDIM  64
#define WW    (EMB * EMB)

// ---------------- scratch (no allocations allowed) ----------------
__device__ __nv_bfloat16 g_xh[S_LEN * EMB];
__device__ __nv_bfloat16 g_xl[S_LEN * EMB];
__device__ __nv_bfloat16 g_wh[4][EMB * EMB];
__device__ __nv_bfloat16 g_wl[4][EMB * EMB];
__device__ __half g_Qhf[NHEAD * S_LEN * HDIM];   // [H][S][D] fp16, pre-scaled by log2e/sqrt(E)
__device__ __half g_Khf[NHEAD * S_LEN * HDIM];   // [H][S][D] fp16
__device__ __half g_Vhf[NHEAD * HDIM * S_LEN];   // [H][D][S] fp16 (transposed)
__device__ __nv_bfloat16 g_ath[S_LEN * EMB];     // attn out hi (bf16 split)
__device__ __nv_bfloat16 g_atl[S_LEN * EMB];

__device__ __forceinline__ void fsplit(float v, __nv_bfloat16& h, __nv_bfloat16& l)
{
    h = __float2bfloat16(v);
    l = __float2bfloat16(v - __bfloat162float(h));
}

__device__ __forceinline__ uint32_t smem_u32(const void* p)
{
    return (uint32_t)__cvta_generic_to_shared(p);
}

__device__ __forceinline__ void cp16(uint32_t saddr, const void* g)
{
    asm volatile("cp.async.cg.shared.global [%0], [%1], 16;" :: "r"(saddr), "l"(g));
}
#define CP_COMMIT() asm volatile("cp.async.commit_group;")
#define CP_WAIT1()  asm volatile("cp.async.wait_group 1;")
#define CP_WAIT0()  asm volatile("cp.async.wait_group 0;")

__device__ __forceinline__ void ldsm_x4(uint32_t& r0, uint32_t& r1,
                                        uint32_t& r2, uint32_t& r3, uint32_t addr)
{
    asm volatile("ldmatrix.sync.aligned.m8n8.x4.shared.b16 {%0,%1,%2,%3}, [%4];"
                 : "=r"(r0), "=r"(r1), "=r"(r2), "=r"(r3) : "r"(addr));
}

// bf16 mma (projections)
__device__ __forceinline__ void mma_bf(float* c, const uint32_t* a,
                                       uint32_t b0, uint32_t b1)
{
    asm volatile(
        "mma.sync.aligned.m16n8k16.row.col.f32.bf16.bf16.f32 "
        "{%0,%1,%2,%3},{%4,%5,%6,%7},{%8,%9},{%0,%1,%2,%3};"
        : "+f"(c[0]), "+f"(c[1]), "+f"(c[2]), "+f"(c[3])
        : "r"(a[0]), "r"(a[1]), "r"(a[2]), "r"(a[3]), "r"(b0), "r"(b1));
}

// fp16 mma (attention)
__device__ __forceinline__ void mma_f16(float* c, const uint32_t* a,
                                        uint32_t b0, uint32_t b1)
{
    asm volatile(
        "mma.sync.aligned.m16n8k16.row.col.f32.f16.f16.f32 "
        "{%0,%1,%2,%3},{%4,%5,%6,%7},{%8,%9},{%0,%1,%2,%3};"
        : "+f"(c[0]), "+f"(c[1]), "+f"(c[2]), "+f"(c[3])
        : "r"(a[0]), "r"(a[1]), "r"(a[2]), "r"(a[3]), "r"(b0), "r"(b1));
}

__device__ __forceinline__ float ex2(float x)
{
    float r;
    asm("ex2.approx.f32 %0, %1;" : "=f"(r) : "f"(x));
    return r;
}

// ---------------- fp32 -> bf16 hi/lo split ----------------
__global__ __launch_bounds__(256) void split_kernel(
    const float* __restrict__ in, __nv_bfloat16* __restrict__ hi,
    __nv_bfloat16* __restrict__ lo, int n4)
{
    const int i = blockIdx.x * 256 + threadIdx.x;
    if (i >= n4) return;
    float4 v = ((const float4*)in)[i];
    __nv_bfloat16 h0, h1, h2, h3, l0, l1, l2, l3;
    fsplit(v.x, h0, l0); fsplit(v.y, h1, l1);
    fsplit(v.z, h2, l2); fsplit(v.w, h3, l3);
    __nv_bfloat162* hp = (__nv_bfloat162*)(hi + i * 4);
    __nv_bfloat162* lp = (__nv_bfloat162*)(lo + i * 4);
    hp[0] = __nv_bfloat162{h0, h1}; hp[1] = __nv_bfloat162{h2, h3};
    lp[0] = __nv_bfloat162{l0, l1}; lp[1] = __nv_bfloat162{l2, l3};
}

__global__ __launch_bounds__(256) void split_w_kernel(
    const float* __restrict__ w0, const float* __restrict__ w1,
    const float* __restrict__ w2, const float* __restrict__ w3,
    __nv_bfloat16* __restrict__ hi, __nv_bfloat16* __restrict__ lo, int n4)
{
    const int i = blockIdx.x * 256 + threadIdx.x;
    if (i >= n4) return;
    const float* src = (blockIdx.y == 0) ? w0 : (blockIdx.y == 1) ? w1
                     : (blockIdx.y == 2) ? w2 : w3;
    const size_t off = (size_t)blockIdx.y * WW;
    float4 v = ((const float4*)src)[i];
    __nv_bfloat16 h0, h1, h2, h3, l0, l1, l2, l3;
    fsplit(v.x, h0, l0); fsplit(v.y, h1, l1);
    fsplit(v.z, h2, l2); fsplit(v.w, h3, l3);
    __nv_bfloat162* hp = (__nv_bfloat162*)(hi + off + i * 4);
    __nv_bfloat162* lp = (__nv_bfloat162*)(lo + off + i * 4);
    hp[0] = __nv_bfloat162{h0, h1}; hp[1] = __nv_bfloat162{h2, h3};
    lp[0] = __nv_bfloat162{l0, l1}; lp[1] = __nv_bfloat162{l2, l3};
}

// ================= pipelined bf16-split GEMM core =================
#define GA_ST 10240
#define GB_ST 5120
#define G_SMEM 61440

__device__ __forceinline__ void gemm_load_stage(
    char* sm, int s, int k0,
    const __nv_bfloat16* __restrict__ Ah, const __nv_bfloat16* __restrict__ Al,
    const __nv_bfloat16* __restrict__ Bh, const __nv_bfloat16* __restrict__ Bl,
    int bm, int bn, int tid)
{
    const __nv_bfloat16* ah = Ah + (size_t)(bm + tid) * EMB + k0;
    const __nv_bfloat16* al = Al + (size_t)(bm + tid) * EMB + k0;
    uint32_t dA = smem_u32(sm) + s * GA_ST + tid * 80;
    #pragma unroll
    for (int i = 0; i < 4; i++) {
        cp16(dA + i * 16, ah + i * 8);
        cp16(dA + 20480 + i * 16, al + i * 8);
    }
    const int brow = tid >> 1;
    const int bcol = (tid & 1) * 16;
    const __nv_bfloat16* bh = Bh + (size_t)(bn + brow) * EMB + k0 + bcol;
    const __nv_bfloat16* bl = Bl + (size_t)(bn + brow) * EMB + k0 + bcol;
    uint32_t dB = smem_u32(sm) + 40960 + s * GB_ST + brow * 80 + bcol * 2;
    cp16(dB, bh);           cp16(dB + 16, bh + 8);
    cp16(dB + 10240, bl);   cp16(dB + 10240 + 16, bl + 8);
}

__device__ __forceinline__ void gemm_mainloop(
    char* sm,
    const __nv_bfloat16* __restrict__ Ah, const __nv_bfloat16* __restrict__ Al,
    const __nv_bfloat16* __restrict__ Bh, const __nv_bfloat16* __restrict__ Bl,
    int bm, int bn, int tid, int wid, int lane, float acc[2][8][4])
{
    #pragma unroll
    for (int mi = 0; mi < 2; mi++)
        #pragma unroll
        for (int ni = 0; ni < 8; ni++)
            #pragma unroll
            for (int i = 0; i < 4; i++) acc[mi][ni][i] = 0.f;

    const int rselA = lane & 15;
    const int cselA = (lane >> 4) << 3;
    const int rselB = (lane & 7) + ((lane >> 4) << 3);
    const int cselB = ((lane >> 3) & 1) << 3;
    const uint32_t base = smem_u32(sm);
    const uint32_t bAh = base + ((wid * 32 + rselA) * 40 + cselA) * 2;
    const uint32_t bBh = base + 40960 + (rselB * 40 + cselB) * 2;

    gemm_load_stage(sm, 0, 0, Ah, Al, Bh, Bl, bm, bn, tid);
    CP_COMMIT();

    const int NIT = EMB / 32;  // 24
    #pragma unroll 1
    for (int it = 0; it < NIT; it++) {
        const int cur = it & 1;
        if (it + 1 < NIT) {
            gemm_load_stage(sm, cur ^ 1, (it + 1) * 32, Ah, Al, Bh, Bl, bm, bn, tid);
            CP_COMMIT();
            CP_WAIT1();
        } else {
            CP_WAIT0();
        }
        __syncthreads();

        const uint32_t cAh = bAh + cur * GA_ST;
        const uint32_t cAl = cAh + 20480;
        const uint32_t cBh = bBh + cur * GB_ST;
        const uint32_t cBl = cBh + 10240;

        #pragma unroll
        for (int ks = 0; ks < 32; ks += 16) {
            uint32_t fah[2][4], fal[2][4];
            #pragma unroll
            for (int mi = 0; mi < 2; mi++) {
                const uint32_t off = (uint32_t)(mi * 16 * 80 + ks * 2);
                ldsm_x4(fah[mi][0], fah[mi][1], fah[mi][2], fah[mi][3], cAh + off);
                ldsm_x4(fal[mi][0], fal[mi][1], fal[mi][2], fal[mi][3], cAl + off);
            }
            #pragma unroll
            for (int nip = 0; nip < 4; nip++) {
                const uint32_t off = (uint32_t)(nip * 16 * 80 + ks * 2);
                uint32_t h0, h1, h2, h3, l0, l1, l2, l3;
                ldsm_x4(h0, h1, h2, h3, cBh + off);
                ldsm_x4(l0, l1, l2, l3, cBl + off);
                #pragma unroll
                for (int mi = 0; mi < 2; mi++) {
                    mma_bf(acc[mi][2 * nip],     fah[mi], h0, h1);
                    mma_bf(acc[mi][2 * nip],     fah[mi], l0, l1);
                    mma_bf(acc[mi][2 * nip],     fal[mi], h0, h1);
                    mma_bf(acc[mi][2 * nip + 1], fah[mi], h2, h3);
                    mma_bf(acc[mi][2 * nip + 1], fah[mi], l2, l3);
                    mma_bf(acc[mi][2 * nip + 1], fal[mi], h2, h3);
                }
            }
        }
        __syncthreads();
    }
}

// QKV projection: grid (12, 32, 3); z: 0=Q (fp16, pre-scaled), 1=K (fp16), 2=V (fp16, T)
__global__ __launch_bounds__(128) void gemm_qkv(
    const __nv_bfloat16* __restrict__ xh, const __nv_bfloat16* __restrict__ xl,
    const __nv_bfloat16* __restrict__ wh, const __nv_bfloat16* __restrict__ wl,
    const float* __restrict__ bq, const float* __restrict__ bk,
    const float* __restrict__ bv,
    __half* __restrict__ Qh, __half* __restrict__ Kh, __half* __restrict__ Vh)
{
    extern __shared__ char sm[];
    const int z = blockIdx.z;
    const int tid = threadIdx.x;
    const int wid = tid >> 5;
    const int lane = tid & 31;
    const int lq = lane >> 2;
    const int lk = lane & 3;
    const int bm = blockIdx.y * 128;
    const int bn = blockIdx.x * 64;

    const __nv_bfloat16* Bh = wh + (size_t)z * WW;
    const __nv_bfloat16* Bl = wl + (size_t)z * WW;
    const float* bias = (z == 0) ? bq : (z == 1) ? bk : bv;
    // base-2 softmax scale folded into Q
    const float qs = (z == 0) ? 1.4426950408889634f * rsqrtf((float)EMB) : 1.0f;

    float acc[2][8][4];
    gemm_mainloop(sm, xh, xl, Bh, Bl, bm, bn, tid, wid, lane, acc);

    #pragma unroll
    for (int mi = 0; mi < 2; mi++) {
        const int r = bm + wid * 32 + mi * 16 + lq;
        #pragma unroll
        for (int ni = 0; ni < 8; ni++) {
            const int c = bn + ni * 8 + lk * 2;
            const float b0 = bias[c], b1 = bias[c + 1];
            float v0 = (acc[mi][ni][0] + b0) * qs;
            float v1 = (acc[mi][ni][1] + b1) * qs;
            float v2 = (acc[mi][ni][2] + b0) * qs;
            float v3 = (acc[mi][ni][3] + b1) * qs;
            const int hh = c >> 6, d = c & 63;
            const size_t i0 = ((size_t)hh * S_LEN + r) * HDIM + d;
            const size_t i1 = ((size_t)hh * S_LEN + r + 8) * HDIM + d;
            if (z == 0) {
                *(__half2*)&Qh[i0] = __floats2half2_rn(v0, v1);
                *(__half2*)&Qh[i1] = __floats2half2_rn(v2, v3);
            } else if (z == 1) {
                *(__half2*)&Kh[i0] = __floats2half2_rn(v0, v1);
                *(__half2*)&Kh[i1] = __floats2half2_rn(v2, v3);
            } else {
                Vh[(size_t)c * S_LEN + r]           = __float2half_rn(v0);
                Vh[(size_t)(c + 1) * S_LEN + r]     = __float2half_rn(v1);
                Vh[(size_t)c * S_LEN + r + 8]       = __float2half_rn(v2);
                Vh[(size_t)(c + 1) * S_LEN + r + 8] = __float2half_rn(v3);
            }
        }
    }
}

// Output projection: fp32 result
__global__ __launch_bounds__(128) void gemm_out(
    const __nv_bfloat16* __restrict__ Ah, const __nv_bfloat16* __restrict__ Al,
    const __nv_bfloat16* __restrict__ Bh, const __nv_bfloat16* __restrict__ Bl,
    const float* __restrict__ bias, float* __restrict__ Cf)
{
    extern __shared__ char sm[];
    const int tid = threadIdx.x;
    const int wid = tid >> 5;
    const int lane = tid & 31;
    const int lq = lane >> 2;
    const int lk = lane & 3;
    const int bm = blockIdx.y * 128;
    const int bn = blockIdx.x * 64;

    float acc[2][8][4];
    gemm_mainloop(sm, Ah, Al, Bh, Bl, bm, bn, tid, wid, lane, acc);

    #pragma unroll
    for (int mi = 0; mi < 2; mi++) {
        const int r = bm + wid * 32 + mi * 16 + lq;
        #pragma unroll
        for (int ni = 0; ni < 8; ni++) {
            const int c = bn + ni * 8 + lk * 2;
            const float b0 = bias[c], b1 = bias[c + 1];
            *(float2*)&Cf[(size_t)r * EMB + c] =
                make_float2(acc[mi][ni][0] + b0, acc[mi][ni][1] + b1);
            *(float2*)&Cf[(size_t)(r + 8) * EMB + c] =
                make_float2(acc[mi][ni][2] + b0, acc[mi][ni][3] + b1);
        }
    }
}

// ================= fp16 flash attention, 3-stage pipeline =========
// smem: K[3][64][72] @0 (9216/st), V[3][64][72] @27648, mask[3][64] f32 @55296
#define AT_ST 9216
#define A_V_OFF 27648
#define A_M_OFF 55296
#define A_SMEM 56064

__global__ __launch_bounds__(128) void attn_mma(
    const __half* __restrict__ Qhf, const __half* __restrict__ Khf,
    const __half* __restrict__ Vhf,
    const unsigned char* __restrict__ mask,
    __nv_bfloat16* __restrict__ Ohi, __nv_bfloat16* __restrict__ Olo)
{
    extern __shared__ char sm[];
    const int h   = blockIdx.y;
    const int q0  = blockIdx.x * 64;
    const int tid = threadIdx.x;
    const int wid = tid >> 5;
    const int lane = tid & 31;
    const int lq = lane >> 2;
    const int lk = lane & 3;

    const size_t hoff = (size_t)h * S_LEN * HDIM;

    const int qr = q0 + wid * 16 + lq;
    uint32_t aQh[4][4];
    {
        const __half* Qhp = Qhf + hoff;
        #pragma unroll
        for (int kc = 0; kc < 4; kc++) {
            const int c = kc * 16 + lk * 2;
            aQh[kc][0] = *(const uint32_t*)&Qhp[(size_t)qr * 64 + c];
            aQh[kc][1] = *(const uint32_t*)&Qhp[(size_t)(qr + 8) * 64 + c];
            aQh[kc][2] = *(const uint32_t*)&Qhp[(size_t)qr * 64 + c + 8];
            aQh[kc][3] = *(const uint32_t*)&Qhp[(size_t)(qr + 8) * 64 + c + 8];
        }
    }

    const int rsel = (lane & 7) + ((lane >> 4) << 3);
    const int csel = ((lane >> 3) & 1) << 3;
    const uint32_t base = smem_u32(sm);
    const uint32_t bK = base + (rsel * 72 + csel) * 2;
    float* smadd = (float*)(sm + A_M_OFF);

    const int trow = tid >> 1;
    const int tcol = (tid & 1) * 32;

    auto load_tile = [&](int s, int k0) {
        const __half* kh = Khf + hoff + (size_t)(k0 + trow) * 64 + tcol;
        const __half* vh = Vhf + hoff + (size_t)trow * S_LEN + k0 + tcol;
        const uint32_t d = base + s * AT_ST + (trow * 72 + tcol) * 2;
        #pragma unroll
        for (int i = 0; i < 4; i++) {
            cp16(d + i * 16,           kh + i * 8);
            cp16(d + A_V_OFF + i * 16, vh + i * 8);
        }
        if (tid < 64) smadd[s * 64 + tid] = mask[k0 + tid] ? -1e30f : 0.f;
    };

    float o[8][4];
    #pragma unroll
    for (int j = 0; j < 8; j++)
        #pragma unroll
        for (int i = 0; i < 4; i++) o[j][i] = 0.f;
    float mrow0 = -1e30f, mrow1 = -1e30f;
    float lrow0 = 0.f,    lrow1 = 0.f;

    load_tile(0, 0);
    CP_COMMIT();
    load_tile(1, 64);
    CP_COMMIT();

    const int NIT = S_LEN / 64;  // 64
    int cur = 0, nxt = 2;
    #pragma unroll 1
    for (int it = 0; it < NIT; it++) {
        CP_WAIT1();
        __syncthreads();
        if (it + 2 < NIT) {
            load_tile(nxt, (it + 2) * 64);
            CP_COMMIT();
        }

        const uint32_t cK = bK + cur * AT_ST;
        const uint32_t cV = cK + A_V_OFF;
        const float* md = smadd + cur * 64;

        // ---- S = Q K^T (Q pre-scaled to base-2 domain) ----
        float s[8][4];
        #pragma unroll
        for (int j = 0; j < 8; j++)
            s[j][0] = s[j][1] = s[j][2] = s[j][3] = 0.f;

        #pragma unroll
        for (int jp = 0; jp < 4; jp++) {
            #pragma unroll
            for (int kc = 0; kc < 4; kc++) {
                const uint32_t off = (uint32_t)(jp * 2304 + kc * 32);
                uint32_t h0, h1, h2, h3;
                ldsm_x4(h0, h1, h2, h3, cK + off);
                mma_f16(s[2 * jp],     aQh[kc], h0, h1);
                mma_f16(s[2 * jp + 1], aQh[kc], h2, h3);
            }
        }

        #pragma unroll
        for (int j = 0; j < 8; j++) {
            const float m0 = md[j * 8 + lk * 2];
            const float m1 = md[j * 8 + lk * 2 + 1];
            s[j][0] += m0; s[j][1] += m1;
            s[j][2] += m0; s[j][3] += m1;
        }

        // ---- online softmax (base 2) ----
        float rm0 = -1e30f, rm1 = -1e30f;
        #pragma unroll
        for (int j = 0; j < 8; j++) {
            rm0 = fmaxf(rm0, fmaxf(s[j][0], s[j][1]));
            rm1 = fmaxf(rm1, fmaxf(s[j][2], s[j][3]));
        }
        rm0 = fmaxf(rm0, __shfl_xor_sync(0xffffffffu, rm0, 1));
        rm0 = fmaxf(rm0, __shfl_xor_sync(0xffffffffu, rm0, 2));
        rm1 = fmaxf(rm1, __shfl_xor_sync(0xffffffffu, rm1, 1));
        rm1 = fmaxf(rm1, __shfl_xor_sync(0xffffffffu, rm1, 2));

        const float mn0 = fmaxf(mrow0, rm0);
        const float mn1 = fmaxf(mrow1, rm1);
        const float corr0 = ex2(mrow0 - mn0);
        const float corr1 = ex2(mrow1 - mn1);
        mrow0 = mn0; mrow1 = mn1;

        float ps0 = 0.f, ps1 = 0.f;
        #pragma unroll
        for (int j = 0; j < 8; j++) {
            s[j][0] = ex2(s[j][0] - mn0);
            s[j][1] = ex2(s[j][1] - mn0);
            s[j][2] = ex2(s[j][2] - mn1);
            s[j][3] = ex2(s[j][3] - mn1);
            ps0 += s[j][0] + s[j][1];
            ps1 += s[j][2] + s[j][3];
        }
        ps0 += __shfl_xor_sync(0xffffffffu, ps0, 1);
        ps0 += __shfl_xor_sync(0xffffffffu, ps0, 2);
        ps1 += __shfl_xor_sync(0xffffffffu, ps1, 1);
        ps1 += __shfl_xor_sync(0xffffffffu, ps1, 2);
        lrow0 = lrow0 * corr0 + ps0;
        lrow1 = lrow1 * corr1 + ps1;

        #pragma unroll
        for (int j = 0; j < 8; j++) {
            o[j][0] *= corr0; o[j][1] *= corr0;
            o[j][2] *= corr1; o[j][3] *= corr1;
        }

        // ---- P fragments (fp16, hi only) ----
        uint32_t ph[4][4];
        #pragma unroll
        for (int kc = 0; kc < 4; kc++) {
            #pragma unroll
            for (int half = 0; half < 2; half++) {
                const int j = 2 * kc + half;
                __half2 h01 = __floats2half2_rn(s[j][0], s[j][1]);
                __half2 h23 = __floats2half2_rn(s[j][2], s[j][3]);
                ph[kc][2 * half + 0] = *(uint32_t*)&h01;
                ph[kc][2 * half + 1] = *(uint32_t*)&h23;
            }
        }

        // ---- O += P V ----
        #pragma unroll
        for (int jp = 0; jp < 4; jp++) {
            #pragma unroll
            for (int kc = 0; kc < 4; kc++) {
                const uint32_t off = (uint32_t)(jp * 2304 + kc * 32);
                uint32_t h0, h1, h2, h3;
                ldsm_x4(h0, h1, h2, h3, cV + off);
                mma_f16(o[2 * jp],     ph[kc], h0, h1);
                mma_f16(o[2 * jp + 1], ph[kc], h2, h3);
            }
        }

        cur = (cur == 2) ? 0 : cur + 1;
        nxt = (nxt == 2) ? 0 : nxt + 1;
    }

    // ---- epilogue: bf16 hi/lo attention output ----
    const float inv0 = 1.0f / lrow0;
    const float inv1 = 1.0f / lrow1;
    #pragma unroll
    for (int j = 0; j < 8; j++) {
        const float v0 = o[j][0] * inv0, v1 = o[j][1] * inv0;
        const float v2 = o[j][2] * inv1, v3 = o[j][3] * inv1;
        const int c = h * 64 + j * 8 + lk * 2;
        const size_t i0 = (size_t)qr * EMB + c;
        const size_t i1 = (size_t)(qr + 8) * EMB + c;
        __nv_bfloat16 h0, h1, h2, h3, l0, l1, l2, l3;
        fsplit(v0, h0, l0); fsplit(v1, h1, l1);
        fsplit(v2, h2, l2); fsplit(v3, h3, l3);
        *(__nv_bfloat162*)&Ohi[i0] = __nv_bfloat162{h0, h1};
        *(__nv_bfloat162*)&Olo[i0] = __nv_bfloat162{l0, l1};
        *(__nv_bfloat162*)&Ohi[i1] = __nv_bfloat162{h2, h3};
        *(__nv_bfloat162*)&Olo[i1] = __nv_bfloat162{l2, l3};
    }
}

// ---------------- launch ----------------
extern "C" void kernel_launch(void* const* d_in, const int* in_sizes, int n_in,
                              void* d_out, int out_size)
{
    const float* x  = (const float*)d_in[0];
    const unsigned char* mask = (const unsigned char*)d_in[1];
    const float* Wq = (const float*)d_in[2];
    const float* bq = (const float*)d_in[3];
    const float* Wk = (const float*)d_in[4];
    const float* bk = (const float*)d_in[5];
    const float* Wv = (const float*)d_in[6];
    const float* bv = (const float*)d_in[7];
    const float* Wo = (const float*)d_in[8];
    const float* bo = (const float*)d_in[9];
    float* out = (float*)d_out;

    __nv_bfloat16 *xh, *xl, *wh, *wl, *ath, *atl;
    __half *Qh, *Kh, *Vh;
    cudaGetSymbolAddress((void**)&xh, g_xh);
    cudaGetSymbolAddress((void**)&xl, g_xl);
    cudaGetSymbolAddress((void**)&wh, g_wh);
    cudaGetSymbolAddress((void**)&wl, g_wl);
    cudaGetSymbolAddress((void**)&Qh, g_Qhf);
    cudaGetSymbolAddress((void**)&Kh, g_Khf);
    cudaGetSymbolAddress((void**)&Vh, g_Vhf);
    cudaGetSymbolAddress((void**)&ath, g_ath);
    cudaGetSymbolAddress((void**)&atl, g_atl);

    cudaFuncSetAttribute(gemm_qkv, cudaFuncAttributeMaxDynamicSharedMemorySize, G_SMEM);
    cudaFuncSetAttribute(gemm_out, cudaFuncAttributeMaxDynamicSharedMemorySize, G_SMEM);
    cudaFuncSetAttribute(attn_mma, cudaFuncAttributeMaxDynamicSharedMemorySize, A_SMEM);

    const int nx4 = S_LEN * EMB / 4;
    const int nw4 = WW / 4;
    split_kernel<<<(nx4 + 255) / 256, 256>>>(x, xh, xl, nx4);
    dim3 wgrid((nw4 + 255) / 256, 4);
    split_w_kernel<<<wgrid, 256>>>(Wq, Wk, Wv, Wo, wh, wl, nw4);

    dim3 qgrid(EMB / 64, S_LEN / 128, 3);   // (12, 32, 3)
    gemm_qkv<<<qgrid, 128, G_SMEM>>>(xh, xl, wh, wl, bq, bk, bv, Qh, Kh, Vh);

    dim3 agrid(S_LEN / 64, NHEAD);          // (64, 12)
    attn_mma<<<agrid, 128, A_SMEM>>>(Qh, Kh, Vh, mask, ath, atl);

    dim3 ogrid(EMB / 64, S_LEN / 128);      // (12, 32)
    gemm_out<<<ogrid, 128, G_SMEM>>>(ath, atl, wh + 3 * WW, wl + 3 * WW, bo, out);
}

// round 8
// speedup vs baseline: 5.9528x; 1.1378x over previous
#include <cuda_runtime.h>
#include <cuda_bf16.h>
#include <cuda_fp16.h>
#include <cstdint>

#define S_LEN 4096
#define EMB   768
#define NHEAD 12
#define HDIM  64
#define WW    (EMB * EMB)

// ---------------- scratch (no allocations allowed) ----------------
__device__ __half g_xfh[S_LEN * EMB];            // x fp16 hi
__device__ __half g_xfl[S_LEN * EMB];            // x fp16 lo
__device__ __half g_wf[3][WW];                   // Wq/Wk/Wv fp16
__device__ __nv_bfloat16 g_woh[WW];              // Wo bf16 hi
__device__ __nv_bfloat16 g_wol[WW];              // Wo bf16 lo
__device__ __half g_Qhf[NHEAD * S_LEN * HDIM];   // [H][S][D] fp16, pre-scaled log2e/sqrt(E)
__device__ __half g_Khf[NHEAD * S_LEN * HDIM];   // [H][S][D] fp16
__device__ __half g_Vhf[NHEAD * HDIM * S_LEN];   // [H][D][S] fp16 (transposed)
__device__ __nv_bfloat16 g_ath[S_LEN * EMB];     // attn out bf16 hi
__device__ __nv_bfloat16 g_atl[S_LEN * EMB];     // attn out bf16 lo

__device__ __forceinline__ void fsplit(float v, __nv_bfloat16& h, __nv_bfloat16& l)
{
    h = __float2bfloat16(v);
    l = __float2bfloat16(v - __bfloat162float(h));
}

__device__ __forceinline__ uint32_t smem_u32(const void* p)
{
    return (uint32_t)__cvta_generic_to_shared(p);
}

__device__ __forceinline__ void cp16(uint32_t saddr, const void* g)
{
    asm volatile("cp.async.cg.shared.global [%0], [%1], 16;" :: "r"(saddr), "l"(g));
}
#define CP_COMMIT() asm volatile("cp.async.commit_group;")
#define CP_WAIT1()  asm volatile("cp.async.wait_group 1;")
#define CP_WAIT0()  asm volatile("cp.async.wait_group 0;")

__device__ __forceinline__ void ldsm_x4(uint32_t& r0, uint32_t& r1,
                                        uint32_t& r2, uint32_t& r3, uint32_t addr)
{
    asm volatile("ldmatrix.sync.aligned.m8n8.x4.shared.b16 {%0,%1,%2,%3}, [%4];"
                 : "=r"(r0), "=r"(r1), "=r"(r2), "=r"(r3) : "r"(addr));
}

__device__ __forceinline__ void mma_bf(float* c, const uint32_t* a,
                                       uint32_t b0, uint32_t b1)
{
    asm volatile(
        "mma.sync.aligned.m16n8k16.row.col.f32.bf16.bf16.f32 "
        "{%0,%1,%2,%3},{%4,%5,%6,%7},{%8,%9},{%0,%1,%2,%3};"
        : "+f"(c[0]), "+f"(c[1]), "+f"(c[2]), "+f"(c[3])
        : "r"(a[0]), "r"(a[1]), "r"(a[2]), "r"(a[3]), "r"(b0), "r"(b1));
}

__device__ __forceinline__ void mma_f16(float* c, const uint32_t* a,
                                        uint32_t b0, uint32_t b1)
{
    asm volatile(
        "mma.sync.aligned.m16n8k16.row.col.f32.f16.f16.f32 "
        "{%0,%1,%2,%3},{%4,%5,%6,%7},{%8,%9},{%0,%1,%2,%3};"
        : "+f"(c[0]), "+f"(c[1]), "+f"(c[2]), "+f"(c[3])
        : "r"(a[0]), "r"(a[1]), "r"(a[2]), "r"(a[3]), "r"(b0), "r"(b1));
}

__device__ __forceinline__ float ex2(float x)
{
    float r;
    asm("ex2.approx.f32 %0, %1;" : "=f"(r) : "f"(x));
    return r;
}

// ---------------- x: fp32 -> fp16 hi/lo ----------------
__global__ __launch_bounds__(256) void split_x_kernel(
    const float* __restrict__ in, __half* __restrict__ hi,
    __half* __restrict__ lo, int n4)
{
    const int i = blockIdx.x * 256 + threadIdx.x;
    if (i >= n4) return;
    float4 v = ((const float4*)in)[i];
    __half2 h01 = __floats2half2_rn(v.x, v.y);
    __half2 h23 = __floats2half2_rn(v.z, v.w);
    float2 f01 = __half22float2(h01);
    float2 f23 = __half22float2(h23);
    __half2 l01 = __floats2half2_rn(v.x - f01.x, v.y - f01.y);
    __half2 l23 = __floats2half2_rn(v.z - f23.x, v.w - f23.y);
    __half2* hp = (__half2*)(hi + i * 4);
    __half2* lp = (__half2*)(lo + i * 4);
    hp[0] = h01; hp[1] = h23;
    lp[0] = l01; lp[1] = l23;
}

// weights: y<3 -> fp16 single; y==3 -> Wo bf16 hi/lo
__global__ __launch_bounds__(256) void split_w_kernel(
    const float* __restrict__ w0, const float* __restrict__ w1,
    const float* __restrict__ w2, const float* __restrict__ w3,
    __half* __restrict__ wf, __nv_bfloat16* __restrict__ woh,
    __nv_bfloat16* __restrict__ wol, int n4)
{
    const int i = blockIdx.x * 256 + threadIdx.x;
    if (i >= n4) return;
    const int y = blockIdx.y;
    const float* src = (y == 0) ? w0 : (y == 1) ? w1 : (y == 2) ? w2 : w3;
    float4 v = ((const float4*)src)[i];
    if (y < 3) {
        __half2* p = (__half2*)(wf + (size_t)y * WW + i * 4);
        p[0] = __floats2half2_rn(v.x, v.y);
        p[1] = __floats2half2_rn(v.z, v.w);
    } else {
        __nv_bfloat16 h0, h1, h2, h3, l0, l1, l2, l3;
        fsplit(v.x, h0, l0); fsplit(v.y, h1, l1);
        fsplit(v.z, h2, l2); fsplit(v.w, h3, l3);
        __nv_bfloat162* hp = (__nv_bfloat162*)(woh + i * 4);
        __nv_bfloat162* lp = (__nv_bfloat162*)(wol + i * 4);
        hp[0] = __nv_bfloat162{h0, h1}; hp[1] = __nv_bfloat162{h2, h3};
        lp[0] = __nv_bfloat162{l0, l1}; lp[1] = __nv_bfloat162{l2, l3};
    }
}

// ================= QKV GEMM: fp16 2-term (A=x hi/lo exact, B=W fp16) ====
// smem: sAh[2][128][40] @0 (10240/st), sAl @20480, sB[2][64][40] @40960 (5120/st)
#define QA_ST 10240
#define QB_ST 5120
#define Q_SMEM 51200

__global__ __launch_bounds__(128) void gemm_qkv(
    const __half* __restrict__ xh, const __half* __restrict__ xl,
    const __half* __restrict__ wf,
    const float* __restrict__ bq, const float* __restrict__ bk,
    const float* __restrict__ bv,
    __half* __restrict__ Qh, __half* __restrict__ Kh, __half* __restrict__ Vh)
{
    extern __shared__ char sm[];
    const int z = blockIdx.z;
    const int tid = threadIdx.x;
    const int wid = tid >> 5;
    const int lane = tid & 31;
    const int lq = lane >> 2;
    const int lk = lane & 3;
    const int bm = blockIdx.y * 128;
    const int bn = blockIdx.x * 64;

    const __half* W = wf + (size_t)z * WW;
    const float* bias = (z == 0) ? bq : (z == 1) ? bk : bv;
    const float qs = (z == 0) ? 1.4426950408889634f * rsqrtf((float)EMB) : 1.0f;

    float acc[2][8][4];
    #pragma unroll
    for (int mi = 0; mi < 2; mi++)
        #pragma unroll
        for (int ni = 0; ni < 8; ni++)
            #pragma unroll
            for (int i = 0; i < 4; i++) acc[mi][ni][i] = 0.f;

    const uint32_t base = smem_u32(sm);
    const int brow = tid >> 1;
    const int bcol = (tid & 1) * 16;

    auto load_stage = [&](int s, int k0) {
        const __half* ah = xh + (size_t)(bm + tid) * EMB + k0;
        const __half* al = xl + (size_t)(bm + tid) * EMB + k0;
        uint32_t dA = base + s * QA_ST + tid * 80;
        #pragma unroll
        for (int i = 0; i < 4; i++) {
            cp16(dA + i * 16, ah + i * 8);
            cp16(dA + 20480 + i * 16, al + i * 8);
        }
        const __half* bw = W + (size_t)(bn + brow) * EMB + k0 + bcol;
        uint32_t dB = base + 40960 + s * QB_ST + brow * 80 + bcol * 2;
        cp16(dB, bw); cp16(dB + 16, bw + 8);
    };

    const int rselA = lane & 15;
    const int cselA = (lane >> 4) << 3;
    const int rselB = (lane & 7) + ((lane >> 4) << 3);
    const int cselB = ((lane >> 3) & 1) << 3;
    const uint32_t bAh = base + (wid * 32 + rselA) * 80 + cselA * 2;
    const uint32_t bB  = base + 40960 + rselB * 80 + cselB * 2;

    load_stage(0, 0);
    CP_COMMIT();

    const int NIT = EMB / 32;  // 24
    #pragma unroll 1
    for (int it = 0; it < NIT; it++) {
        const int cur = it & 1;
        if (it + 1 < NIT) {
            load_stage(cur ^ 1, (it + 1) * 32);
            CP_COMMIT();
            CP_WAIT1();
        } else {
            CP_WAIT0();
        }
        __syncthreads();

        const uint32_t cAh = bAh + cur * QA_ST;
        const uint32_t cAl = cAh + 20480;
        const uint32_t cB  = bB + cur * QB_ST;

        #pragma unroll
        for (int ks = 0; ks < 32; ks += 16) {
            uint32_t fah[2][4], fal[2][4];
            #pragma unroll
            for (int mi = 0; mi < 2; mi++) {
                const uint32_t off = (uint32_t)(mi * 16 * 80 + ks * 2);
                ldsm_x4(fah[mi][0], fah[mi][1], fah[mi][2], fah[mi][3], cAh + off);
                ldsm_x4(fal[mi][0], fal[mi][1], fal[mi][2], fal[mi][3], cAl + off);
            }
            #pragma unroll
            for (int nip = 0; nip < 4; nip++) {
                const uint32_t off = (uint32_t)(nip * 16 * 80 + ks * 2);
                uint32_t h0, h1, h2, h3;
                ldsm_x4(h0, h1, h2, h3, cB + off);
                #pragma unroll
                for (int mi = 0; mi < 2; mi++) {
                    mma_f16(acc[mi][2 * nip],     fah[mi], h0, h1);
                    mma_f16(acc[mi][2 * nip],     fal[mi], h0, h1);
                    mma_f16(acc[mi][2 * nip + 1], fah[mi], h2, h3);
                    mma_f16(acc[mi][2 * nip + 1], fal[mi], h2, h3);
                }
            }
        }
        __syncthreads();
    }

    // ---- epilogue ----
    #pragma unroll
    for (int mi = 0; mi < 2; mi++) {
        const int r = bm + wid * 32 + mi * 16 + lq;
        #pragma unroll
        for (int ni = 0; ni < 8; ni++) {
            const int c = bn + ni * 8 + lk * 2;
            const float b0 = bias[c], b1 = bias[c + 1];
            float v0 = (acc[mi][ni][0] + b0) * qs;
            float v1 = (acc[mi][ni][1] + b1) * qs;
            float v2 = (acc[mi][ni][2] + b0) * qs;
            float v3 = (acc[mi][ni][3] + b1) * qs;
            const int hh = c >> 6, d = c & 63;
            const size_t i0 = ((size_t)hh * S_LEN + r) * HDIM + d;
            const size_t i1 = ((size_t)hh * S_LEN + r + 8) * HDIM + d;
            if (z == 0) {
                *(__half2*)&Qh[i0] = __floats2half2_rn(v0, v1);
                *(__half2*)&Qh[i1] = __floats2half2_rn(v2, v3);
            } else if (z == 1) {
                *(__half2*)&Kh[i0] = __floats2half2_rn(v0, v1);
                *(__half2*)&Kh[i1] = __floats2half2_rn(v2, v3);
            } else {
                Vh[(size_t)c * S_LEN + r]           = __float2half_rn(v0);
                Vh[(size_t)(c + 1) * S_LEN + r]     = __float2half_rn(v1);
                Vh[(size_t)c * S_LEN + r + 8]       = __float2half_rn(v2);
                Vh[(size_t)(c + 1) * S_LEN + r + 8] = __float2half_rn(v3);
            }
        }
    }
}

// ================= output GEMM: bf16 3-term (accuracy-critical) =========
#define GA_ST 10240
#define GB_ST 5120
#define G_SMEM 61440

__global__ __launch_bounds__(128) void gemm_out(
    const __nv_bfloat16* __restrict__ Ah, const __nv_bfloat16* __restrict__ Al,
    const __nv_bfloat16* __restrict__ Bh, const __nv_bfloat16* __restrict__ Bl,
    const float* __restrict__ bias, float* __restrict__ Cf)
{
    extern __shared__ char sm[];
    const int tid = threadIdx.x;
    const int wid = tid >> 5;
    const int lane = tid & 31;
    const int lq = lane >> 2;
    const int lk = lane & 3;
    const int bm = blockIdx.y * 128;
    const int bn = blockIdx.x * 64;

    float acc[2][8][4];
    #pragma unroll
    for (int mi = 0; mi < 2; mi++)
        #pragma unroll
        for (int ni = 0; ni < 8; ni++)
            #pragma unroll
            for (int i = 0; i < 4; i++) acc[mi][ni][i] = 0.f;

    const uint32_t base = smem_u32(sm);
    const int brow = tid >> 1;
    const int bcol = (tid & 1) * 16;

    auto load_stage = [&](int s, int k0) {
        const __nv_bfloat16* ah = Ah + (size_t)(bm + tid) * EMB + k0;
        const __nv_bfloat16* al = Al + (size_t)(bm + tid) * EMB + k0;
        uint32_t dA = base + s * GA_ST + tid * 80;
        #pragma unroll
        for (int i = 0; i < 4; i++) {
            cp16(dA + i * 16, ah + i * 8);
            cp16(dA + 20480 + i * 16, al + i * 8);
        }
        const __nv_bfloat16* bh = Bh + (size_t)(bn + brow) * EMB + k0 + bcol;
        const __nv_bfloat16* bl = Bl + (size_t)(bn + brow) * EMB + k0 + bcol;
        uint32_t dB = base + 40960 + s * GB_ST + brow * 80 + bcol * 2;
        cp16(dB, bh);          cp16(dB + 16, bh + 8);
        cp16(dB + 10240, bl);  cp16(dB + 10240 + 16, bl + 8);
    };

    const int rselA = lane & 15;
    const int cselA = (lane >> 4) << 3;
    const int rselB = (lane & 7) + ((lane >> 4) << 3);
    const int cselB = ((lane >> 3) & 1) << 3;
    const uint32_t bAh = base + (wid * 32 + rselA) * 80 + cselA * 2;
    const uint32_t bBh = base + 40960 + rselB * 80 + cselB * 2;

    load_stage(0, 0);
    CP_COMMIT();

    const int NIT = EMB / 32;
    #pragma unroll 1
    for (int it = 0; it < NIT; it++) {
        const int cur = it & 1;
        if (it + 1 < NIT) {
            load_stage(cur ^ 1, (it + 1) * 32);
            CP_COMMIT();
            CP_WAIT1();
        } else {
            CP_WAIT0();
        }
        __syncthreads();

        const uint32_t cAh = bAh + cur * GA_ST;
        const uint32_t cAl = cAh + 20480;
        const uint32_t cBh = bBh + cur * GB_ST;
        const uint32_t cBl = cBh + 10240;

        #pragma unroll
        for (int ks = 0; ks < 32; ks += 16) {
            uint32_t fah[2][4], fal[2][4];
            #pragma unroll
            for (int mi = 0; mi < 2; mi++) {
                const uint32_t off = (uint32_t)(mi * 16 * 80 + ks * 2);
                ldsm_x4(fah[mi][0], fah[mi][1], fah[mi][2], fah[mi][3], cAh + off);
                ldsm_x4(fal[mi][0], fal[mi][1], fal[mi][2], fal[mi][3], cAl + off);
            }
            #pragma unroll
            for (int nip = 0; nip < 4; nip++) {
                const uint32_t off = (uint32_t)(nip * 16 * 80 + ks * 2);
                uint32_t h0, h1, h2, h3, l0, l1, l2, l3;
                ldsm_x4(h0, h1, h2, h3, cBh + off);
                ldsm_x4(l0, l1, l2, l3, cBl + off);
                #pragma unroll
                for (int mi = 0; mi < 2; mi++) {
                    mma_bf(acc[mi][2 * nip],     fah[mi], h0, h1);
                    mma_bf(acc[mi][2 * nip],     fah[mi], l0, l1);
                    mma_bf(acc[mi][2 * nip],     fal[mi], h0, h1);
                    mma_bf(acc[mi][2 * nip + 1], fah[mi], h2, h3);
                    mma_bf(acc[mi][2 * nip + 1], fah[mi], l2, l3);
                    mma_bf(acc[mi][2 * nip + 1], fal[mi], h2, h3);
                }
            }
        }
        __syncthreads();
    }

    #pragma unroll
    for (int mi = 0; mi < 2; mi++) {
        const int r = bm + wid * 32 + mi * 16 + lq;
        #pragma unroll
        for (int ni = 0; ni < 8; ni++) {
            const int c = bn + ni * 8 + lk * 2;
            const float b0 = bias[c], b1 = bias[c + 1];
            *(float2*)&Cf[(size_t)r * EMB + c] =
                make_float2(acc[mi][ni][0] + b0, acc[mi][ni][1] + b1);
            *(float2*)&Cf[(size_t)(r + 8) * EMB + c] =
                make_float2(acc[mi][ni][2] + b0, acc[mi][ni][3] + b1);
        }
    }
}

// ========== fp16 flash attention, NO online max (tiny logits), 3-stage ===
#define AT_ST 9216
#define A_V_OFF 27648
#define A_M_OFF 55296
#define A_SMEM 56064

__global__ __launch_bounds__(128, 4) void attn_mma(
    const __half* __restrict__ Qhf, const __half* __restrict__ Khf,
    const __half* __restrict__ Vhf,
    const unsigned char* __restrict__ mask,
    __nv_bfloat16* __restrict__ Ohi, __nv_bfloat16* __restrict__ Olo)
{
    extern __shared__ char sm[];
    const int h   = blockIdx.y;
    const int q0  = blockIdx.x * 64;
    const int tid = threadIdx.x;
    const int wid = tid >> 5;
    const int lane = tid & 31;
    const int lq = lane >> 2;
    const int lk = lane & 3;

    const size_t hoff = (size_t)h * S_LEN * HDIM;

    const int qr = q0 + wid * 16 + lq;
    uint32_t aQh[4][4];
    {
        const __half* Qhp = Qhf + hoff;
        #pragma unroll
        for (int kc = 0; kc < 4; kc++) {
            const int c = kc * 16 + lk * 2;
            aQh[kc][0] = *(const uint32_t*)&Qhp[(size_t)qr * 64 + c];
            aQh[kc][1] = *(const uint32_t*)&Qhp[(size_t)(qr + 8) * 64 + c];
            aQh[kc][2] = *(const uint32_t*)&Qhp[(size_t)qr * 64 + c + 8];
            aQh[kc][3] = *(const uint32_t*)&Qhp[(size_t)(qr + 8) * 64 + c + 8];
        }
    }

    const int rsel = (lane & 7) + ((lane >> 4) << 3);
    const int csel = ((lane >> 3) & 1) << 3;
    const uint32_t base = smem_u32(sm);
    const uint32_t bK = base + (rsel * 72 + csel) * 2;
    float* smadd = (float*)(sm + A_M_OFF);

    const int trow = tid >> 1;
    const int tcol = (tid & 1) * 32;

    auto load_tile = [&](int s, int k0) {
        const __half* kh = Khf + hoff + (size_t)(k0 + trow) * 64 + tcol;
        const __half* vh = Vhf + hoff + (size_t)trow * S_LEN + k0 + tcol;
        const uint32_t d = base + s * AT_ST + (trow * 72 + tcol) * 2;
        #pragma unroll
        for (int i = 0; i < 4; i++) {
            cp16(d + i * 16,           kh + i * 8);
            cp16(d + A_V_OFF + i * 16, vh + i * 8);
        }
        if (tid < 64) smadd[s * 64 + tid] = mask[k0 + tid] ? -1e30f : 0.f;
    };

    float o[8][4];
    #pragma unroll
    for (int j = 0; j < 8; j++)
        #pragma unroll
        for (int i = 0; i < 4; i++) o[j][i] = 0.f;
    float lrow0 = 0.f, lrow1 = 0.f;   // per-thread partial; reduced at the end

    load_tile(0, 0);
    CP_COMMIT();
    load_tile(1, 64);
    CP_COMMIT();

    const int NIT = S_LEN / 64;  // 64
    int cur = 0, nxt = 2;
    #pragma unroll 1
    for (int it = 0; it < NIT; it++) {
        CP_WAIT1();
        __syncthreads();
        if (it + 2 < NIT) {
            load_tile(nxt, (it + 2) * 64);
            CP_COMMIT();
        }

        const uint32_t cK = bK + cur * AT_ST;
        const uint32_t cV = cK + A_V_OFF;
        const float* md = smadd + cur * 64;

        // ---- S = Q K^T (Q pre-scaled to base-2 domain) ----
        float s[8][4];
        #pragma unroll
        for (int j = 0; j < 8; j++)
            s[j][0] = s[j][1] = s[j][2] = s[j][3] = 0.f;

        #pragma unroll
        for (int jp = 0; jp < 4; jp++) {
            #pragma unroll
            for (int kc = 0; kc < 4; kc++) {
                const uint32_t off = (uint32_t)(jp * 2304 + kc * 32);
                uint32_t h0, h1, h2, h3;
                ldsm_x4(h0, h1, h2, h3, cK + off);
                mma_f16(s[2 * jp],     aQh[kc], h0, h1);
                mma_f16(s[2 * jp + 1], aQh[kc], h2, h3);
            }
        }

        // ---- p = 2^(s + mask), accumulate l, pack P (no max needed:
        //      |s| <~ 10 in base-2 domain; fp32 overflow needs s > 127) ----
        uint32_t ph[4][4];
        #pragma unroll
        for (int j = 0; j < 8; j++) {
            const float m0 = md[j * 8 + lk * 2];
            const float m1 = md[j * 8 + lk * 2 + 1];
            s[j][0] = ex2(s[j][0] + m0);
            s[j][1] = ex2(s[j][1] + m1);
            s[j][2] = ex2(s[j][2] + m0);
            s[j][3] = ex2(s[j][3] + m1);
            lrow0 += s[j][0] + s[j][1];
            lrow1 += s[j][2] + s[j][3];
            __half2 h01 = __floats2half2_rn(s[j][0], s[j][1]);
            __half2 h23 = __floats2half2_rn(s[j][2], s[j][3]);
            ph[j >> 1][2 * (j & 1) + 0] = *(uint32_t*)&h01;
            ph[j >> 1][2 * (j & 1) + 1] = *(uint32_t*)&h23;
        }

        // ---- O += P V ----
        #pragma unroll
        for (int jp = 0; jp < 4; jp++) {
            #pragma unroll
            for (int kc = 0; kc < 4; kc++) {
                const uint32_t off = (uint32_t)(jp * 2304 + kc * 32);
                uint32_t h0, h1, h2, h3;
                ldsm_x4(h0, h1, h2, h3, cV + off);
                mma_f16(o[2 * jp],     ph[kc], h0, h1);
                mma_f16(o[2 * jp + 1], ph[kc], h2, h3);
            }
        }

        cur = (cur == 2) ? 0 : cur + 1;
        nxt = (nxt == 2) ? 0 : nxt + 1;
    }

    // ---- one final l reduce across the lk quad ----
    lrow0 += __shfl_xor_sync(0xffffffffu, lrow0, 1);
    lrow0 += __shfl_xor_sync(0xffffffffu, lrow0, 2);
    lrow1 += __shfl_xor_sync(0xffffffffu, lrow1, 1);
    lrow1 += __shfl_xor_sync(0xffffffffu, lrow1, 2);
    const float inv0 = 1.0f / lrow0;
    const float inv1 = 1.0f / lrow1;

    #pragma unroll
    for (int j = 0; j < 8; j++) {
        const float v0 = o[j][0] * inv0, v1 = o[j][1] * inv0;
        const float v2 = o[j][2] * inv1, v3 = o[j][3] * inv1;
        const int c = h * 64 + j * 8 + lk * 2;
        const size_t i0 = (size_t)qr * EMB + c;
        const size_t i1 = (size_t)(qr + 8) * EMB + c;
        __nv_bfloat16 h0, h1, h2, h3, l0, l1, l2, l3;
        fsplit(v0, h0, l0); fsplit(v1, h1, l1);
        fsplit(v2, h2, l2); fsplit(v3, h3, l3);
        *(__nv_bfloat162*)&Ohi[i0] = __nv_bfloat162{h0, h1};
        *(__nv_bfloat162*)&Olo[i0] = __nv_bfloat162{l0, l1};
        *(__nv_bfloat162*)&Ohi[i1] = __nv_bfloat162{h2, h3};
        *(__nv_bfloat162*)&Olo[i1] = __nv_bfloat162{l2, l3};
    }
}

// ---------------- launch ----------------
extern "C" void kernel_launch(void* const* d_in, const int* in_sizes, int n_in,
                              void* d_out, int out_size)
{
    const float* x  = (const float*)d_in[0];
    const unsigned char* mask = (const unsigned char*)d_in[1];
    const float* Wq = (const float*)d_in[2];
    const float* bq = (const float*)d_in[3];
    const float* Wk = (const float*)d_in[4];
    const float* bk = (const float*)d_in[5];
    const float* Wv = (const float*)d_in[6];
    const float* bv = (const float*)d_in[7];
    const float* Wo = (const float*)d_in[8];
    const float* bo = (const float*)d_in[9];
    float* out = (float*)d_out;

    __half *xfh, *xfl, *wf, *Qh, *Kh, *Vh;
    __nv_bfloat16 *woh, *wol, *ath, *atl;
    cudaGetSymbolAddress((void**)&xfh, g_xfh);
    cudaGetSymbolAddress((void**)&xfl, g_xfl);
    cudaGetSymbolAddress((void**)&wf,  g_wf);
    cudaGetSymbolAddress((void**)&woh, g_woh);
    cudaGetSymbolAddress((void**)&wol, g_wol);
    cudaGetSymbolAddress((void**)&Qh, g_Qhf);
    cudaGetSymbolAddress((void**)&Kh, g_Khf);
    cudaGetSymbolAddress((void**)&Vh, g_Vhf);
    cudaGetSymbolAddress((void**)&ath, g_ath);
    cudaGetSymbolAddress((void**)&atl, g_atl);

    cudaFuncSetAttribute(gemm_qkv, cudaFuncAttributeMaxDynamicSharedMemorySize, Q_SMEM);
    cudaFuncSetAttribute(gemm_out, cudaFuncAttributeMaxDynamicSharedMemorySize, G_SMEM);
    cudaFuncSetAttribute(attn_mma, cudaFuncAttributeMaxDynamicSharedMemorySize, A_SMEM);

    const int nx4 = S_LEN * EMB / 4;
    const int nw4 = WW / 4;
    split_x_kernel<<<(nx4 + 255) / 256, 256>>>(x, xfh, xfl, nx4);
    dim3 wgrid((nw4 + 255) / 256, 4);
    split_w_kernel<<<wgrid, 256>>>(Wq, Wk, Wv, Wo, wf, woh, wol, nw4);

    dim3 qgrid(EMB / 64, S_LEN / 128, 3);   // (12, 32, 3)
    gemm_qkv<<<qgrid, 128, Q_SMEM>>>(xfh, xfl, wf, bq, bk, bv, Qh, Kh, Vh);

    dim3 agrid(S_LEN / 64, NHEAD);          // (64, 12)
    attn_mma<<<agrid, 128, A_SMEM>>>(Qh, Kh, Vh, mask, ath, atl);

    dim3 ogrid(EMB / 64, S_LEN / 128);      // (12, 32)
    gemm_out<<<ogrid, 128, G_SMEM>>>(ath, atl, woh, wol, bo, out);
}

// round 10
// speedup vs baseline: 6.4068x; 1.0763x over previous
#include <cuda_runtime.h>
#include <cuda_bf16.h>
#include <cuda_fp16.h>
#include <cstdint>

#define S_LEN 4096
#define EMB   768
#define NHEAD 12
#define HDIM  64
#define WW    (EMB * EMB)

// ---------------- scratch (no allocations allowed) ----------------
__device__ __half g_xfh[S_LEN * EMB];            // x fp16 hi
__device__ __half g_xfl[S_LEN * EMB];            // x fp16 lo
__device__ __half g_wf[4][WW];                   // Wq/Wk/Wv/Wo fp16
__device__ __half g_Qhf[NHEAD * S_LEN * HDIM];   // [H][S][D] fp16, pre-scaled log2e/sqrt(E)
__device__ __half g_Khf[NHEAD * S_LEN * HDIM];   // [H][S][D] fp16
__device__ __half g_Vhf[NHEAD * HDIM * S_LEN];   // [H][D][S] fp16 (transposed)
__device__ __half g_ath[S_LEN * EMB];            // attn out fp16 hi
__device__ __half g_atl[S_LEN * EMB];            // attn out fp16 lo

__device__ __forceinline__ uint32_t smem_u32(const void* p)
{
    return (uint32_t)__cvta_generic_to_shared(p);
}

__device__ __forceinline__ void cp16(uint32_t saddr, const void* g)
{
    asm volatile("cp.async.cg.shared.global [%0], [%1], 16;" :: "r"(saddr), "l"(g));
}
#define CP_COMMIT() asm volatile("cp.async.commit_group;")
#define CP_WAIT1()  asm volatile("cp.async.wait_group 1;")
#define CP_WAIT0()  asm volatile("cp.async.wait_group 0;")

__device__ __forceinline__ void ldsm_x4(uint32_t& r0, uint32_t& r1,
                                        uint32_t& r2, uint32_t& r3, uint32_t addr)
{
    asm volatile("ldmatrix.sync.aligned.m8n8.x4.shared.b16 {%0,%1,%2,%3}, [%4];"
                 : "=r"(r0), "=r"(r1), "=r"(r2), "=r"(r3) : "r"(addr));
}

__device__ __forceinline__ void mma_f16(float* c, const uint32_t* a,
                                        uint32_t b0, uint32_t b1)
{
    asm volatile(
        "mma.sync.aligned.m16n8k16.row.col.f32.f16.f16.f32 "
        "{%0,%1,%2,%3},{%4,%5,%6,%7},{%8,%9},{%0,%1,%2,%3};"
        : "+f"(c[0]), "+f"(c[1]), "+f"(c[2]), "+f"(c[3])
        : "r"(a[0]), "r"(a[1]), "r"(a[2]), "r"(a[3]), "r"(b0), "r"(b1));
}

__device__ __forceinline__ float ex2(float x)
{
    float r;
    asm("ex2.approx.f32 %0, %1;" : "=f"(r) : "f"(x));
    return r;
}

// ---------------- x: fp32 -> fp16 hi/lo ----------------
__global__ __launch_bounds__(256) void split_x_kernel(
    const float* __restrict__ in, __half* __restrict__ hi,
    __half* __restrict__ lo, int n4)
{
    const int i = blockIdx.x * 256 + threadIdx.x;
    if (i >= n4) return;
    float4 v = ((const float4*)in)[i];
    __half2 h01 = __floats2half2_rn(v.x, v.y);
    __half2 h23 = __floats2half2_rn(v.z, v.w);
    float2 f01 = __half22float2(h01);
    float2 f23 = __half22float2(h23);
    __half2* hp = (__half2*)(hi + i * 4);
    __half2* lp = (__half2*)(lo + i * 4);
    hp[0] = h01; hp[1] = h23;
    lp[0] = __floats2half2_rn(v.x - f01.x, v.y - f01.y);
    lp[1] = __floats2half2_rn(v.z - f23.x, v.w - f23.y);
}

// all 4 weights -> fp16 (y selects matrix)
__global__ __launch_bounds__(256) void split_w_kernel(
    const float* __restrict__ w0, const float* __restrict__ w1,
    const float* __restrict__ w2, const float* __restrict__ w3,
    __half* __restrict__ wf, int n4)
{
    const int i = blockIdx.x * 256 + threadIdx.x;
    if (i >= n4) return;
    const int y = blockIdx.y;
    const float* src = (y == 0) ? w0 : (y == 1) ? w1 : (y == 2) ? w2 : w3;
    float4 v = ((const float4*)src)[i];
    __half2* p = (__half2*)(wf + (size_t)y * WW + i * 4);
    p[0] = __floats2half2_rn(v.x, v.y);
    p[1] = __floats2half2_rn(v.z, v.w);
}

// ================= fp16 2-term GEMM core (A hi/lo exact, B fp16) =========
// smem: sAh[2][128][40] @0 (10240/st), sAl @20480, sB[2][64][40] @40960 (5120/st)
#define QA_ST 10240
#define QB_ST 5120
#define Q_SMEM 51200

struct GemmAcc { float a[2][8][4]; };

__device__ __forceinline__ void gemm_f16_mainloop(
    char* sm,
    const __half* __restrict__ Ah, const __half* __restrict__ Al,
    const __half* __restrict__ W,
    int bm, int bn, int tid, int wid, int lane, GemmAcc& G)
{
    #pragma unroll
    for (int mi = 0; mi < 2; mi++)
        #pragma unroll
        for (int ni = 0; ni < 8; ni++)
            #pragma unroll
            for (int i = 0; i < 4; i++) G.a[mi][ni][i] = 0.f;

    const uint32_t base = smem_u32(sm);
    const int brow = tid >> 1;
    const int bcol = (tid & 1) * 16;

    auto load_stage = [&](int s, int k0) {
        const __half* ah = Ah + (size_t)(bm + tid) * EMB + k0;
        const __half* al = Al + (size_t)(bm + tid) * EMB + k0;
        uint32_t dA = base + s * QA_ST + tid * 80;
        #pragma unroll
        for (int i = 0; i < 4; i++) {
            cp16(dA + i * 16, ah + i * 8);
            cp16(dA + 20480 + i * 16, al + i * 8);
        }
        const __half* bw = W + (size_t)(bn + brow) * EMB + k0 + bcol;
        uint32_t dB = base + 40960 + s * QB_ST + brow * 80 + bcol * 2;
        cp16(dB, bw); cp16(dB + 16, bw + 8);
    };

    const int rselA = lane & 15;
    const int cselA = (lane >> 4) << 3;
    const int rselB = (lane & 7) + ((lane >> 4) << 3);
    const int cselB = ((lane >> 3) & 1) << 3;
    const uint32_t bAh = base + (wid * 32 + rselA) * 80 + cselA * 2;
    const uint32_t bB  = base + 40960 + rselB * 80 + cselB * 2;

    load_stage(0, 0);
    CP_COMMIT();

    const int NIT = EMB / 32;  // 24
    #pragma unroll 1
    for (int it = 0; it < NIT; it++) {
        const int cur = it & 1;
        if (it + 1 < NIT) {
            load_stage(cur ^ 1, (it + 1) * 32);
            CP_COMMIT();
            CP_WAIT1();
        } else {
            CP_WAIT0();
        }
        __syncthreads();

        const uint32_t cAh = bAh + cur * QA_ST;
        const uint32_t cAl = cAh + 20480;
        const uint32_t cB  = bB + cur * QB_ST;

        #pragma unroll
        for (int ks = 0; ks < 32; ks += 16) {
            uint32_t fah[2][4], fal[2][4];
            #pragma unroll
            for (int mi = 0; mi < 2; mi++) {
                const uint32_t off = (uint32_t)(mi * 16 * 80 + ks * 2);
                ldsm_x4(fah[mi][0], fah[mi][1], fah[mi][2], fah[mi][3], cAh + off);
                ldsm_x4(fal[mi][0], fal[mi][1], fal[mi][2], fal[mi][3], cAl + off);
            }
            #pragma unroll
            for (int nip = 0; nip < 4; nip++) {
                const uint32_t off = (uint32_t)(nip * 16 * 80 + ks * 2);
                uint32_t h0, h1, h2, h3;
                ldsm_x4(h0, h1, h2, h3, cB + off);
                #pragma unroll
                for (int mi = 0; mi < 2; mi++) {
                    mma_f16(G.a[mi][2 * nip],     fah[mi], h0, h1);
                    mma_f16(G.a[mi][2 * nip],     fal[mi], h0, h1);
                    mma_f16(G.a[mi][2 * nip + 1], fah[mi], h2, h3);
                    mma_f16(G.a[mi][2 * nip + 1], fal[mi], h2, h3);
                }
            }
        }
        __syncthreads();
    }
}

// QKV projection: grid (12, 32, 3); z: 0=Q (fp16, pre-scaled), 1=K, 2=V (T)
__global__ __launch_bounds__(128) void gemm_qkv(
    const __half* __restrict__ xh, const __half* __restrict__ xl,
    const __half* __restrict__ wf,
    const float* __restrict__ bq, const float* __restrict__ bk,
    const float* __restrict__ bv,
    __half* __restrict__ Qh, __half* __restrict__ Kh, __half* __restrict__ Vh)
{
    extern __shared__ char sm[];
    const int z = blockIdx.z;
    const int tid = threadIdx.x;
    const int wid = tid >> 5;
    const int lane = tid & 31;
    const int lq = lane >> 2;
    const int lk = lane & 3;
    const int bm = blockIdx.y * 128;
    const int bn = blockIdx.x * 64;

    const __half* W = wf + (size_t)z * WW;
    const float* bias = (z == 0) ? bq : (z == 1) ? bk : bv;
    const float qs = (z == 0) ? 1.4426950408889634f * rsqrtf((float)EMB) : 1.0f;

    GemmAcc G;
    gemm_f16_mainloop(sm, xh, xl, W, bm, bn, tid, wid, lane, G);

    #pragma unroll
    for (int mi = 0; mi < 2; mi++) {
        const int r = bm + wid * 32 + mi * 16 + lq;
        #pragma unroll
        for (int ni = 0; ni < 8; ni++) {
            const int c = bn + ni * 8 + lk * 2;
            const float b0 = bias[c], b1 = bias[c + 1];
            float v0 = (G.a[mi][ni][0] + b0) * qs;
            float v1 = (G.a[mi][ni][1] + b1) * qs;
            float v2 = (G.a[mi][ni][2] + b0) * qs;
            float v3 = (G.a[mi][ni][3] + b1) * qs;
            const int hh = c >> 6, d = c & 63;
            const size_t i0 = ((size_t)hh * S_LEN + r) * HDIM + d;
            const size_t i1 = ((size_t)hh * S_LEN + r + 8) * HDIM + d;
            if (z == 0) {
                *(__half2*)&Qh[i0] = __floats2half2_rn(v0, v1);
                *(__half2*)&Qh[i1] = __floats2half2_rn(v2, v3);
            } else if (z == 1) {
                *(__half2*)&Kh[i0] = __floats2half2_rn(v0, v1);
                *(__half2*)&Kh[i1] = __floats2half2_rn(v2, v3);
            } else {
                Vh[(size_t)c * S_LEN + r]           = __float2half_rn(v0);
                Vh[(size_t)(c + 1) * S_LEN + r]     = __float2half_rn(v1);
                Vh[(size_t)c * S_LEN + r + 8]       = __float2half_rn(v2);
                Vh[(size_t)(c + 1) * S_LEN + r + 8] = __float2half_rn(v3);
            }
        }
    }
}

// Output projection: fp16 2-term, fp32 result
__global__ __launch_bounds__(128) void gemm_out(
    const __half* __restrict__ Ah, const __half* __restrict__ Al,
    const __half* __restrict__ W,
    const float* __restrict__ bias, float* __restrict__ Cf)
{
    extern __shared__ char sm[];
    const int tid = threadIdx.x;
    const int wid = tid >> 5;
    const int lane = tid & 31;
    const int lq = lane >> 2;
    const int lk = lane & 3;
    const int bm = blockIdx.y * 128;
    const int bn = blockIdx.x * 64;

    GemmAcc G;
    gemm_f16_mainloop(sm, Ah, Al, W, bm, bn, tid, wid, lane, G);

    #pragma unroll
    for (int mi = 0; mi < 2; mi++) {
        const int r = bm + wid * 32 + mi * 16 + lq;
        #pragma unroll
        for (int ni = 0; ni < 8; ni++) {
            const int c = bn + ni * 8 + lk * 2;
            const float b0 = bias[c], b1 = bias[c + 1];
            *(float2*)&Cf[(size_t)r * EMB + c] =
                make_float2(G.a[mi][ni][0] + b0, G.a[mi][ni][1] + b1);
            *(float2*)&Cf[(size_t)(r + 8) * EMB + c] =
                make_float2(G.a[mi][ni][2] + b0, G.a[mi][ni][3] + b1);
        }
    }
}

// ===== fp16 flash attention, no online max, 2 m-tiles/warp, 3-stage ======
// smem: K[3][64][72] @0 (9216/st), V[3][64][72] @27648, mask[3][64] f32 @55296
#define AT_ST 9216
#define A_V_OFF 27648
#define A_M_OFF 55296
#define A_SMEM 56064

__global__ __launch_bounds__(128) void attn_mma(
    const __half* __restrict__ Qhf, const __half* __restrict__ Khf,
    const __half* __restrict__ Vhf,
    const unsigned char* __restrict__ mask,
    __half* __restrict__ Ohi, __half* __restrict__ Olo)
{
    extern __shared__ char sm[];
    const int h   = blockIdx.y;
    const int q0  = blockIdx.x * 128;       // 128 queries per block
    const int tid = threadIdx.x;
    const int wid = tid >> 5;
    const int lane = tid & 31;
    const int lq = lane >> 2;
    const int lk = lane & 3;

    const size_t hoff = (size_t)h * S_LEN * HDIM;

    // warp owns queries [q0 + wid*32, +32): two 16-row m-tiles
    const int qr = q0 + wid * 32 + lq;      // m-tile 0 row; m-tile 1 = qr+16
    uint32_t aQ[2][4][4];
    {
        const __half* Qhp = Qhf + hoff;
        #pragma unroll
        for (int mi = 0; mi < 2; mi++) {
            #pragma unroll
            for (int kc = 0; kc < 4; kc++) {
                const int c = kc * 16 + lk * 2;
                const size_t r0 = (size_t)(qr + mi * 16) * 64;
                const size_t r8 = (size_t)(qr + mi * 16 + 8) * 64;
                aQ[mi][kc][0] = *(const uint32_t*)&Qhp[r0 + c];
                aQ[mi][kc][1] = *(const uint32_t*)&Qhp[r8 + c];
                aQ[mi][kc][2] = *(const uint32_t*)&Qhp[r0 + c + 8];
                aQ[mi][kc][3] = *(const uint32_t*)&Qhp[r8 + c + 8];
            }
        }
    }

    const int rsel = (lane & 7) + ((lane >> 4) << 3);
    const int csel = ((lane >> 3) & 1) << 3;
    const uint32_t base = smem_u32(sm);
    const uint32_t bK = base + (rsel * 72 + csel) * 2;
    float* smadd = (float*)(sm + A_M_OFF);

    const int trow = tid >> 1;
    const int tcol = (tid & 1) * 32;

    auto load_tile = [&](int s, int k0) {
        const __half* kh = Khf + hoff + (size_t)(k0 + trow) * 64 + tcol;
        const __half* vh = Vhf + hoff + (size_t)trow * S_LEN + k0 + tcol;
        const uint32_t d = base + s * AT_ST + (trow * 72 + tcol) * 2;
        #pragma unroll
        for (int i = 0; i < 4; i++) {
            cp16(d + i * 16,           kh + i * 8);
            cp16(d + A_V_OFF + i * 16, vh + i * 8);
        }
        if (tid < 64) smadd[s * 64 + tid] = mask[k0 + tid] ? -1e30f : 0.f;
    };

    float o[2][8][4];
    #pragma unroll
    for (int mi = 0; mi < 2; mi++)
        #pragma unroll
        for (int j = 0; j < 8; j++)
            #pragma unroll
            for (int i = 0; i < 4; i++) o[mi][j][i] = 0.f;
    float lsum[2][2] = {{0.f, 0.f}, {0.f, 0.f}};   // [m-tile][row half]

    load_tile(0, 0);
    CP_COMMIT();
    load_tile(1, 64);
    CP_COMMIT();

    const int NIT = S_LEN / 64;  // 64
    int cur = 0, nxt = 2;
    #pragma unroll 1
    for (int it = 0; it < NIT; it++) {
        CP_WAIT1();
        __syncthreads();
        if (it + 2 < NIT) {
            load_tile(nxt, (it + 2) * 64);
            CP_COMMIT();
        }

        const uint32_t cK = bK + cur * AT_ST;
        const uint32_t cV = cK + A_V_OFF;
        const float* md = smadd + cur * 64;

        // ---- S = Q K^T: one K ldsm feeds 4 MMAs (2 m-tiles x 2 j) ----
        float s[2][8][4];
        #pragma unroll
        for (int mi = 0; mi < 2; mi++)
            #pragma unroll
            for (int j = 0; j < 8; j++)
                s[mi][j][0] = s[mi][j][1] = s[mi][j][2] = s[mi][j][3] = 0.f;

        #pragma unroll
        for (int jp = 0; jp < 4; jp++) {
            #pragma unroll
            for (int kc = 0; kc < 4; kc++) {
                const uint32_t off = (uint32_t)(jp * 2304 + kc * 32);
                uint32_t h0, h1, h2, h3;
                ldsm_x4(h0, h1, h2, h3, cK + off);
                mma_f16(s[0][2 * jp],     aQ[0][kc], h0, h1);
                mma_f16(s[0][2 * jp + 1], aQ[0][kc], h2, h3);
                mma_f16(s[1][2 * jp],     aQ[1][kc], h0, h1);
                mma_f16(s[1][2 * jp + 1], aQ[1][kc], h2, h3);
            }
        }

        // ---- p = 2^(s + mask), accumulate l, pack P fp16 ----
        uint32_t ph[2][4][4];
        #pragma unroll
        for (int mi = 0; mi < 2; mi++) {
            #pragma unroll
            for (int j = 0; j < 8; j++) {
                const float m0 = md[j * 8 + lk * 2];
                const float m1 = md[j * 8 + lk * 2 + 1];
                float p0 = ex2(s[mi][j][0] + m0);
                float p1 = ex2(s[mi][j][1] + m1);
                float p2 = ex2(s[mi][j][2] + m0);
                float p3 = ex2(s[mi][j][3] + m1);
                lsum[mi][0] += p0 + p1;
                lsum[mi][1] += p2 + p3;
                __half2 h01 = __floats2half2_rn(p0, p1);
                __half2 h23 = __floats2half2_rn(p2, p3);
                ph[mi][j >> 1][2 * (j & 1) + 0] = *(uint32_t*)&h01;
                ph[mi][j >> 1][2 * (j & 1) + 1] = *(uint32_t*)&h23;
            }
        }

        // ---- O += P V: one V ldsm feeds 4 MMAs ----
        #pragma unroll
        for (int jp = 0; jp < 4; jp++) {
            #pragma unroll
            for (int kc = 0; kc < 4; kc++) {
                const uint32_t off = (uint32_t)(jp * 2304 + kc * 32);
                uint32_t h0, h1, h2, h3;
                ldsm_x4(h0, h1, h2, h3, cV + off);
                mma_f16(o[0][2 * jp],     ph[0][kc], h0, h1);
                mma_f16(o[0][2 * jp + 1], ph[0][kc], h2, h3);
                mma_f16(o[1][2 * jp],     ph[1][kc], h0, h1);
                mma_f16(o[1][2 * jp + 1], ph[1][kc], h2, h3);
            }
        }

        cur = (cur == 2) ? 0 : cur + 1;
        nxt = (nxt == 2) ? 0 : nxt + 1;
    }

    // ---- final l reduce (quad) + epilogue: fp16 hi/lo output ----
    #pragma unroll
    for (int mi = 0; mi < 2; mi++) {
        lsum[mi][0] += __shfl_xor_sync(0xffffffffu, lsum[mi][0], 1);
        lsum[mi][0] += __shfl_xor_sync(0xffffffffu, lsum[mi][0], 2);
        lsum[mi][1] += __shfl_xor_sync(0xffffffffu, lsum[mi][1], 1);
        lsum[mi][1] += __shfl_xor_sync(0xffffffffu, lsum[mi][1], 2);
        const float inv0 = 1.0f / lsum[mi][0];
        const float inv1 = 1.0f / lsum[mi][1];
        const int r = qr + mi * 16;
        #pragma unroll
        for (int j = 0; j < 8; j++) {
            const float v0 = o[mi][j][0] * inv0, v1 = o[mi][j][1] * inv0;
            const float v2 = o[mi][j][2] * inv1, v3 = o[mi][j][3] * inv1;
            const int c = h * 64 + j * 8 + lk * 2;
            const size_t i0 = (size_t)r * EMB + c;
            const size_t i1 = (size_t)(r + 8) * EMB + c;
            __half2 h01 = __floats2half2_rn(v0, v1);
            __half2 h23 = __floats2half2_rn(v2, v3);
            float2 f01 = __half22float2(h01);
            float2 f23 = __half22float2(h23);
            *(__half2*)&Ohi[i0] = h01;
            *(__half2*)&Ohi[i1] = h23;
            *(__half2*)&Olo[i0] = __floats2half2_rn(v0 - f01.x, v1 - f01.y);
            *(__half2*)&Olo[i1] = __floats2half2_rn(v2 - f23.x, v3 - f23.y);
        }
    }
}

// ---------------- launch ----------------
extern "C" void kernel_launch(void* const* d_in, const int* in_sizes, int n_in,
                              void* d_out, int out_size)
{
    const float* x  = (const float*)d_in[0];
    const unsigned char* mask = (const unsigned char*)d_in[1];
    const float* Wq = (const float*)d_in[2];
    const float* bq = (const float*)d_in[3];
    const float* Wk = (const float*)d_in[4];
    const float* bk = (const float*)d_in[5];
    const float* Wv = (const float*)d_in[6];
    const float* bv = (const float*)d_in[7];
    const float* Wo = (const float*)d_in[8];
    const float* bo = (const float*)d_in[9];
    float* out = (float*)d_out;

    __half *xfh, *xfl, *wf, *Qh, *Kh, *Vh, *ath, *atl;
    cudaGetSymbolAddress((void**)&xfh, g_xfh);
    cudaGetSymbolAddress((void**)&xfl, g_xfl);
    cudaGetSymbolAddress((void**)&wf,  g_wf);
    cudaGetSymbolAddress((void**)&Qh, g_Qhf);
    cudaGetSymbolAddress((void**)&Kh, g_Khf);
    cudaGetSymbolAddress((void**)&Vh, g_Vhf);
    cudaGetSymbolAddress((void**)&ath, g_ath);
    cudaGetSymbolAddress((void**)&atl, g_atl);

    cudaFuncSetAttribute(gemm_qkv, cudaFuncAttributeMaxDynamicSharedMemorySize, Q_SMEM);
    cudaFuncSetAttribute(gemm_out, cudaFuncAttributeMaxDynamicSharedMemorySize, Q_SMEM);
    cudaFuncSetAttribute(attn_mma, cudaFuncAttributeMaxDynamicSharedMemorySize, A_SMEM);

    const int nx4 = S_LEN * EMB / 4;
    const int nw4 = WW / 4;
    split_x_kernel<<<(nx4 + 255) / 256, 256>>>(x, xfh, xfl, nx4);
    dim3 wgrid((nw4 + 255) / 256, 4);
    split_w_kernel<<<wgrid, 256>>>(Wq, Wk, Wv, Wo, wf, nw4);

    dim3 qgrid(EMB / 64, S_LEN / 128, 3);   // (12, 32, 3)
    gemm_qkv<<<qgrid, 128, Q_SMEM>>>(xfh, xfl, wf, bq, bk, bv, Qh, Kh, Vh);

    dim3 agrid(S_LEN / 128, NHEAD);         // (32, 12)
    attn_mma<<<agrid, 128, A_SMEM>>>(Qh, Kh, Vh, mask, ath, atl);

    dim3 ogrid(EMB / 64, S_LEN / 128);      // (12, 32)
    gemm_out<<<ogrid, 128, Q_SMEM>>>(ath, atl, wf + 3 * WW, bo, out);
}

// round 11
// speedup vs baseline: 6.7770x; 1.0578x over previous
#include <cuda_runtime.h>
#include <cuda_bf16.h>
#include <cuda_fp16.h>
#include <cstdint>

#define S_LEN 4096
#define EMB   768
#define NHEAD 12
#define HDIM  64
#define WW    (EMB * EMB)
#define NSPLIT 3

// ---------------- scratch (no allocations allowed) ----------------
__device__ __half g_xfh[S_LEN * EMB];            // x fp16 hi
__device__ __half g_xfl[S_LEN * EMB];            // x fp16 lo
__device__ __half g_wf[4][WW];                   // Wq/Wk/Wv/Wo fp16
__device__ __half g_Qhf[NHEAD * S_LEN * HDIM];   // [H][S][D] fp16, pre-scaled log2e/sqrt(E)
__device__ __half g_Khf[NHEAD * S_LEN * HDIM];   // [H][S][D] fp16
__device__ __half g_Vhf[NHEAD * HDIM * S_LEN];   // [H][D][S] fp16 (transposed)
__device__ float  g_opart[NSPLIT * S_LEN * EMB]; // unnormalized O partials (fp32)
__device__ float  g_lpart[NSPLIT * NHEAD * S_LEN];
__device__ __half g_ath[S_LEN * EMB];            // attn out fp16 hi
__device__ __half g_atl[S_LEN * EMB];            // attn out fp16 lo

__device__ __forceinline__ uint32_t smem_u32(const void* p)
{
    return (uint32_t)__cvta_generic_to_shared(p);
}

__device__ __forceinline__ void cp16(uint32_t saddr, const void* g)
{
    asm volatile("cp.async.cg.shared.global [%0], [%1], 16;" :: "r"(saddr), "l"(g));
}
#define CP_COMMIT() asm volatile("cp.async.commit_group;")
#define CP_WAIT1()  asm volatile("cp.async.wait_group 1;")
#define CP_WAIT0()  asm volatile("cp.async.wait_group 0;")

__device__ __forceinline__ void ldsm_x4(uint32_t& r0, uint32_t& r1,
                                        uint32_t& r2, uint32_t& r3, uint32_t addr)
{
    asm volatile("ldmatrix.sync.aligned.m8n8.x4.shared.b16 {%0,%1,%2,%3}, [%4];"
                 : "=r"(r0), "=r"(r1), "=r"(r2), "=r"(r3) : "r"(addr));
}

__device__ __forceinline__ void mma_f16(float* c, const uint32_t* a,
                                        uint32_t b0, uint32_t b1)
{
    asm volatile(
        "mma.sync.aligned.m16n8k16.row.col.f32.f16.f16.f32 "
        "{%0,%1,%2,%3},{%4,%5,%6,%7},{%8,%9},{%0,%1,%2,%3};"
        : "+f"(c[0]), "+f"(c[1]), "+f"(c[2]), "+f"(c[3])
        : "r"(a[0]), "r"(a[1]), "r"(a[2]), "r"(a[3]), "r"(b0), "r"(b1));
}

__device__ __forceinline__ uint32_t ex2_h2(uint32_t x)
{
    uint32_t r;
    asm("ex2.approx.f16x2 %0, %1;" : "=r"(r) : "r"(x));
    return r;
}

__device__ __forceinline__ uint32_t hadd2u(uint32_t a, uint32_t b)
{
    __half2 r = __hadd2(*(__half2*)&a, *(__half2*)&b);
    return *(uint32_t*)&r;
}

// ---------------- x: fp32 -> fp16 hi/lo ----------------
__global__ __launch_bounds__(256) void split_x_kernel(
    const float* __restrict__ in, __half* __restrict__ hi,
    __half* __restrict__ lo, int n4)
{
    const int i = blockIdx.x * 256 + threadIdx.x;
    if (i >= n4) return;
    float4 v = ((const float4*)in)[i];
    __half2 h01 = __floats2half2_rn(v.x, v.y);
    __half2 h23 = __floats2half2_rn(v.z, v.w);
    float2 f01 = __half22float2(h01);
    float2 f23 = __half22float2(h23);
    __half2* hp = (__half2*)(hi + i * 4);
    __half2* lp = (__half2*)(lo + i * 4);
    hp[0] = h01; hp[1] = h23;
    lp[0] = __floats2half2_rn(v.x - f01.x, v.y - f01.y);
    lp[1] = __floats2half2_rn(v.z - f23.x, v.w - f23.y);
}

// all 4 weights -> fp16 (y selects matrix)
__global__ __launch_bounds__(256) void split_w_kernel(
    const float* __restrict__ w0, const float* __restrict__ w1,
    const float* __restrict__ w2, const float* __restrict__ w3,
    __half* __restrict__ wf, int n4)
{
    const int i = blockIdx.x * 256 + threadIdx.x;
    if (i >= n4) return;
    const int y = blockIdx.y;
    const float* src = (y == 0) ? w0 : (y == 1) ? w1 : (y == 2) ? w2 : w3;
    float4 v = ((const float4*)src)[i];
    __half2* p = (__half2*)(wf + (size_t)y * WW + i * 4);
    p[0] = __floats2half2_rn(v.x, v.y);
    p[1] = __floats2half2_rn(v.z, v.w);
}

// ================= fp16 2-term GEMM core (A hi/lo exact, B fp16) =========
#define QA_ST 10240
#define QB_ST 5120
#define Q_SMEM 51200

struct GemmAcc { float a[2][8][4]; };

__device__ __forceinline__ void gemm_f16_mainloop(
    char* sm,
    const __half* __restrict__ Ah, const __half* __restrict__ Al,
    const __half* __restrict__ W,
    int bm, int bn, int tid, int wid, int lane, GemmAcc& G)
{
    #pragma unroll
    for (int mi = 0; mi < 2; mi++)
        #pragma unroll
        for (int ni = 0; ni < 8; ni++)
            #pragma unroll
            for (int i = 0; i < 4; i++) G.a[mi][ni][i] = 0.f;

    const uint32_t base = smem_u32(sm);
    const int brow = tid >> 1;
    const int bcol = (tid & 1) * 16;

    auto load_stage = [&](int s, int k0) {
        const __half* ah = Ah + (size_t)(bm + tid) * EMB + k0;
        const __half* al = Al + (size_t)(bm + tid) * EMB + k0;
        uint32_t dA = base + s * QA_ST + tid * 80;
        #pragma unroll
        for (int i = 0; i < 4; i++) {
            cp16(dA + i * 16, ah + i * 8);
            cp16(dA + 20480 + i * 16, al + i * 8);
        }
        const __half* bw = W + (size_t)(bn + brow) * EMB + k0 + bcol;
        uint32_t dB = base + 40960 + s * QB_ST + brow * 80 + bcol * 2;
        cp16(dB, bw); cp16(dB + 16, bw + 8);
    };

    const int rselA = lane & 15;
    const int cselA = (lane >> 4) << 3;
    const int rselB = (lane & 7) + ((lane >> 4) << 3);
    const int cselB = ((lane >> 3) & 1) << 3;
    const uint32_t bAh = base + (wid * 32 + rselA) * 80 + cselA * 2;
    const uint32_t bB  = base + 40960 + rselB * 80 + cselB * 2;

    load_stage(0, 0);
    CP_COMMIT();

    const int NIT = EMB / 32;  // 24
    #pragma unroll 1
    for (int it = 0; it < NIT; it++) {
        const int cur = it & 1;
        if (it + 1 < NIT) {
            load_stage(cur ^ 1, (it + 1) * 32);
            CP_COMMIT();
            CP_WAIT1();
        } else {
            CP_WAIT0();
        }
        __syncthreads();

        const uint32_t cAh = bAh + cur * QA_ST;
        const uint32_t cAl = cAh + 20480;
        const uint32_t cB  = bB + cur * QB_ST;

        #pragma unroll
        for (int ks = 0; ks < 32; ks += 16) {
            uint32_t fah[2][4], fal[2][4];
            #pragma unroll
            for (int mi = 0; mi < 2; mi++) {
                const uint32_t off = (uint32_t)(mi * 16 * 80 + ks * 2);
                ldsm_x4(fah[mi][0], fah[mi][1], fah[mi][2], fah[mi][3], cAh + off);
                ldsm_x4(fal[mi][0], fal[mi][1], fal[mi][2], fal[mi][3], cAl + off);
            }
            #pragma unroll
            for (int nip = 0; nip < 4; nip++) {
                const uint32_t off = (uint32_t)(nip * 16 * 80 + ks * 2);
                uint32_t h0, h1, h2, h3;
                ldsm_x4(h0, h1, h2, h3, cB + off);
                #pragma unroll
                for (int mi = 0; mi < 2; mi++) {
                    mma_f16(G.a[mi][2 * nip],     fah[mi], h0, h1);
                    mma_f16(G.a[mi][2 * nip],     fal[mi], h0, h1);
                    mma_f16(G.a[mi][2 * nip + 1], fah[mi], h2, h3);
                    mma_f16(G.a[mi][2 * nip + 1], fal[mi], h2, h3);
                }
            }
        }
        __syncthreads();
    }
}

// QKV projection: grid (12, 32, 3); z: 0=Q (fp16, pre-scaled), 1=K, 2=V (T)
__global__ __launch_bounds__(128) void gemm_qkv(
    const __half* __restrict__ xh, const __half* __restrict__ xl,
    const __half* __restrict__ wf,
    const float* __restrict__ bq, const float* __restrict__ bk,
    const float* __restrict__ bv,
    __half* __restrict__ Qh, __half* __restrict__ Kh, __half* __restrict__ Vh)
{
    extern __shared__ char sm[];
    const int z = blockIdx.z;
    const int tid = threadIdx.x;
    const int wid = tid >> 5;
    const int lane = tid & 31;
    const int lq = lane >> 2;
    const int lk = lane & 3;
    const int bm = blockIdx.y * 128;
    const int bn = blockIdx.x * 64;

    const __half* W = wf + (size_t)z * WW;
    const float* bias = (z == 0) ? bq : (z == 1) ? bk : bv;
    const float qs = (z == 0) ? 1.4426950408889634f * rsqrtf((float)EMB) : 1.0f;

    GemmAcc G;
    gemm_f16_mainloop(sm, xh, xl, W, bm, bn, tid, wid, lane, G);

    #pragma unroll
    for (int mi = 0; mi < 2; mi++) {
        const int r = bm + wid * 32 + mi * 16 + lq;
        #pragma unroll
        for (int ni = 0; ni < 8; ni++) {
            const int c = bn + ni * 8 + lk * 2;
            const float b0 = bias[c], b1 = bias[c + 1];
            float v0 = (G.a[mi][ni][0] + b0) * qs;
            float v1 = (G.a[mi][ni][1] + b1) * qs;
            float v2 = (G.a[mi][ni][2] + b0) * qs;
            float v3 = (G.a[mi][ni][3] + b1) * qs;
            const int hh = c >> 6, d = c & 63;
            const size_t i0 = ((size_t)hh * S_LEN + r) * HDIM + d;
            const size_t i1 = ((size_t)hh * S_LEN + r + 8) * HDIM + d;
            if (z == 0) {
                *(__half2*)&Qh[i0] = __floats2half2_rn(v0, v1);
                *(__half2*)&Qh[i1] = __floats2half2_rn(v2, v3);
            } else if (z == 1) {
                *(__half2*)&Kh[i0] = __floats2half2_rn(v0, v1);
                *(__half2*)&Kh[i1] = __floats2half2_rn(v2, v3);
            } else {
                Vh[(size_t)c * S_LEN + r]           = __float2half_rn(v0);
                Vh[(size_t)(c + 1) * S_LEN + r]     = __float2half_rn(v1);
                Vh[(size_t)c * S_LEN + r + 8]       = __float2half_rn(v2);
                Vh[(size_t)(c + 1) * S_LEN + r + 8] = __float2half_rn(v3);
            }
        }
    }
}

// Output projection: fp16 2-term, fp32 result
__global__ __launch_bounds__(128) void gemm_out(
    const __half* __restrict__ Ah, const __half* __restrict__ Al,
    const __half* __restrict__ W,
    const float* __restrict__ bias, float* __restrict__ Cf)
{
    extern __shared__ char sm[];
    const int tid = threadIdx.x;
    const int wid = tid >> 5;
    const int lane = tid & 31;
    const int lq = lane >> 2;
    const int lk = lane & 3;
    const int bm = blockIdx.y * 128;
    const int bn = blockIdx.x * 64;

    GemmAcc G;
    gemm_f16_mainloop(sm, Ah, Al, W, bm, bn, tid, wid, lane, G);

    #pragma unroll
    for (int mi = 0; mi < 2; mi++) {
        const int r = bm + wid * 32 + mi * 16 + lq;
        #pragma unroll
        for (int ni = 0; ni < 8; ni++) {
            const int c = bn + ni * 8 + lk * 2;
            const float b0 = bias[c], b1 = bias[c + 1];
            *(float2*)&Cf[(size_t)r * EMB + c] =
                make_float2(G.a[mi][ni][0] + b0, G.a[mi][ni][1] + b1);
            *(float2*)&Cf[(size_t)(r + 8) * EMB + c] =
                make_float2(G.a[mi][ni][2] + b0, G.a[mi][ni][3] + b1);
        }
    }
}

// ===== fp16 flash attention, key-split 3-way, f16x2 softmax, 3-stage =====
// smem: K[3][64][72] @0 (9216/st), V[3][64][72] @27648, mask half[3][64] @55296
#define AT_ST 9216
#define A_V_OFF 27648
#define A_M_OFF 55296
#define A_SMEM 55680

__global__ __launch_bounds__(128) void attn_mma(
    const __half* __restrict__ Qhf, const __half* __restrict__ Khf,
    const __half* __restrict__ Vhf,
    const unsigned char* __restrict__ mask,
    float* __restrict__ opart, float* __restrict__ lpart)
{
    extern __shared__ char sm[];
    const int h   = blockIdx.y;
    const int z   = blockIdx.z;                  // key split
    const int q0  = blockIdx.x * 128;
    const int tid = threadIdx.x;
    const int wid = tid >> 5;
    const int lane = tid & 31;
    const int lq = lane >> 2;
    const int lk = lane & 3;

    const int t0  = (z == 0) ? 0 : 22 + (z - 1) * 21;   // first key tile
    const int nit = (z == 0) ? 22 : 21;                 // tiles this split

    const size_t hoff = (size_t)h * S_LEN * HDIM;

    const int qr = q0 + wid * 32 + lq;
    uint32_t aQ[2][4][4];
    {
        const __half* Qhp = Qhf + hoff;
        #pragma unroll
        for (int mi = 0; mi < 2; mi++) {
            #pragma unroll
            for (int kc = 0; kc < 4; kc++) {
                const int c = kc * 16 + lk * 2;
                const size_t r0 = (size_t)(qr + mi * 16) * 64;
                const size_t r8 = (size_t)(qr + mi * 16 + 8) * 64;
                aQ[mi][kc][0] = *(const uint32_t*)&Qhp[r0 + c];
                aQ[mi][kc][1] = *(const uint32_t*)&Qhp[r8 + c];
                aQ[mi][kc][2] = *(const uint32_t*)&Qhp[r0 + c + 8];
                aQ[mi][kc][3] = *(const uint32_t*)&Qhp[r8 + c + 8];
            }
        }
    }

    const int rsel = (lane & 7) + ((lane >> 4) << 3);
    const int csel = ((lane >> 3) & 1) << 3;
    const uint32_t base = smem_u32(sm);
    const uint32_t bK = base + (rsel * 72 + csel) * 2;
    __half* smadd = (__half*)(sm + A_M_OFF);

    const int trow = tid >> 1;
    const int tcol = (tid & 1) * 32;

    auto load_tile = [&](int s, int k0) {
        const __half* kh = Khf + hoff + (size_t)(k0 + trow) * 64 + tcol;
        const __half* vh = Vhf + hoff + (size_t)trow * S_LEN + k0 + tcol;
        const uint32_t d = base + s * AT_ST + (trow * 72 + tcol) * 2;
        #pragma unroll
        for (int i = 0; i < 4; i++) {
            cp16(d + i * 16,           kh + i * 8);
            cp16(d + A_V_OFF + i * 16, vh + i * 8);
        }
        if (tid < 64)
            smadd[s * 64 + tid] = mask[k0 + tid] ? __float2half(-30000.f)
                                                 : __float2half(0.f);
    };

    float o[2][8][4];
    #pragma unroll
    for (int mi = 0; mi < 2; mi++)
        #pragma unroll
        for (int j = 0; j < 8; j++)
            #pragma unroll
            for (int i = 0; i < 4; i++) o[mi][j][i] = 0.f;
    float lsum[2][2] = {{0.f, 0.f}, {0.f, 0.f}};   // [m-tile][row half]

    load_tile(0, t0 * 64);
    CP_COMMIT();
    load_tile(1, (t0 + 1) * 64);
    CP_COMMIT();

    int cur = 0, nxt = 2;
    #pragma unroll 1
    for (int it = 0; it < nit; it++) {
        CP_WAIT1();
        __syncthreads();
        if (it + 2 < nit) {
            load_tile(nxt, (t0 + it + 2) * 64);
            CP_COMMIT();
        }

        const uint32_t cK = bK + cur * AT_ST;
        const uint32_t cV = cK + A_V_OFF;
        const __half2* md2 = (const __half2*)(smadd + cur * 64);

        // ---- S = Q K^T ----
        float s[2][8][4];
        #pragma unroll
        for (int mi = 0; mi < 2; mi++)
            #pragma unroll
            for (int j = 0; j < 8; j++)
                s[mi][j][0] = s[mi][j][1] = s[mi][j][2] = s[mi][j][3] = 0.f;

        #pragma unroll
        for (int jp = 0; jp < 4; jp++) {
            #pragma unroll
            for (int kc = 0; kc < 4; kc++) {
                const uint32_t off = (uint32_t)(jp * 2304 + kc * 32);
                uint32_t h0, h1, h2, h3;
                ldsm_x4(h0, h1, h2, h3, cK + off);
                mma_f16(s[0][2 * jp],     aQ[0][kc], h0, h1);
                mma_f16(s[0][2 * jp + 1], aQ[0][kc], h2, h3);
                mma_f16(s[1][2 * jp],     aQ[1][kc], h0, h1);
                mma_f16(s[1][2 * jp + 1], aQ[1][kc], h2, h3);
            }
        }

        // ---- p = 2^(s + mask) in f16x2; l via shallow HADD2 tree ----
        uint32_t ph[2][4][4];
        #pragma unroll
        for (int mi = 0; mi < 2; mi++) {
            #pragma unroll
            for (int j = 0; j < 8; j++) {
                __half2 mv = md2[j * 4 + lk];
                __half2 s01 = __floats2half2_rn(s[mi][j][0], s[mi][j][1]);
                __half2 s23 = __floats2half2_rn(s[mi][j][2], s[mi][j][3]);
                s01 = __hadd2(s01, mv);
                s23 = __hadd2(s23, mv);
                ph[mi][j >> 1][2 * (j & 1) + 0] = ex2_h2(*(uint32_t*)&s01);
                ph[mi][j >> 1][2 * (j & 1) + 1] = ex2_h2(*(uint32_t*)&s23);
            }
            // l tree: row-half0 = slots {0,2}, row-half1 = slots {1,3}
            uint32_t a0 = hadd2u(hadd2u(ph[mi][0][0], ph[mi][0][2]),
                                 hadd2u(ph[mi][1][0], ph[mi][1][2]));
            uint32_t b0 = hadd2u(hadd2u(ph[mi][2][0], ph[mi][2][2]),
                                 hadd2u(ph[mi][3][0], ph[mi][3][2]));
            uint32_t a1 = hadd2u(hadd2u(ph[mi][0][1], ph[mi][0][3]),
                                 hadd2u(ph[mi][1][1], ph[mi][1][3]));
            uint32_t b1 = hadd2u(hadd2u(ph[mi][2][1], ph[mi][2][3]),
                                 hadd2u(ph[mi][3][1], ph[mi][3][3]));
            float2 f0a = __half22float2(*(__half2*)&a0);
            float2 f0b = __half22float2(*(__half2*)&b0);
            float2 f1a = __half22float2(*(__half2*)&a1);
            float2 f1b = __half22float2(*(__half2*)&b1);
            lsum[mi][0] += (f0a.x + f0a.y) + (f0b.x + f0b.y);
            lsum[mi][1] += (f1a.x + f1a.y) + (f1b.x + f1b.y);
        }

        // ---- O += P V ----
        #pragma unroll
        for (int jp = 0; jp < 4; jp++) {
            #pragma unroll
            for (int kc = 0; kc < 4; kc++) {
                const uint32_t off = (uint32_t)(jp * 2304 + kc * 32);
                uint32_t h0, h1, h2, h3;
                ldsm_x4(h0, h1, h2, h3, cV + off);
                mma_f16(o[0][2 * jp],     ph[0][kc], h0, h1);
                mma_f16(o[0][2 * jp + 1], ph[0][kc], h2, h3);
                mma_f16(o[1][2 * jp],     ph[1][kc], h0, h1);
                mma_f16(o[1][2 * jp + 1], ph[1][kc], h2, h3);
            }
        }

        cur = (cur == 2) ? 0 : cur + 1;
        nxt = (nxt == 2) ? 0 : nxt + 1;
    }

    // ---- epilogue: write UNNORMALIZED partials (fp32) + l ----
    float* opz = opart + (size_t)z * S_LEN * EMB;
    #pragma unroll
    for (int mi = 0; mi < 2; mi++) {
        lsum[mi][0] += __shfl_xor_sync(0xffffffffu, lsum[mi][0], 1);
        lsum[mi][0] += __shfl_xor_sync(0xffffffffu, lsum[mi][0], 2);
        lsum[mi][1] += __shfl_xor_sync(0xffffffffu, lsum[mi][1], 1);
        lsum[mi][1] += __shfl_xor_sync(0xffffffffu, lsum[mi][1], 2);
        const int r = qr + mi * 16;
        #pragma unroll
        for (int j = 0; j < 8; j++) {
            const int c = h * 64 + j * 8 + lk * 2;
            *(float2*)&opz[(size_t)r * EMB + c] =
                make_float2(o[mi][j][0], o[mi][j][1]);
            *(float2*)&opz[(size_t)(r + 8) * EMB + c] =
                make_float2(o[mi][j][2], o[mi][j][3]);
        }
        if (lk == 0) {
            lpart[((size_t)z * NHEAD + h) * S_LEN + r]     = lsum[mi][0];
            lpart[((size_t)z * NHEAD + h) * S_LEN + r + 8] = lsum[mi][1];
        }
    }
}

// ---- combine: out = (o0+o1+o2)/(l0+l1+l2), emit fp16 hi/lo ----
__global__ __launch_bounds__(256) void combine_kernel(
    const float* __restrict__ op, const float* __restrict__ lp,
    __half* __restrict__ Ohi, __half* __restrict__ Olo)
{
    const int i = blockIdx.x * 256 + threadIdx.x;   // float4 index
    if (i >= S_LEN * EMB / 4) return;
    const int e4 = i * 4;
    const int q = e4 / EMB;
    const int c = e4 % EMB;
    const int h = c >> 6;
    const float l = lp[(size_t)h * S_LEN + q]
                  + lp[((size_t)NHEAD + h) * S_LEN + q]
                  + lp[((size_t)2 * NHEAD + h) * S_LEN + q];
    const float inv = 1.0f / l;
    float4 o0 = ((const float4*)op)[i];
    float4 o1 = ((const float4*)(op + (size_t)S_LEN * EMB))[i];
    float4 o2 = ((const float4*)(op + 2 * (size_t)S_LEN * EMB))[i];
    const float v0 = (o0.x + o1.x + o2.x) * inv;
    const float v1 = (o0.y + o1.y + o2.y) * inv;
    const float v2 = (o0.z + o1.z + o2.z) * inv;
    const float v3 = (o0.w + o1.w + o2.w) * inv;
    __half2 h01 = __floats2half2_rn(v0, v1);
    __half2 h23 = __floats2half2_rn(v2, v3);
    float2 f01 = __half22float2(h01);
    float2 f23 = __half22float2(h23);
    ((__half2*)Ohi)[i * 2]     = h01;
    ((__half2*)Ohi)[i * 2 + 1] = h23;
    ((__half2*)Olo)[i * 2]     = __floats2half2_rn(v0 - f01.x, v1 - f01.y);
    ((__half2*)Olo)[i * 2 + 1] = __floats2half2_rn(v2 - f23.x, v3 - f23.y);
}

// ---------------- launch ----------------
extern "C" void kernel_launch(void* const* d_in, const int* in_sizes, int n_in,
                              void* d_out, int out_size)
{
    const float* x  = (const float*)d_in[0];
    const unsigned char* mask = (const unsigned char*)d_in[1];
    const float* Wq = (const float*)d_in[2];
    const float* bq = (const float*)d_in[3];
    const float* Wk = (const float*)d_in[4];
    const float* bk = (const float*)d_in[5];
    const float* Wv = (const float*)d_in[6];
    const float* bv = (const float*)d_in[7];
    const float* Wo = (const float*)d_in[8];
    const float* bo = (const float*)d_in[9];
    float* out = (float*)d_out;

    __half *xfh, *xfl, *wf, *Qh, *Kh, *Vh, *ath, *atl;
    float *opart, *lpart;
    cudaGetSymbolAddress((void**)&xfh, g_xfh);
    cudaGetSymbolAddress((void**)&xfl, g_xfl);
    cudaGetSymbolAddress((void**)&wf,  g_wf);
    cudaGetSymbolAddress((void**)&Qh, g_Qhf);
    cudaGetSymbolAddress((void**)&Kh, g_Khf);
    cudaGetSymbolAddress((void**)&Vh, g_Vhf);
    cudaGetSymbolAddress((void**)&opart, g_opart);
    cudaGetSymbolAddress((void**)&lpart, g_lpart);
    cudaGetSymbolAddress((void**)&ath, g_ath);
    cudaGetSymbolAddress((void**)&atl, g_atl);

    cudaFuncSetAttribute(gemm_qkv, cudaFuncAttributeMaxDynamicSharedMemorySize, Q_SMEM);
    cudaFuncSetAttribute(gemm_out, cudaFuncAttributeMaxDynamicSharedMemorySize, Q_SMEM);
    cudaFuncSetAttribute(attn_mma, cudaFuncAttributeMaxDynamicSharedMemorySize, A_SMEM);

    const int nx4 = S_LEN * EMB / 4;
    const int nw4 = WW / 4;
    split_x_kernel<<<(nx4 + 255) / 256, 256>>>(x, xfh, xfl, nx4);
    dim3 wgrid((nw4 + 255) / 256, 4);
    split_w_kernel<<<wgrid, 256>>>(Wq, Wk, Wv, Wo, wf, nw4);

    dim3 qgrid(EMB / 64, S_LEN / 128, 3);      // (12, 32, 3)
    gemm_qkv<<<qgrid, 128, Q_SMEM>>>(xfh, xfl, wf, bq, bk, bv, Qh, Kh, Vh);

    dim3 agrid(S_LEN / 128, NHEAD, NSPLIT);    // (32, 12, 3)
    attn_mma<<<agrid, 128, A_SMEM>>>(Qh, Kh, Vh, mask, opart, lpart);

    const int nc = S_LEN * EMB / 4;
    combine_kernel<<<(nc + 255) / 256, 256>>>(opart, lpart, ath, atl);

    dim3 ogrid(EMB / 64, S_LEN / 128);         // (12, 32)
    gemm_out<<<ogrid, 128, Q_SMEM>>>(ath, atl, wf + 3 * WW, bo, out);
}

// round 12
// speedup vs baseline: 6.9678x; 1.0282x over previous
#include <cuda_runtime.h>
#include <cuda_bf16.h>
#include <cuda_fp16.h>
#include <cstdint>

#define S_LEN 4096
#define EMB   768
#define NHEAD 12
#define HDIM  64
#define WW    (EMB * EMB)
#define NSPLIT 3

// ---------------- scratch (no allocations allowed) ----------------
__device__ __half g_xfh[S_LEN * EMB];            // x fp16 hi
__device__ __half g_xfl[S_LEN * EMB];            // x fp16 lo
__device__ __half g_wf[4][WW];                   // Wq/Wk/Wv/Wo fp16
__device__ __half g_Qhf[NHEAD * S_LEN * HDIM];   // [H][S][D] fp16, pre-scaled log2e/sqrt(E)
__device__ __half g_Khf[NHEAD * S_LEN * HDIM];   // [H][S][D] fp16
__device__ __half g_Vhf[NHEAD * HDIM * S_LEN];   // [H][D][S] fp16 (transposed)
__device__ float  g_opart[NSPLIT * S_LEN * EMB]; // unnormalized O partials (fp32)
__device__ float  g_lpart[NSPLIT * NHEAD * S_LEN];
__device__ __half g_ath[S_LEN * EMB];            // attn out fp16 hi
__device__ __half g_atl[S_LEN * EMB];            // attn out fp16 lo

__device__ __forceinline__ uint32_t smem_u32(const void* p)
{
    return (uint32_t)__cvta_generic_to_shared(p);
}

__device__ __forceinline__ void cp16(uint32_t saddr, const void* g)
{
    asm volatile("cp.async.cg.shared.global [%0], [%1], 16;" :: "r"(saddr), "l"(g));
}
#define CP_COMMIT() asm volatile("cp.async.commit_group;")
#define CP_WAIT1()  asm volatile("cp.async.wait_group 1;")
#define CP_WAIT0()  asm volatile("cp.async.wait_group 0;")

__device__ __forceinline__ void ldsm_x4(uint32_t& r0, uint32_t& r1,
                                        uint32_t& r2, uint32_t& r3, uint32_t addr)
{
    asm volatile("ldmatrix.sync.aligned.m8n8.x4.shared.b16 {%0,%1,%2,%3}, [%4];"
                 : "=r"(r0), "=r"(r1), "=r"(r2), "=r"(r3) : "r"(addr));
}

__device__ __forceinline__ void mma_f16(float* c, const uint32_t* a,
                                        uint32_t b0, uint32_t b1)
{
    asm volatile(
        "mma.sync.aligned.m16n8k16.row.col.f32.f16.f16.f32 "
        "{%0,%1,%2,%3},{%4,%5,%6,%7},{%8,%9},{%0,%1,%2,%3};"
        : "+f"(c[0]), "+f"(c[1]), "+f"(c[2]), "+f"(c[3])
        : "r"(a[0]), "r"(a[1]), "r"(a[2]), "r"(a[3]), "r"(b0), "r"(b1));
}

__device__ __forceinline__ uint32_t ex2_h2(uint32_t x)
{
    uint32_t r;
    asm("ex2.approx.f16x2 %0, %1;" : "=r"(r) : "r"(x));
    return r;
}

__device__ __forceinline__ uint32_t hadd2u(uint32_t a, uint32_t b)
{
    __half2 r = __hadd2(*(__half2*)&a, *(__half2*)&b);
    return *(uint32_t*)&r;
}

// ---------------- x: fp32 -> fp16 hi/lo ----------------
__global__ __launch_bounds__(256) void split_x_kernel(
    const float* __restrict__ in, __half* __restrict__ hi,
    __half* __restrict__ lo, int n4)
{
    const int i = blockIdx.x * 256 + threadIdx.x;
    if (i >= n4) return;
    float4 v = ((const float4*)in)[i];
    __half2 h01 = __floats2half2_rn(v.x, v.y);
    __half2 h23 = __floats2half2_rn(v.z, v.w);
    float2 f01 = __half22float2(h01);
    float2 f23 = __half22float2(h23);
    __half2* hp = (__half2*)(hi + i * 4);
    __half2* lp = (__half2*)(lo + i * 4);
    hp[0] = h01; hp[1] = h23;
    lp[0] = __floats2half2_rn(v.x - f01.x, v.y - f01.y);
    lp[1] = __floats2half2_rn(v.z - f23.x, v.w - f23.y);
}

// all 4 weights -> fp16 (y selects matrix)
__global__ __launch_bounds__(256) void split_w_kernel(
    const float* __restrict__ w0, const float* __restrict__ w1,
    const float* __restrict__ w2, const float* __restrict__ w3,
    __half* __restrict__ wf, int n4)
{
    const int i = blockIdx.x * 256 + threadIdx.x;
    if (i >= n4) return;
    const int y = blockIdx.y;
    const float* src = (y == 0) ? w0 : (y == 1) ? w1 : (y == 2) ? w2 : w3;
    float4 v = ((const float4*)src)[i];
    __half2* p = (__half2*)(wf + (size_t)y * WW + i * 4);
    p[0] = __floats2half2_rn(v.x, v.y);
    p[1] = __floats2half2_rn(v.z, v.w);
}

// ================= fp16 2-term GEMM core (A hi/lo exact, B fp16) =========
#define QA_ST 10240
#define QB_ST 5120
#define Q_SMEM 51200

struct GemmAcc { float a[2][8][4]; };

__device__ __forceinline__ void gemm_f16_mainloop(
    char* sm,
    const __half* __restrict__ Ah, const __half* __restrict__ Al,
    const __half* __restrict__ W,
    int bm, int bn, int tid, int wid, int lane, GemmAcc& G)
{
    #pragma unroll
    for (int mi = 0; mi < 2; mi++)
        #pragma unroll
        for (int ni = 0; ni < 8; ni++)
            #pragma unroll
            for (int i = 0; i < 4; i++) G.a[mi][ni][i] = 0.f;

    const uint32_t base = smem_u32(sm);
    const int brow = tid >> 1;
    const int bcol = (tid & 1) * 16;

    auto load_stage = [&](int s, int k0) {
        const __half* ah = Ah + (size_t)(bm + tid) * EMB + k0;
        const __half* al = Al + (size_t)(bm + tid) * EMB + k0;
        uint32_t dA = base + s * QA_ST + tid * 80;
        #pragma unroll
        for (int i = 0; i < 4; i++) {
            cp16(dA + i * 16, ah + i * 8);
            cp16(dA + 20480 + i * 16, al + i * 8);
        }
        const __half* bw = W + (size_t)(bn + brow) * EMB + k0 + bcol;
        uint32_t dB = base + 40960 + s * QB_ST + brow * 80 + bcol * 2;
        cp16(dB, bw); cp16(dB + 16, bw + 8);
    };

    const int rselA = lane & 15;
    const int cselA = (lane >> 4) << 3;
    const int rselB = (lane & 7) + ((lane >> 4) << 3);
    const int cselB = ((lane >> 3) & 1) << 3;
    const uint32_t bAh = base + (wid * 32 + rselA) * 80 + cselA * 2;
    const uint32_t bB  = base + 40960 + rselB * 80 + cselB * 2;

    load_stage(0, 0);
    CP_COMMIT();

    const int NIT = EMB / 32;  // 24
    #pragma unroll 1
    for (int it = 0; it < NIT; it++) {
        const int cur = it & 1;
        if (it + 1 < NIT) {
            load_stage(cur ^ 1, (it + 1) * 32);
            CP_COMMIT();
            CP_WAIT1();
        } else {
            CP_WAIT0();
        }
        __syncthreads();

        const uint32_t cAh = bAh + cur * QA_ST;
        const uint32_t cAl = cAh + 20480;
        const uint32_t cB  = bB + cur * QB_ST;

        #pragma unroll
        for (int ks = 0; ks < 32; ks += 16) {
            uint32_t fah[2][4], fal[2][4];
            #pragma unroll
            for (int mi = 0; mi < 2; mi++) {
                const uint32_t off = (uint32_t)(mi * 16 * 80 + ks * 2);
                ldsm_x4(fah[mi][0], fah[mi][1], fah[mi][2], fah[mi][3], cAh + off);
                ldsm_x4(fal[mi][0], fal[mi][1], fal[mi][2], fal[mi][3], cAl + off);
            }
            #pragma unroll
            for (int nip = 0; nip < 4; nip++) {
                const uint32_t off = (uint32_t)(nip * 16 * 80 + ks * 2);
                uint32_t h0, h1, h2, h3;
                ldsm_x4(h0, h1, h2, h3, cB + off);
                #pragma unroll
                for (int mi = 0; mi < 2; mi++) {
                    mma_f16(G.a[mi][2 * nip],     fah[mi], h0, h1);
                    mma_f16(G.a[mi][2 * nip],     fal[mi], h0, h1);
                    mma_f16(G.a[mi][2 * nip + 1], fah[mi], h2, h3);
                    mma_f16(G.a[mi][2 * nip + 1], fal[mi], h2, h3);
                }
            }
        }
        __syncthreads();
    }
}

// QKV projection: grid (12, 32, 3); z: 0=Q (fp16, pre-scaled), 1=K, 2=V (T)
__global__ __launch_bounds__(128, 3) void gemm_qkv(
    const __half* __restrict__ xh, const __half* __restrict__ xl,
    const __half* __restrict__ wf,
    const float* __restrict__ bq, const float* __restrict__ bk,
    const float* __restrict__ bv,
    __half* __restrict__ Qh, __half* __restrict__ Kh, __half* __restrict__ Vh)
{
    extern __shared__ char sm[];
    const int z = blockIdx.z;
    const int tid = threadIdx.x;
    const int wid = tid >> 5;
    const int lane = tid & 31;
    const int lq = lane >> 2;
    const int lk = lane & 3;
    const int bm = blockIdx.y * 128;
    const int bn = blockIdx.x * 64;

    const __half* W = wf + (size_t)z * WW;
    const float* bias = (z == 0) ? bq : (z == 1) ? bk : bv;
    const float qs = (z == 0) ? 1.4426950408889634f * rsqrtf((float)EMB) : 1.0f;

    GemmAcc G;
    gemm_f16_mainloop(sm, xh, xl, W, bm, bn, tid, wid, lane, G);

    #pragma unroll
    for (int mi = 0; mi < 2; mi++) {
        const int r = bm + wid * 32 + mi * 16 + lq;
        #pragma unroll
        for (int ni = 0; ni < 8; ni++) {
            const int c = bn + ni * 8 + lk * 2;
            const float b0 = bias[c], b1 = bias[c + 1];
            float v0 = (G.a[mi][ni][0] + b0) * qs;
            float v1 = (G.a[mi][ni][1] + b1) * qs;
            float v2 = (G.a[mi][ni][2] + b0) * qs;
            float v3 = (G.a[mi][ni][3] + b1) * qs;
            const int hh = c >> 6, d = c & 63;
            const size_t i0 = ((size_t)hh * S_LEN + r) * HDIM + d;
            const size_t i1 = ((size_t)hh * S_LEN + r + 8) * HDIM + d;
            if (z == 0) {
                *(__half2*)&Qh[i0] = __floats2half2_rn(v0, v1);
                *(__half2*)&Qh[i1] = __floats2half2_rn(v2, v3);
            } else if (z == 1) {
                *(__half2*)&Kh[i0] = __floats2half2_rn(v0, v1);
                *(__half2*)&Kh[i1] = __floats2half2_rn(v2, v3);
            } else {
                Vh[(size_t)c * S_LEN + r]           = __float2half_rn(v0);
                Vh[(size_t)(c + 1) * S_LEN + r]     = __float2half_rn(v1);
                Vh[(size_t)c * S_LEN + r + 8]       = __float2half_rn(v2);
                Vh[(size_t)(c + 1) * S_LEN + r + 8] = __float2half_rn(v3);
            }
        }
    }
}

// Output projection: fp16 2-term, fp32 result
__global__ __launch_bounds__(128, 3) void gemm_out(
    const __half* __restrict__ Ah, const __half* __restrict__ Al,
    const __half* __restrict__ W,
    const float* __restrict__ bias, float* __restrict__ Cf)
{
    extern __shared__ char sm[];
    const int tid = threadIdx.x;
    const int wid = tid >> 5;
    const int lane = tid & 31;
    const int lq = lane >> 2;
    const int lk = lane & 3;
    const int bm = blockIdx.y * 128;
    const int bn = blockIdx.x * 64;

    GemmAcc G;
    gemm_f16_mainloop(sm, Ah, Al, W, bm, bn, tid, wid, lane, G);

    #pragma unroll
    for (int mi = 0; mi < 2; mi++) {
        const int r = bm + wid * 32 + mi * 16 + lq;
        #pragma unroll
        for (int ni = 0; ni < 8; ni++) {
            const int c = bn + ni * 8 + lk * 2;
            const float b0 = bias[c], b1 = bias[c + 1];
            *(float2*)&Cf[(size_t)r * EMB + c] =
                make_float2(G.a[mi][ni][0] + b0, G.a[mi][ni][1] + b1);
            *(float2*)&Cf[(size_t)(r + 8) * EMB + c] =
                make_float2(G.a[mi][ni][2] + b0, G.a[mi][ni][3] + b1);
        }
    }
}

// ===== fp16 flash attention, key-split 3-way, streamed S->P, 3 CTAs/SM ===
// smem: K[3][64][72] @0 (9216/st), V[3][64][72] @27648, mask half[3][64] @55296
#define AT_ST 9216
#define A_V_OFF 27648
#define A_M_OFF 55296
#define A_SMEM 55680

__global__ __launch_bounds__(128, 3) void attn_mma(
    const __half* __restrict__ Qhf, const __half* __restrict__ Khf,
    const __half* __restrict__ Vhf,
    const unsigned char* __restrict__ mask,
    float* __restrict__ opart, float* __restrict__ lpart)
{
    extern __shared__ char sm[];
    const int h   = blockIdx.y;
    const int z   = blockIdx.z;                  // key split
    const int q0  = blockIdx.x * 128;
    const int tid = threadIdx.x;
    const int wid = tid >> 5;
    const int lane = tid & 31;
    const int lq = lane >> 2;
    const int lk = lane & 3;

    const int t0  = (z == 0) ? 0 : 22 + (z - 1) * 21;   // first key tile
    const int nit = (z == 0) ? 22 : 21;                 // tiles this split

    const size_t hoff = (size_t)h * S_LEN * HDIM;

    const int qr = q0 + wid * 32 + lq;
    uint32_t aQ[2][4][4];
    {
        const __half* Qhp = Qhf + hoff;
        #pragma unroll
        for (int mi = 0; mi < 2; mi++) {
            #pragma unroll
            for (int kc = 0; kc < 4; kc++) {
                const int c = kc * 16 + lk * 2;
                const size_t r0 = (size_t)(qr + mi * 16) * 64;
                const size_t r8 = (size_t)(qr + mi * 16 + 8) * 64;
                aQ[mi][kc][0] = *(const uint32_t*)&Qhp[r0 + c];
                aQ[mi][kc][1] = *(const uint32_t*)&Qhp[r8 + c];
                aQ[mi][kc][2] = *(const uint32_t*)&Qhp[r0 + c + 8];
                aQ[mi][kc][3] = *(const uint32_t*)&Qhp[r8 + c + 8];
            }
        }
    }

    const int rsel = (lane & 7) + ((lane >> 4) << 3);
    const int csel = ((lane >> 3) & 1) << 3;
    const uint32_t base = smem_u32(sm);
    const uint32_t bK = base + (rsel * 72 + csel) * 2;
    __half* smadd = (__half*)(sm + A_M_OFF);

    const int trow = tid >> 1;
    const int tcol = (tid & 1) * 32;

    auto load_tile = [&](int s, int k0) {
        const __half* kh = Khf + hoff + (size_t)(k0 + trow) * 64 + tcol;
        const __half* vh = Vhf + hoff + (size_t)trow * S_LEN + k0 + tcol;
        const uint32_t d = base + s * AT_ST + (trow * 72 + tcol) * 2;
        #pragma unroll
        for (int i = 0; i < 4; i++) {
            cp16(d + i * 16,           kh + i * 8);
            cp16(d + A_V_OFF + i * 16, vh + i * 8);
        }
        if (tid < 64)
            smadd[s * 64 + tid] = mask[k0 + tid] ? __float2half(-30000.f)
                                                 : __float2half(0.f);
    };

    float o[2][8][4];
    #pragma unroll
    for (int mi = 0; mi < 2; mi++)
        #pragma unroll
        for (int j = 0; j < 8; j++)
            #pragma unroll
            for (int i = 0; i < 4; i++) o[mi][j][i] = 0.f;
    float lsum[2][2] = {{0.f, 0.f}, {0.f, 0.f}};   // [m-tile][row half]

    load_tile(0, t0 * 64);
    CP_COMMIT();
    load_tile(1, (t0 + 1) * 64);
    CP_COMMIT();

    int cur = 0, nxt = 2;
    #pragma unroll 1
    for (int it = 0; it < nit; it++) {
        CP_WAIT1();
        __syncthreads();
        if (it + 2 < nit) {
            load_tile(nxt, (t0 + it + 2) * 64);
            CP_COMMIT();
        }

        const uint32_t cK = bK + cur * AT_ST;
        const uint32_t cV = cK + A_V_OFF;
        const __half2* md2 = (const __half2*)(smadd + cur * 64);

        // ---- streamed S -> P per 16-key group (keeps live regs low) ----
        uint32_t ph[2][4][4];
        #pragma unroll
        for (int jp = 0; jp < 4; jp++) {
            float st[2][2][4];
            #pragma unroll
            for (int mi = 0; mi < 2; mi++)
                #pragma unroll
                for (int half = 0; half < 2; half++)
                    st[mi][half][0] = st[mi][half][1] =
                    st[mi][half][2] = st[mi][half][3] = 0.f;

            #pragma unroll
            for (int kc = 0; kc < 4; kc++) {
                const uint32_t off = (uint32_t)(jp * 2304 + kc * 32);
                uint32_t h0, h1, h2, h3;
                ldsm_x4(h0, h1, h2, h3, cK + off);
                mma_f16(st[0][0], aQ[0][kc], h0, h1);
                mma_f16(st[0][1], aQ[0][kc], h2, h3);
                mma_f16(st[1][0], aQ[1][kc], h0, h1);
                mma_f16(st[1][1], aQ[1][kc], h2, h3);
            }

            const __half2 mv0 = md2[(2 * jp) * 4 + lk];
            const __half2 mv1 = md2[(2 * jp + 1) * 4 + lk];
            #pragma unroll
            for (int mi = 0; mi < 2; mi++) {
                __half2 a01 = __hadd2(__floats2half2_rn(st[mi][0][0], st[mi][0][1]), mv0);
                __half2 a23 = __hadd2(__floats2half2_rn(st[mi][0][2], st[mi][0][3]), mv0);
                __half2 b01 = __hadd2(__floats2half2_rn(st[mi][1][0], st[mi][1][1]), mv1);
                __half2 b23 = __hadd2(__floats2half2_rn(st[mi][1][2], st[mi][1][3]), mv1);
                ph[mi][jp][0] = ex2_h2(*(uint32_t*)&a01);
                ph[mi][jp][1] = ex2_h2(*(uint32_t*)&a23);
                ph[mi][jp][2] = ex2_h2(*(uint32_t*)&b01);
                ph[mi][jp][3] = ex2_h2(*(uint32_t*)&b23);
                uint32_t u0 = hadd2u(ph[mi][jp][0], ph[mi][jp][2]);
                uint32_t u1 = hadd2u(ph[mi][jp][1], ph[mi][jp][3]);
                float2 f0 = __half22float2(*(__half2*)&u0);
                float2 f1 = __half22float2(*(__half2*)&u1);
                lsum[mi][0] += f0.x + f0.y;
                lsum[mi][1] += f1.x + f1.y;
            }
        }

        // ---- O += P V ----
        #pragma unroll
        for (int jp = 0; jp < 4; jp++) {
            #pragma unroll
            for (int kc = 0; kc < 4; kc++) {
                const uint32_t off = (uint32_t)(jp * 2304 + kc * 32);
                uint32_t h0, h1, h2, h3;
                ldsm_x4(h0, h1, h2, h3, cV + off);
                mma_f16(o[0][2 * jp],     ph[0][kc], h0, h1);
                mma_f16(o[0][2 * jp + 1], ph[0][kc], h2, h3);
                mma_f16(o[1][2 * jp],     ph[1][kc], h0, h1);
                mma_f16(o[1][2 * jp + 1], ph[1][kc], h2, h3);
            }
        }

        cur = (cur == 2) ? 0 : cur + 1;
        nxt = (nxt == 2) ? 0 : nxt + 1;
    }

    // ---- epilogue: write UNNORMALIZED partials (fp32) + l ----
    float* opz = opart + (size_t)z * S_LEN * EMB;
    #pragma unroll
    for (int mi = 0; mi < 2; mi++) {
        lsum[mi][0] += __shfl_xor_sync(0xffffffffu, lsum[mi][0], 1);
        lsum[mi][0] += __shfl_xor_sync(0xffffffffu, lsum[mi][0], 2);
        lsum[mi][1] += __shfl_xor_sync(0xffffffffu, lsum[mi][1], 1);
        lsum[mi][1] += __shfl_xor_sync(0xffffffffu, lsum[mi][1], 2);
        const int r = qr + mi * 16;
        #pragma unroll
        for (int j = 0; j < 8; j++) {
            const int c = h * 64 + j * 8 + lk * 2;
            *(float2*)&opz[(size_t)r * EMB + c] =
                make_float2(o[mi][j][0], o[mi][j][1]);
            *(float2*)&opz[(size_t)(r + 8) * EMB + c] =
                make_float2(o[mi][j][2], o[mi][j][3]);
        }
        if (lk == 0) {
            lpart[((size_t)z * NHEAD + h) * S_LEN + r]     = lsum[mi][0];
            lpart[((size_t)z * NHEAD + h) * S_LEN + r + 8] = lsum[mi][1];
        }
    }
}

// ---- combine: out = (o0+o1+o2)/(l0+l1+l2), emit fp16 hi/lo ----
__global__ __launch_bounds__(256) void combine_kernel(
    const float* __restrict__ op, const float* __restrict__ lp,
    __half* __restrict__ Ohi, __half* __restrict__ Olo)
{
    const int i = blockIdx.x * 256 + threadIdx.x;   // float4 index
    if (i >= S_LEN * EMB / 4) return;
    const int e4 = i * 4;
    const int q = e4 / EMB;
    const int c = e4 % EMB;
    const int h = c >> 6;
    const float l = lp[(size_t)h * S_LEN + q]
                  + lp[((size_t)NHEAD + h) * S_LEN + q]
                  + lp[((size_t)2 * NHEAD + h) * S_LEN + q];
    const float inv = 1.0f / l;
    float4 o0 = ((const float4*)op)[i];
    float4 o1 = ((const float4*)(op + (size_t)S_LEN * EMB))[i];
    float4 o2 = ((const float4*)(op + 2 * (size_t)S_LEN * EMB))[i];
    const float v0 = (o0.x + o1.x + o2.x) * inv;
    const float v1 = (o0.y + o1.y + o2.y) * inv;
    const float v2 = (o0.z + o1.z + o2.z) * inv;
    const float v3 = (o0.w + o1.w + o2.w) * inv;
    __half2 h01 = __floats2half2_rn(v0, v1);
    __half2 h23 = __floats2half2_rn(v2, v3);
    float2 f01 = __half22float2(h01);
    float2 f23 = __half22float2(h23);
    ((__half2*)Ohi)[i * 2]     = h01;
    ((__half2*)Ohi)[i * 2 + 1] = h23;
    ((__half2*)Olo)[i * 2]     = __floats2half2_rn(v0 - f01.x, v1 - f01.y);
    ((__half2*)Olo)[i * 2 + 1] = __floats2half2_rn(v2 - f23.x, v3 - f23.y);
}

// ---------------- launch ----------------
extern "C" void kernel_launch(void* const* d_in, const int* in_sizes, int n_in,
                              void* d_out, int out_size)
{
    const float* x  = (const float*)d_in[0];
    const unsigned char* mask = (const unsigned char*)d_in[1];
    const float* Wq = (const float*)d_in[2];
    const float* bq = (const float*)d_in[3];
    const float* Wk = (const float*)d_in[4];
    const float* bk = (const float*)d_in[5];
    const float* Wv = (const float*)d_in[6];
    const float* bv = (const float*)d_in[7];
    const float* Wo = (const float*)d_in[8];
    const float* bo = (const float*)d_in[9];
    float* out = (float*)d_out;

    __half *xfh, *xfl, *wf, *Qh, *Kh, *Vh, *ath, *atl;
    float *opart, *lpart;
    cudaGetSymbolAddress((void**)&xfh, g_xfh);
    cudaGetSymbolAddress((void**)&xfl, g_xfl);
    cudaGetSymbolAddress((void**)&wf,  g_wf);
    cudaGetSymbolAddress((void**)&Qh, g_Qhf);
    cudaGetSymbolAddress((void**)&Kh, g_Khf);
    cudaGetSymbolAddress((void**)&Vh, g_Vhf);
    cudaGetSymbolAddress((void**)&opart, g_opart);
    cudaGetSymbolAddress((void**)&lpart, g_lpart);
    cudaGetSymbolAddress((void**)&ath, g_ath);
    cudaGetSymbolAddress((void**)&atl, g_atl);

    cudaFuncSetAttribute(gemm_qkv, cudaFuncAttributeMaxDynamicSharedMemorySize, Q_SMEM);
    cudaFuncSetAttribute(gemm_out, cudaFuncAttributeMaxDynamicSharedMemorySize, Q_SMEM);
    cudaFuncSetAttribute(attn_mma, cudaFuncAttributeMaxDynamicSharedMemorySize, A_SMEM);

    const int nx4 = S_LEN * EMB / 4;
    const int nw4 = WW / 4;
    split_x_kernel<<<(nx4 + 255) / 256, 256>>>(x, xfh, xfl, nx4);
    dim3 wgrid((nw4 + 255) / 256, 4);
    split_w_kernel<<<wgrid, 256>>>(Wq, Wk, Wv, Wo, wf, nw4);

    dim3 qgrid(EMB / 64, S_LEN / 128, 3);      // (12, 32, 3)
    gemm_qkv<<<qgrid, 128, Q_SMEM>>>(xfh, xfl, wf, bq, bk, bv, Qh, Kh, Vh);

    dim3 agrid(S_LEN / 128, NHEAD, NSPLIT);    // (32, 12, 3)
    attn_mma<<<agrid, 128, A_SMEM>>>(Qh, Kh, Vh, mask, opart, lpart);

    const int nc = S_LEN * EMB / 4;
    combine_kernel<<<(nc + 255) / 256, 256>>>(opart, lpart, ath, atl);

    dim3 ogrid(EMB / 64, S_LEN / 128);         // (12, 32)
    gemm_out<<<ogrid, 128, Q_SMEM>>>(ath, atl, wf + 3 * WW, bo, out);
}

// round 16
// speedup vs baseline: 8.2581x; 1.1852x over previous
#include <cuda_runtime.h>
#include <cuda_bf16.h>
#include <cuda_fp16.h>
#include <cstdint>

#define S_LEN 4096
#define EMB   768
#define NHEAD 12
#define HDIM  64
#define WW    (EMB * EMB)
#define NSPLIT 3

// ---------------- scratch (no allocations allowed) ----------------
__device__ __half g_xf[S_LEN * EMB];             // x fp16
__device__ __half g_wf[4][WW];                   // Wq/Wk/Wv/Wo fp16
__device__ __half g_Qhf[NHEAD * S_LEN * HDIM];   // [H][S][D] fp16, pre-scaled log2e/sqrt(E)
__device__ __half g_Khf[NHEAD * S_LEN * HDIM];   // [H][S][D] fp16
__device__ __half g_Vhf[NHEAD * HDIM * S_LEN];   // [H][D][S] fp16 (transposed)
__device__ float  g_opart[NSPLIT * S_LEN * EMB]; // unnormalized O partials (fp32)
__device__ float  g_lpart[NSPLIT * NHEAD * S_LEN];
__device__ __half g_ath[S_LEN * EMB];            // attn out fp16 hi
__device__ __half g_atl[S_LEN * EMB];            // attn out fp16 lo

__device__ __forceinline__ uint32_t smem_u32(const void* p)
{
    return (uint32_t)__cvta_generic_to_shared(p);
}

__device__ __forceinline__ void cp16(uint32_t saddr, const void* g)
{
    asm volatile("cp.async.cg.shared.global [%0], [%1], 16;" :: "r"(saddr), "l"(g));
}
#define CP_COMMIT() asm volatile("cp.async.commit_group;")
#define CP_WAIT1()  asm volatile("cp.async.wait_group 1;")
#define CP_WAIT0()  asm volatile("cp.async.wait_group 0;")

__device__ __forceinline__ void ldsm_x4(uint32_t& r0, uint32_t& r1,
                                        uint32_t& r2, uint32_t& r3, uint32_t addr)
{
    asm volatile("ldmatrix.sync.aligned.m8n8.x4.shared.b16 {%0,%1,%2,%3}, [%4];"
                 : "=r"(r0), "=r"(r1), "=r"(r2), "=r"(r3) : "r"(addr));
}

__device__ __forceinline__ void mma_f16(float* c, const uint32_t* a,
                                        uint32_t b0, uint32_t b1)
{
    asm volatile(
        "mma.sync.aligned.m16n8k16.row.col.f32.f16.f16.f32 "
        "{%0,%1,%2,%3},{%4,%5,%6,%7},{%8,%9},{%0,%1,%2,%3};"
        : "+f"(c[0]), "+f"(c[1]), "+f"(c[2]), "+f"(c[3])
        : "r"(a[0]), "r"(a[1]), "r"(a[2]), "r"(a[3]), "r"(b0), "r"(b1));
}

__device__ __forceinline__ uint32_t ex2_h2(uint32_t x)
{
    uint32_t r;
    asm("ex2.approx.f16x2 %0, %1;" : "=r"(r) : "r"(x));
    return r;
}

__device__ __forceinline__ uint32_t hadd2u(uint32_t a, uint32_t b)
{
    __half2 r = __hadd2(*(__half2*)&a, *(__half2*)&b);
    return *(uint32_t*)&r;
}

// ---------------- x: fp32 -> fp16 ----------------
__global__ __launch_bounds__(256) void split_x_kernel(
    const float* __restrict__ in, __half* __restrict__ hi, int n4)
{
    const int i = blockIdx.x * 256 + threadIdx.x;
    if (i >= n4) return;
    float4 v = ((const float4*)in)[i];
    __half2* hp = (__half2*)(hi + i * 4);
    hp[0] = __floats2half2_rn(v.x, v.y);
    hp[1] = __floats2half2_rn(v.z, v.w);
}

// all 4 weights -> fp16 (y selects matrix)
__global__ __launch_bounds__(256) void split_w_kernel(
    const float* __restrict__ w0, const float* __restrict__ w1,
    const float* __restrict__ w2, const float* __restrict__ w3,
    __half* __restrict__ wf, int n4)
{
    const int i = blockIdx.x * 256 + threadIdx.x;
    if (i >= n4) return;
    const int y = blockIdx.y;
    const float* src = (y == 0) ? w0 : (y == 1) ? w1 : (y == 2) ? w2 : w3;
    float4 v = ((const float4*)src)[i];
    __half2* p = (__half2*)(wf + (size_t)y * WW + i * 4);
    p[0] = __floats2half2_rn(v.x, v.y);
    p[1] = __floats2half2_rn(v.z, v.w);
}

// ========== QKV GEMM: 1-term fp16 (A fp16, B fp16), grid (12,32,3) =======
// smem: sA[2][128][40] @0 (10240/st), sB[2][64][40] @20480 (5120/st)
#define PA_ST 10240
#define PB_ST 5120
#define P_SMEM 30720

__global__ __launch_bounds__(128, 3) void gemm_qkv(
    const __half* __restrict__ xf, const __half* __restrict__ wf,
    const float* __restrict__ bq, const float* __restrict__ bk,
    const float* __restrict__ bv,
    __half* __restrict__ Qh, __half* __restrict__ Kh, __half* __restrict__ Vh)
{
    extern __shared__ char sm[];
    const int z = blockIdx.z;
    const int tid = threadIdx.x;
    const int wid = tid >> 5;
    const int lane = tid & 31;
    const int lq = lane >> 2;
    const int lk = lane & 3;
    const int bm = blockIdx.y * 128;
    const int bn = blockIdx.x * 64;

    const __half* W = wf + (size_t)z * WW;
    const float* bias = (z == 0) ? bq : (z == 1) ? bk : bv;
    const float qs = (z == 0) ? 1.4426950408889634f * rsqrtf((float)EMB) : 1.0f;

    float acc[2][8][4];
    #pragma unroll
    for (int mi = 0; mi < 2; mi++)
        #pragma unroll
        for (int ni = 0; ni < 8; ni++)
            #pragma unroll
            for (int i = 0; i < 4; i++) acc[mi][ni][i] = 0.f;

    const uint32_t base = smem_u32(sm);
    const int brow = tid >> 1;
    const int bcol = (tid & 1) * 16;

    auto load_stage = [&](int s, int k0) {
        const __half* ah = xf + (size_t)(bm + tid) * EMB + k0;
        uint32_t dA = base + s * PA_ST + tid * 80;
        #pragma unroll
        for (int i = 0; i < 4; i++)
            cp16(dA + i * 16, ah + i * 8);
        const __half* bw = W + (size_t)(bn + brow) * EMB + k0 + bcol;
        uint32_t dB = base + 20480 + s * PB_ST + brow * 80 + bcol * 2;
        cp16(dB, bw); cp16(dB + 16, bw + 8);
    };

    const int rselA = lane & 15;
    const int cselA = (lane >> 4) << 3;
    const int rselB = (lane & 7) + ((lane >> 4) << 3);
    const int cselB = ((lane >> 3) & 1) << 3;
    const uint32_t bA = base + (wid * 32 + rselA) * 80 + cselA * 2;
    const uint32_t bB = base + 20480 + rselB * 80 + cselB * 2;

    load_stage(0, 0);
    CP_COMMIT();

    const int NIT = EMB / 32;  // 24
    #pragma unroll 1
    for (int it = 0; it < NIT; it++) {
        const int cur = it & 1;
        if (it + 1 < NIT) {
            load_stage(cur ^ 1, (it + 1) * 32);
            CP_COMMIT();
            CP_WAIT1();
        } else {
            CP_WAIT0();
        }
        __syncthreads();

        const uint32_t cA = bA + cur * PA_ST;
        const uint32_t cB = bB + cur * PB_ST;

        #pragma unroll
        for (int ks = 0; ks < 32; ks += 16) {
            uint32_t fa[2][4];
            #pragma unroll
            for (int mi = 0; mi < 2; mi++) {
                const uint32_t off = (uint32_t)(mi * 16 * 80 + ks * 2);
                ldsm_x4(fa[mi][0], fa[mi][1], fa[mi][2], fa[mi][3], cA + off);
            }
            #pragma unroll
            for (int nip = 0; nip < 4; nip++) {
                const uint32_t off = (uint32_t)(nip * 16 * 80 + ks * 2);
                uint32_t h0, h1, h2, h3;
                ldsm_x4(h0, h1, h2, h3, cB + off);
                #pragma unroll
                for (int mi = 0; mi < 2; mi++) {
                    mma_f16(acc[mi][2 * nip],     fa[mi], h0, h1);
                    mma_f16(acc[mi][2 * nip + 1], fa[mi], h2, h3);
                }
            }
        }
        __syncthreads();
    }

    #pragma unroll
    for (int mi = 0; mi < 2; mi++) {
        const int r = bm + wid * 32 + mi * 16 + lq;
        #pragma unroll
        for (int ni = 0; ni < 8; ni++) {
            const int c = bn + ni * 8 + lk * 2;
            const float b0 = bias[c], b1 = bias[c + 1];
            float v0 = (acc[mi][ni][0] + b0) * qs;
            float v1 = (acc[mi][ni][1] + b1) * qs;
            float v2 = (acc[mi][ni][2] + b0) * qs;
            float v3 = (acc[mi][ni][3] + b1) * qs;
            const int hh = c >> 6, d = c & 63;
            const size_t i0 = ((size_t)hh * S_LEN + r) * HDIM + d;
            const size_t i1 = ((size_t)hh * S_LEN + r + 8) * HDIM + d;
            if (z == 0) {
                *(__half2*)&Qh[i0] = __floats2half2_rn(v0, v1);
                *(__half2*)&Qh[i1] = __floats2half2_rn(v2, v3);
            } else if (z == 1) {
                *(__half2*)&Kh[i0] = __floats2half2_rn(v0, v1);
                *(__half2*)&Kh[i1] = __floats2half2_rn(v2, v3);
            } else {
                Vh[(size_t)c * S_LEN + r]           = __float2half_rn(v0);
                Vh[(size_t)(c + 1) * S_LEN + r]     = __float2half_rn(v1);
                Vh[(size_t)c * S_LEN + r + 8]       = __float2half_rn(v2);
                Vh[(size_t)(c + 1) * S_LEN + r + 8] = __float2half_rn(v3);
            }
        }
    }
}

// ======== output GEMM: 2-term fp16 (A hi/lo exact, B fp16), fp32 out ====
#define QA_ST 10240
#define QB_ST 5120
#define Q_SMEM 51200

__global__ __launch_bounds__(128, 3) void gemm_out(
    const __half* __restrict__ Ah, const __half* __restrict__ Al,
    const __half* __restrict__ W,
    const float* __restrict__ bias, float* __restrict__ Cf)
{
    extern __shared__ char sm[];
    const int tid = threadIdx.x;
    const int wid = tid >> 5;
    const int lane = tid & 31;
    const int lq = lane >> 2;
    const int lk = lane & 3;
    const int bm = blockIdx.y * 128;
    const int bn = blockIdx.x * 64;

    float acc[2][8][4];
    #pragma unroll
    for (int mi = 0; mi < 2; mi++)
        #pragma unroll
        for (int ni = 0; ni < 8; ni++)
            #pragma unroll
            for (int i = 0; i < 4; i++) acc[mi][ni][i] = 0.f;

    const uint32_t base = smem_u32(sm);
    const int brow = tid >> 1;
    const int bcol = (tid & 1) * 16;

    auto load_stage = [&](int s, int k0) {
        const __half* ah = Ah + (size_t)(bm + tid) * EMB + k0;
        const __half* al = Al + (size_t)(bm + tid) * EMB + k0;
        uint32_t dA = base + s * QA_ST + tid * 80;
        #pragma unroll
        for (int i = 0; i < 4; i++) {
            cp16(dA + i * 16, ah + i * 8);
            cp16(dA + 20480 + i * 16, al + i * 8);
        }
        const __half* bw = W + (size_t)(bn + brow) * EMB + k0 + bcol;
        uint32_t dB = base + 40960 + s * QB_ST + brow * 80 + bcol * 2;
        cp16(dB, bw); cp16(dB + 16, bw + 8);
    };

    const int rselA = lane & 15;
    const int cselA = (lane >> 4) << 3;
    const int rselB = (lane & 7) + ((lane >> 4) << 3);
    const int cselB = ((lane >> 3) & 1) << 3;
    const uint32_t bAh = base + (wid * 32 + rselA) * 80 + cselA * 2;
    const uint32_t bB  = base + 40960 + rselB * 80 + cselB * 2;

    load_stage(0, 0);
    CP_COMMIT();

    const int NIT = EMB / 32;
    #pragma unroll 1
    for (int it = 0; it < NIT; it++) {
        const int cur = it & 1;
        if (it + 1 < NIT) {
            load_stage(cur ^ 1, (it + 1) * 32);
            CP_COMMIT();
            CP_WAIT1();
        } else {
            CP_WAIT0();
        }
        __syncthreads();

        const uint32_t cAh = bAh + cur * QA_ST;
        const uint32_t cAl = cAh + 20480;
        const uint32_t cB  = bB + cur * QB_ST;

        #pragma unroll
        for (int ks = 0; ks < 32; ks += 16) {
            uint32_t fah[2][4], fal[2][4];
            #pragma unroll
            for (int mi = 0; mi < 2; mi++) {
                const uint32_t off = (uint32_t)(mi * 16 * 80 + ks * 2);
                ldsm_x4(fah[mi][0], fah[mi][1], fah[mi][2], fah[mi][3], cAh + off);
                ldsm_x4(fal[mi][0], fal[mi][1], fal[mi][2], fal[mi][3], cAl + off);
            }
            #pragma unroll
            for (int nip = 0; nip < 4; nip++) {
                const uint32_t off = (uint32_t)(nip * 16 * 80 + ks * 2);
                uint32_t h0, h1, h2, h3;
                ldsm_x4(h0, h1, h2, h3, cB + off);
                #pragma unroll
                for (int mi = 0; mi < 2; mi++) {
                    mma_f16(acc[mi][2 * nip],     fah[mi], h0, h1);
                    mma_f16(acc[mi][2 * nip],     fal[mi], h0, h1);
                    mma_f16(acc[mi][2 * nip + 1], fah[mi], h2, h3);
                    mma_f16(acc[mi][2 * nip + 1], fal[mi], h2, h3);
                }
            }
        }
        __syncthreads();
    }

    #pragma unroll
    for (int mi = 0; mi < 2; mi++) {
        const int r = bm + wid * 32 + mi * 16 + lq;
        #pragma unroll
        for (int ni = 0; ni < 8; ni++) {
            const int c = bn + ni * 8 + lk * 2;
            const float b0 = bias[c], b1 = bias[c + 1];
            *(float2*)&Cf[(size_t)r * EMB + c] =
                make_float2(acc[mi][ni][0] + b0, acc[mi][ni][1] + b1);
            *(float2*)&Cf[(size_t)(r + 8) * EMB + c] =
                make_float2(acc[mi][ni][2] + b0, acc[mi][ni][3] + b1);
        }
    }
}

// ===== fp16 flash attention, key-split 3-way, streamed S->P, 3 CTAs/SM ===
// (identical to the 444us-passing R11 version)
// smem: K[3][64][72] @0 (9216/st), V[3][64][72] @27648, mask half[3][64] @55296
#define AT_ST 9216
#define A_V_OFF 27648
#define A_M_OFF 55296
#define A_SMEM 55680

__global__ __launch_bounds__(128, 3) void attn_mma(
    const __half* __restrict__ Qhf, const __half* __restrict__ Khf,
    const __half* __restrict__ Vhf,
    const unsigned char* __restrict__ mask,
    float* __restrict__ opart, float* __restrict__ lpart)
{
    extern __shared__ char sm[];
    const int h   = blockIdx.y;
    const int z   = blockIdx.z;                  // key split
    const int q0  = blockIdx.x * 128;
    const int tid = threadIdx.x;
    const int wid = tid >> 5;
    const int lane = tid & 31;
    const int lq = lane >> 2;
    const int lk = lane & 3;

    const int t0  = (z == 0) ? 0 : 22 + (z - 1) * 21;   // first key tile
    const int nit = (z == 0) ? 22 : 21;                 // tiles this split

    const size_t hoff = (size_t)h * S_LEN * HDIM;

    const int qr = q0 + wid * 32 + lq;
    uint32_t aQ[2][4][4];
    {
        const __half* Qhp = Qhf + hoff;
        #pragma unroll
        for (int mi = 0; mi < 2; mi++) {
            #pragma unroll
            for (int kc = 0; kc < 4; kc++) {
                const int c = kc * 16 + lk * 2;
                const size_t r0 = (size_t)(qr + mi * 16) * 64;
                const size_t r8 = (size_t)(qr + mi * 16 + 8) * 64;
                aQ[mi][kc][0] = *(const uint32_t*)&Qhp[r0 + c];
                aQ[mi][kc][1] = *(const uint32_t*)&Qhp[r8 + c];
                aQ[mi][kc][2] = *(const uint32_t*)&Qhp[r0 + c + 8];
                aQ[mi][kc][3] = *(const uint32_t*)&Qhp[r8 + c + 8];
            }
        }
    }

    const int rsel = (lane & 7) + ((lane >> 4) << 3);
    const int csel = ((lane >> 3) & 1) << 3;
    const uint32_t base = smem_u32(sm);
    const uint32_t bK = base + (rsel * 72 + csel) * 2;
    __half* smadd = (__half*)(sm + A_M_OFF);

    const int trow = tid >> 1;
    const int tcol = (tid & 1) * 32;

    auto load_tile = [&](int s, int k0) {
        const __half* kh = Khf + hoff + (size_t)(k0 + trow) * 64 + tcol;
        const __half* vh = Vhf + hoff + (size_t)trow * S_LEN + k0 + tcol;
        const uint32_t d = base + s * AT_ST + (trow * 72 + tcol) * 2;
        #pragma unroll
        for (int i = 0; i < 4; i++) {
            cp16(d + i * 16,           kh + i * 8);
            cp16(d + A_V_OFF + i * 16, vh + i * 8);
        }
        if (tid < 64)
            smadd[s * 64 + tid] = mask[k0 + tid] ? __float2half(-30000.f)
                                                 : __float2half(0.f);
    };

    float o[2][8][4];
    #pragma unroll
    for (int mi = 0; mi < 2; mi++)
        #pragma unroll
        for (int j = 0; j < 8; j++)
            #pragma unroll
            for (int i = 0; i < 4; i++) o[mi][j][i] = 0.f;
    float lsum[2][2] = {{0.f, 0.f}, {0.f, 0.f}};   // [m-tile][row half]

    load_tile(0, t0 * 64);
    CP_COMMIT();
    load_tile(1, (t0 + 1) * 64);
    CP_COMMIT();

    int cur = 0, nxt = 2;
    #pragma unroll 1
    for (int it = 0; it < nit; it++) {
        CP_WAIT1();
        __syncthreads();
        if (it + 2 < nit) {
            load_tile(nxt, (t0 + it + 2) * 64);
            CP_COMMIT();
        }

        const uint32_t cK = bK + cur * AT_ST;
        const uint32_t cV = cK + A_V_OFF;
        const __half2* md2 = (const __half2*)(smadd + cur * 64);

        // ---- streamed S -> P per 16-key group (keeps live regs low) ----
        uint32_t ph[2][4][4];
        #pragma unroll
        for (int jp = 0; jp < 4; jp++) {
            float st[2][2][4];
            #pragma unroll
            for (int mi = 0; mi < 2; mi++)
                #pragma unroll
                for (int half = 0; half < 2; half++)
                    st[mi][half][0] = st[mi][half][1] =
                    st[mi][half][2] = st[mi][half][3] = 0.f;

            #pragma unroll
            for (int kc = 0; kc < 4; kc++) {
                const uint32_t off = (uint32_t)(jp * 2304 + kc * 32);
                uint32_t h0, h1, h2, h3;
                ldsm_x4(h0, h1, h2, h3, cK + off);
                mma_f16(st[0][0], aQ[0][kc], h0, h1);
                mma_f16(st[0][1], aQ[0][kc], h2, h3);
                mma_f16(st[1][0], aQ[1][kc], h0, h1);
                mma_f16(st[1][1], aQ[1][kc], h2, h3);
            }

            const __half2 mv0 = md2[(2 * jp) * 4 + lk];
            const __half2 mv1 = md2[(2 * jp + 1) * 4 + lk];
            #pragma unroll
            for (int mi = 0; mi < 2; mi++) {
                __half2 a01 = __hadd2(__floats2half2_rn(st[mi][0][0], st[mi][0][1]), mv0);
                __half2 a23 = __hadd2(__floats2half2_rn(st[mi][0][2], st[mi][0][3]), mv0);
                __half2 b01 = __hadd2(__floats2half2_rn(st[mi][1][0], st[mi][1][1]), mv1);
                __half2 b23 = __hadd2(__floats2half2_rn(st[mi][1][2], st[mi][1][3]), mv1);
                ph[mi][jp][0] = ex2_h2(*(uint32_t*)&a01);
                ph[mi][jp][1] = ex2_h2(*(uint32_t*)&a23);
                ph[mi][jp][2] = ex2_h2(*(uint32_t*)&b01);
                ph[mi][jp][3] = ex2_h2(*(uint32_t*)&b23);
                uint32_t u0 = hadd2u(ph[mi][jp][0], ph[mi][jp][2]);
                uint32_t u1 = hadd2u(ph[mi][jp][1], ph[mi][jp][3]);
                float2 f0 = __half22float2(*(__half2*)&u0);
                float2 f1 = __half22float2(*(__half2*)&u1);
                lsum[mi][0] += f0.x + f0.y;
                lsum[mi][1] += f1.x + f1.y;
            }
        }

        // ---- O += P V ----
        #pragma unroll
        for (int jp = 0; jp < 4; jp++) {
            #pragma unroll
            for (int kc = 0; kc < 4; kc++) {
                const uint32_t off = (uint32_t)(jp * 2304 + kc * 32);
                uint32_t h0, h1, h2, h3;
                ldsm_x4(h0, h1, h2, h3, cV + off);
                mma_f16(o[0][2 * jp],     ph[0][kc], h0, h1);
                mma_f16(o[0][2 * jp + 1], ph[0][kc], h2, h3);
                mma_f16(o[1][2 * jp],     ph[1][kc], h0, h1);
                mma_f16(o[1][2 * jp + 1], ph[1][kc], h2, h3);
            }
        }

        cur = (cur == 2) ? 0 : cur + 1;
        nxt = (nxt == 2) ? 0 : nxt + 1;
    }

    // ---- epilogue: write UNNORMALIZED partials (fp32) + l ----
    float* opz = opart + (size_t)z * S_LEN * EMB;
    #pragma unroll
    for (int mi = 0; mi < 2; mi++) {
        lsum[mi][0] += __shfl_xor_sync(0xffffffffu, lsum[mi][0], 1);
        lsum[mi][0] += __shfl_xor_sync(0xffffffffu, lsum[mi][0], 2);
        lsum[mi][1] += __shfl_xor_sync(0xffffffffu, lsum[mi][1], 1);
        lsum[mi][1] += __shfl_xor_sync(0xffffffffu, lsum[mi][1], 2);
        const int r = qr + mi * 16;
        #pragma unroll
        for (int j = 0; j < 8; j++) {
            const int c = h * 64 + j * 8 + lk * 2;
            *(float2*)&opz[(size_t)r * EMB + c] =
                make_float2(o[mi][j][0], o[mi][j][1]);
            *(float2*)&opz[(size_t)(r + 8) * EMB + c] =
                make_float2(o[mi][j][2], o[mi][j][3]);
        }
        if (lk == 0) {
            lpart[((size_t)z * NHEAD + h) * S_LEN + r]     = lsum[mi][0];
            lpart[((size_t)z * NHEAD + h) * S_LEN + r + 8] = lsum[mi][1];
        }
    }
}

// ---- combine: out = (o0+o1+o2)/(l0+l1+l2), emit fp16 hi/lo ----
__global__ __launch_bounds__(256) void combine_kernel(
    const float* __restrict__ op, const float* __restrict__ lp,
    __half* __restrict__ Ohi, __half* __restrict__ Olo)
{
    const int i = blockIdx.x * 256 + threadIdx.x;   // float4 index
    if (i >= S_LEN * EMB / 4) return;
    const int e4 = i * 4;
    const int q = e4 / EMB;
    const int c = e4 % EMB;
    const int h = c >> 6;
    const float l = lp[(size_t)h * S_LEN + q]
                  + lp[((size_t)NHEAD + h) * S_LEN + q]
                  + lp[((size_t)2 * NHEAD + h) * S_LEN + q];
    const float inv = 1.0f / l;
    float4 o0 = ((const float4*)op)[i];
    float4 o1 = ((const float4*)(op + (size_t)S_LEN * EMB))[i];
    float4 o2 = ((const float4*)(op + 2 * (size_t)S_LEN * EMB))[i];
    const float v0 = (o0.x + o1.x + o2.x) * inv;
    const float v1 = (o0.y + o1.y + o2.y) * inv;
    const float v2 = (o0.z + o1.z + o2.z) * inv;
    const float v3 = (o0.w + o1.w + o2.w) * inv;
    __half2 h01 = __floats2half2_rn(v0, v1);
    __half2 h23 = __floats2half2_rn(v2, v3);
    float2 f01 = __half22float2(h01);
    float2 f23 = __half22float2(h23);
    ((__half2*)Ohi)[i * 2]     = h01;
    ((__half2*)Ohi)[i * 2 + 1] = h23;
    ((__half2*)Olo)[i * 2]     = __floats2half2_rn(v0 - f01.x, v1 - f01.y);
    ((__half2*)Olo)[i * 2 + 1] = __floats2half2_rn(v2 - f23.x, v3 - f23.y);
}

// ---------------- launch ----------------
extern "C" void kernel_launch(void* const* d_in, const int* in_sizes, int n_in,
                              void* d_out, int out_size)
{
    const float* x  = (const float*)d_in[0];
    const unsigned char* mask = (const unsigned char*)d_in[1];
    const float* Wq = (const float*)d_in[2];
    const float* bq = (const float*)d_in[3];
    const float* Wk = (const float*)d_in[4];
    const float* bk = (const float*)d_in[5];
    const float* Wv = (const float*)d_in[6];
    const float* bv = (const float*)d_in[7];
    const float* Wo = (const float*)d_in[8];
    const float* bo = (const float*)d_in[9];
    float* out = (float*)d_out;

    __half *xf, *wf, *Qh, *Kh, *Vh, *ath, *atl;
    float *opart, *lpart;
    cudaGetSymbolAddress((void**)&xf,  g_xf);
    cudaGetSymbolAddress((void**)&wf,  g_wf);
    cudaGetSymbolAddress((void**)&Qh, g_Qhf);
    cudaGetSymbolAddress((void**)&Kh, g_Khf);
    cudaGetSymbolAddress((void**)&Vh, g_Vhf);
    cudaGetSymbolAddress((void**)&opart, g_opart);
    cudaGetSymbolAddress((void**)&lpart, g_lpart);
    cudaGetSymbolAddress((void**)&ath, g_ath);
    cudaGetSymbolAddress((void**)&atl, g_atl);

    cudaFuncSetAttribute(gemm_qkv, cudaFuncAttributeMaxDynamicSharedMemorySize, P_SMEM);
    cudaFuncSetAttribute(gemm_out, cudaFuncAttributeMaxDynamicSharedMemorySize, Q_SMEM);
    cudaFuncSetAttribute(attn_mma, cudaFuncAttributeMaxDynamicSharedMemorySize, A_SMEM);

    const int nx4 = S_LEN * EMB / 4;
    const int nw4 = WW / 4;
    split_x_kernel<<<(nx4 + 255) / 256, 256>>>(x, xf, nx4);
    dim3 wgrid((nw4 + 255) / 256, 4);
    split_w_kernel<<<wgrid, 256>>>(Wq, Wk, Wv, Wo, wf, nw4);

    dim3 qgrid(EMB / 64, S_LEN / 128, 3);      // (12, 32, 3)
    gemm_qkv<<<qgrid, 128, P_SMEM>>>(xf, wf, bq, bk, bv, Qh, Kh, Vh);

    dim3 agrid(S_LEN / 128, NHEAD, NSPLIT);    // (32, 12, 3)
    attn_mma<<<agrid, 128, A_SMEM>>>(Qh, Kh, Vh, mask, opart, lpart);

    const int nc = S_LEN * EMB / 4;
    combine_kernel<<<(nc + 255) / 256, 256>>>(opart, lpart, ath, atl);

    dim3 ogrid(EMB / 64, S_LEN / 128);         // (12, 32)
    gemm_out<<<ogrid, 128, Q_SMEM>>>(ath, atl, wf + 3 * WW, bo, out);
}

// round 17
// speedup vs baseline: 8.9427x; 1.0829x over previous
#include <cuda_runtime.h>
#include <cuda_bf16.h>
#include <cuda_fp16.h>
#include <cstdint>

#define S_LEN 4096
#define EMB   768
#define NHEAD 12
#define HDIM  64
#define WW    (EMB * EMB)
#define NSPLIT 3

// ---------------- scratch (no allocations allowed) ----------------
__device__ __half g_xf[S_LEN * EMB];             // x fp16
__device__ __half g_wf[4][WW];                   // Wq/Wk/Wv/Wo fp16
__device__ __half g_Qhf[NHEAD * S_LEN * HDIM];   // [H][S][D] fp16, pre-scaled log2e/sqrt(E)
__device__ __half g_Khf[NHEAD * S_LEN * HDIM];   // [H][S][D] fp16
__device__ __half g_Vhf[NHEAD * HDIM * S_LEN];   // [H][D][S] fp16 (transposed)
__device__ float  g_opart[NSPLIT * S_LEN * EMB]; // unnormalized O partials (fp32)
__device__ float  g_lpart[NSPLIT * NHEAD * S_LEN];
__device__ __half g_ath[S_LEN * EMB];            // attn out fp16

__device__ __forceinline__ uint32_t smem_u32(const void* p)
{
    return (uint32_t)__cvta_generic_to_shared(p);
}

__device__ __forceinline__ void cp16(uint32_t saddr, const void* g)
{
    asm volatile("cp.async.cg.shared.global [%0], [%1], 16;" :: "r"(saddr), "l"(g));
}
#define CP_COMMIT() asm volatile("cp.async.commit_group;")
#define CP_WAIT1()  asm volatile("cp.async.wait_group 1;")
#define CP_WAIT0()  asm volatile("cp.async.wait_group 0;")

__device__ __forceinline__ void ldsm_x4(uint32_t& r0, uint32_t& r1,
                                        uint32_t& r2, uint32_t& r3, uint32_t addr)
{
    asm volatile("ldmatrix.sync.aligned.m8n8.x4.shared.b16 {%0,%1,%2,%3}, [%4];"
                 : "=r"(r0), "=r"(r1), "=r"(r2), "=r"(r3) : "r"(addr));
}

__device__ __forceinline__ void mma_f16(float* c, const uint32_t* a,
                                        uint32_t b0, uint32_t b1)
{
    asm volatile(
        "mma.sync.aligned.m16n8k16.row.col.f32.f16.f16.f32 "
        "{%0,%1,%2,%3},{%4,%5,%6,%7},{%8,%9},{%0,%1,%2,%3};"
        : "+f"(c[0]), "+f"(c[1]), "+f"(c[2]), "+f"(c[3])
        : "r"(a[0]), "r"(a[1]), "r"(a[2]), "r"(a[3]), "r"(b0), "r"(b1));
}

__device__ __forceinline__ uint32_t ex2_h2(uint32_t x)
{
    uint32_t r;
    asm("ex2.approx.f16x2 %0, %1;" : "=r"(r) : "r"(x));
    return r;
}

__device__ __forceinline__ uint32_t hadd2u(uint32_t a, uint32_t b)
{
    __half2 r = __hadd2(*(__half2*)&a, *(__half2*)&b);
    return *(uint32_t*)&r;
}

// ---------------- x: fp32 -> fp16 ----------------
__global__ __launch_bounds__(256) void split_x_kernel(
    const float* __restrict__ in, __half* __restrict__ hi, int n4)
{
    const int i = blockIdx.x * 256 + threadIdx.x;
    if (i >= n4) return;
    float4 v = ((const float4*)in)[i];
    __half2* hp = (__half2*)(hi + i * 4);
    hp[0] = __floats2half2_rn(v.x, v.y);
    hp[1] = __floats2half2_rn(v.z, v.w);
}

// all 4 weights -> fp16 (y selects matrix)
__global__ __launch_bounds__(256) void split_w_kernel(
    const float* __restrict__ w0, const float* __restrict__ w1,
    const float* __restrict__ w2, const float* __restrict__ w3,
    __half* __restrict__ wf, int n4)
{
    const int i = blockIdx.x * 256 + threadIdx.x;
    if (i >= n4) return;
    const int y = blockIdx.y;
    const float* src = (y == 0) ? w0 : (y == 1) ? w1 : (y == 2) ? w2 : w3;
    float4 v = ((const float4*)src)[i];
    __half2* p = (__half2*)(wf + (size_t)y * WW + i * 4);
    p[0] = __floats2half2_rn(v.x, v.y);
    p[1] = __floats2half2_rn(v.z, v.w);
}

// ========== 1-term fp16 GEMM mainloop (A fp16, B fp16) ===================
// smem: sA[2][128][40] @0 (10240/st), sB[2][64][40] @20480 (5120/st)
#define PA_ST 10240
#define PB_ST 5120
#define P_SMEM 30720

__device__ __forceinline__ void gemm1_mainloop(
    char* sm, const __half* __restrict__ A, const __half* __restrict__ W,
    int bm, int bn, int tid, int wid, int lane, float acc[2][8][4])
{
    #pragma unroll
    for (int mi = 0; mi < 2; mi++)
        #pragma unroll
        for (int ni = 0; ni < 8; ni++)
            #pragma unroll
            for (int i = 0; i < 4; i++) acc[mi][ni][i] = 0.f;

    const uint32_t base = smem_u32(sm);
    const int brow = tid >> 1;
    const int bcol = (tid & 1) * 16;

    auto load_stage = [&](int s, int k0) {
        const __half* ah = A + (size_t)(bm + tid) * EMB + k0;
        uint32_t dA = base + s * PA_ST + tid * 80;
        #pragma unroll
        for (int i = 0; i < 4; i++)
            cp16(dA + i * 16, ah + i * 8);
        const __half* bw = W + (size_t)(bn + brow) * EMB + k0 + bcol;
        uint32_t dB = base + 20480 + s * PB_ST + brow * 80 + bcol * 2;
        cp16(dB, bw); cp16(dB + 16, bw + 8);
    };

    const int rselA = lane & 15;
    const int cselA = (lane >> 4) << 3;
    const int rselB = (lane & 7) + ((lane >> 4) << 3);
    const int cselB = ((lane >> 3) & 1) << 3;
    const uint32_t bA = base + (wid * 32 + rselA) * 80 + cselA * 2;
    const uint32_t bB = base + 20480 + rselB * 80 + cselB * 2;

    load_stage(0, 0);
    CP_COMMIT();

    const int NIT = EMB / 32;  // 24
    #pragma unroll 1
    for (int it = 0; it < NIT; it++) {
        const int cur = it & 1;
        if (it + 1 < NIT) {
            load_stage(cur ^ 1, (it + 1) * 32);
            CP_COMMIT();
            CP_WAIT1();
        } else {
            CP_WAIT0();
        }
        __syncthreads();

        const uint32_t cA = bA + cur * PA_ST;
        const uint32_t cB = bB + cur * PB_ST;

        #pragma unroll
        for (int ks = 0; ks < 32; ks += 16) {
            uint32_t fa[2][4];
            #pragma unroll
            for (int mi = 0; mi < 2; mi++) {
                const uint32_t off = (uint32_t)(mi * 16 * 80 + ks * 2);
                ldsm_x4(fa[mi][0], fa[mi][1], fa[mi][2], fa[mi][3], cA + off);
            }
            #pragma unroll
            for (int nip = 0; nip < 4; nip++) {
                const uint32_t off = (uint32_t)(nip * 16 * 80 + ks * 2);
                uint32_t h0, h1, h2, h3;
                ldsm_x4(h0, h1, h2, h3, cB + off);
                #pragma unroll
                for (int mi = 0; mi < 2; mi++) {
                    mma_f16(acc[mi][2 * nip],     fa[mi], h0, h1);
                    mma_f16(acc[mi][2 * nip + 1], fa[mi], h2, h3);
                }
            }
        }
        __syncthreads();
    }
}

// QKV projection: grid (12, 32, 3); z: 0=Q (fp16, pre-scaled), 1=K, 2=V (T)
__global__ __launch_bounds__(128, 4) void gemm_qkv(
    const __half* __restrict__ xf, const __half* __restrict__ wf,
    const float* __restrict__ bq, const float* __restrict__ bk,
    const float* __restrict__ bv,
    __half* __restrict__ Qh, __half* __restrict__ Kh, __half* __restrict__ Vh)
{
    extern __shared__ char sm[];
    const int z = blockIdx.z;
    const int tid = threadIdx.x;
    const int wid = tid >> 5;
    const int lane = tid & 31;
    const int lq = lane >> 2;
    const int lk = lane & 3;
    const int bm = blockIdx.y * 128;
    const int bn = blockIdx.x * 64;

    const __half* W = wf + (size_t)z * WW;
    const float* bias = (z == 0) ? bq : (z == 1) ? bk : bv;
    const float qs = (z == 0) ? 1.4426950408889634f * rsqrtf((float)EMB) : 1.0f;

    float acc[2][8][4];
    gemm1_mainloop(sm, xf, W, bm, bn, tid, wid, lane, acc);

    #pragma unroll
    for (int mi = 0; mi < 2; mi++) {
        const int r = bm + wid * 32 + mi * 16 + lq;
        #pragma unroll
        for (int ni = 0; ni < 8; ni++) {
            const int c = bn + ni * 8 + lk * 2;
            const float b0 = bias[c], b1 = bias[c + 1];
            float v0 = (acc[mi][ni][0] + b0) * qs;
            float v1 = (acc[mi][ni][1] + b1) * qs;
            float v2 = (acc[mi][ni][2] + b0) * qs;
            float v3 = (acc[mi][ni][3] + b1) * qs;
            const int hh = c >> 6, d = c & 63;
            const size_t i0 = ((size_t)hh * S_LEN + r) * HDIM + d;
            const size_t i1 = ((size_t)hh * S_LEN + r + 8) * HDIM + d;
            if (z == 0) {
                *(__half2*)&Qh[i0] = __floats2half2_rn(v0, v1);
                *(__half2*)&Qh[i1] = __floats2half2_rn(v2, v3);
            } else if (z == 1) {
                *(__half2*)&Kh[i0] = __floats2half2_rn(v0, v1);
                *(__half2*)&Kh[i1] = __floats2half2_rn(v2, v3);
            } else {
                Vh[(size_t)c * S_LEN + r]           = __float2half_rn(v0);
                Vh[(size_t)(c + 1) * S_LEN + r]     = __float2half_rn(v1);
                Vh[(size_t)c * S_LEN + r + 8]       = __float2half_rn(v2);
                Vh[(size_t)(c + 1) * S_LEN + r + 8] = __float2half_rn(v3);
            }
        }
    }
}

// Output projection: 1-term fp16 A (attn out), fp32 result
__global__ __launch_bounds__(128, 4) void gemm_out(
    const __half* __restrict__ A, const __half* __restrict__ W,
    const float* __restrict__ bias, float* __restrict__ Cf)
{
    extern __shared__ char sm[];
    const int tid = threadIdx.x;
    const int wid = tid >> 5;
    const int lane = tid & 31;
    const int lq = lane >> 2;
    const int lk = lane & 3;
    const int bm = blockIdx.y * 128;
    const int bn = blockIdx.x * 64;

    float acc[2][8][4];
    gemm1_mainloop(sm, A, W, bm, bn, tid, wid, lane, acc);

    #pragma unroll
    for (int mi = 0; mi < 2; mi++) {
        const int r = bm + wid * 32 + mi * 16 + lq;
        #pragma unroll
        for (int ni = 0; ni < 8; ni++) {
            const int c = bn + ni * 8 + lk * 2;
            const float b0 = bias[c], b1 = bias[c + 1];
            *(float2*)&Cf[(size_t)r * EMB + c] =
                make_float2(acc[mi][ni][0] + b0, acc[mi][ni][1] + b1);
            *(float2*)&Cf[(size_t)(r + 8) * EMB + c] =
                make_float2(acc[mi][ni][2] + b0, acc[mi][ni][3] + b1);
        }
    }
}

// ===== fp16 flash attention, key-split 3-way, streamed S->P, 3 CTAs/SM ===
// (identical to the 375us-passing version)
// smem: K[3][64][72] @0 (9216/st), V[3][64][72] @27648, mask half[3][64] @55296
#define AT_ST 9216
#define A_V_OFF 27648
#define A_M_OFF 55296
#define A_SMEM 55680

__global__ __launch_bounds__(128, 3) void attn_mma(
    const __half* __restrict__ Qhf, const __half* __restrict__ Khf,
    const __half* __restrict__ Vhf,
    const unsigned char* __restrict__ mask,
    float* __restrict__ opart, float* __restrict__ lpart)
{
    extern __shared__ char sm[];
    const int h   = blockIdx.y;
    const int z   = blockIdx.z;                  // key split
    const int q0  = blockIdx.x * 128;
    const int tid = threadIdx.x;
    const int wid = tid >> 5;
    const int lane = tid & 31;
    const int lq = lane >> 2;
    const int lk = lane & 3;

    const int t0  = (z == 0) ? 0 : 22 + (z - 1) * 21;   // first key tile
    const int nit = (z == 0) ? 22 : 21;                 // tiles this split

    const size_t hoff = (size_t)h * S_LEN * HDIM;

    const int qr = q0 + wid * 32 + lq;
    uint32_t aQ[2][4][4];
    {
        const __half* Qhp = Qhf + hoff;
        #pragma unroll
        for (int mi = 0; mi < 2; mi++) {
            #pragma unroll
            for (int kc = 0; kc < 4; kc++) {
                const int c = kc * 16 + lk * 2;
                const size_t r0 = (size_t)(qr + mi * 16) * 64;
                const size_t r8 = (size_t)(qr + mi * 16 + 8) * 64;
                aQ[mi][kc][0] = *(const uint32_t*)&Qhp[r0 + c];
                aQ[mi][kc][1] = *(const uint32_t*)&Qhp[r8 + c];
                aQ[mi][kc][2] = *(const uint32_t*)&Qhp[r0 + c + 8];
                aQ[mi][kc][3] = *(const uint32_t*)&Qhp[r8 + c + 8];
            }
        }
    }

    const int rsel = (lane & 7) + ((lane >> 4) << 3);
    const int csel = ((lane >> 3) & 1) << 3;
    const uint32_t base = smem_u32(sm);
    const uint32_t bK = base + (rsel * 72 + csel) * 2;
    __half* smadd = (__half*)(sm + A_M_OFF);

    const int trow = tid >> 1;
    const int tcol = (tid & 1) * 32;

    auto load_tile = [&](int s, int k0) {
        const __half* kh = Khf + hoff + (size_t)(k0 + trow) * 64 + tcol;
        const __half* vh = Vhf + hoff + (size_t)trow * S_LEN + k0 + tcol;
        const uint32_t d = base + s * AT_ST + (trow * 72 + tcol) * 2;
        #pragma unroll
        for (int i = 0; i < 4; i++) {
            cp16(d + i * 16,           kh + i * 8);
            cp16(d + A_V_OFF + i * 16, vh + i * 8);
        }
        if (tid < 64)
            smadd[s * 64 + tid] = mask[k0 + tid] ? __float2half(-30000.f)
                                                 : __float2half(0.f);
    };

    float o[2][8][4];
    #pragma unroll
    for (int mi = 0; mi < 2; mi++)
        #pragma unroll
        for (int j = 0; j < 8; j++)
            #pragma unroll
            for (int i = 0; i < 4; i++) o[mi][j][i] = 0.f;
    float lsum[2][2] = {{0.f, 0.f}, {0.f, 0.f}};   // [m-tile][row half]

    load_tile(0, t0 * 64);
    CP_COMMIT();
    load_tile(1, (t0 + 1) * 64);
    CP_COMMIT();

    int cur = 0, nxt = 2;
    #pragma unroll 1
    for (int it = 0; it < nit; it++) {
        CP_WAIT1();
        __syncthreads();
        if (it + 2 < nit) {
            load_tile(nxt, (t0 + it + 2) * 64);
            CP_COMMIT();
        }

        const uint32_t cK = bK + cur * AT_ST;
        const uint32_t cV = cK + A_V_OFF;
        const __half2* md2 = (const __half2*)(smadd + cur * 64);

        // ---- streamed S -> P per 16-key group (keeps live regs low) ----
        uint32_t ph[2][4][4];
        #pragma unroll
        for (int jp = 0; jp < 4; jp++) {
            float st[2][2][4];
            #pragma unroll
            for (int mi = 0; mi < 2; mi++)
                #pragma unroll
                for (int half = 0; half < 2; half++)
                    st[mi][half][0] = st[mi][half][1] =
                    st[mi][half][2] = st[mi][half][3] = 0.f;

            #pragma unroll
            for (int kc = 0; kc < 4; kc++) {
                const uint32_t off = (uint32_t)(jp * 2304 + kc * 32);
                uint32_t h0, h1, h2, h3;
                ldsm_x4(h0, h1, h2, h3, cK + off);
                mma_f16(st[0][0], aQ[0][kc], h0, h1);
                mma_f16(st[0][1], aQ[0][kc], h2, h3);
                mma_f16(st[1][0], aQ[1][kc], h0, h1);
                mma_f16(st[1][1], aQ[1][kc], h2, h3);
            }

            const __half2 mv0 = md2[(2 * jp) * 4 + lk];
            const __half2 mv1 = md2[(2 * jp + 1) * 4 + lk];
            #pragma unroll
            for (int mi = 0; mi < 2; mi++) {
                __half2 a01 = __hadd2(__floats2half2_rn(st[mi][0][0], st[mi][0][1]), mv0);
                __half2 a23 = __hadd2(__floats2half2_rn(st[mi][0][2], st[mi][0][3]), mv0);
                __half2 b01 = __hadd2(__floats2half2_rn(st[mi][1][0], st[mi][1][1]), mv1);
                __half2 b23 = __hadd2(__floats2half2_rn(st[mi][1][2], st[mi][1][3]), mv1);
                ph[mi][jp][0] = ex2_h2(*(uint32_t*)&a01);
                ph[mi][jp][1] = ex2_h2(*(uint32_t*)&a23);
                ph[mi][jp][2] = ex2_h2(*(uint32_t*)&b01);
                ph[mi][jp][3] = ex2_h2(*(uint32_t*)&b23);
                uint32_t u0 = hadd2u(ph[mi][jp][0], ph[mi][jp][2]);
                uint32_t u1 = hadd2u(ph[mi][jp][1], ph[mi][jp][3]);
                float2 f0 = __half22float2(*(__half2*)&u0);
                float2 f1 = __half22float2(*(__half2*)&u1);
                lsum[mi][0] += f0.x + f0.y;
                lsum[mi][1] += f1.x + f1.y;
            }
        }

        // ---- O += P V ----
        #pragma unroll
        for (int jp = 0; jp < 4; jp++) {
            #pragma unroll
            for (int kc = 0; kc < 4; kc++) {
                const uint32_t off = (uint32_t)(jp * 2304 + kc * 32);
                uint32_t h0, h1, h2, h3;
                ldsm_x4(h0, h1, h2, h3, cV + off);
                mma_f16(o[0][2 * jp],     ph[0][kc], h0, h1);
                mma_f16(o[0][2 * jp + 1], ph[0][kc], h2, h3);
                mma_f16(o[1][2 * jp],     ph[1][kc], h0, h1);
                mma_f16(o[1][2 * jp + 1], ph[1][kc], h2, h3);
            }
        }

        cur = (cur == 2) ? 0 : cur + 1;
        nxt = (nxt == 2) ? 0 : nxt + 1;
    }

    // ---- epilogue: write UNNORMALIZED partials (fp32) + l ----
    float* opz = opart + (size_t)z * S_LEN * EMB;
    #pragma unroll
    for (int mi = 0; mi < 2; mi++) {
        lsum[mi][0] += __shfl_xor_sync(0xffffffffu, lsum[mi][0], 1);
        lsum[mi][0] += __shfl_xor_sync(0xffffffffu, lsum[mi][0], 2);
        lsum[mi][1] += __shfl_xor_sync(0xffffffffu, lsum[mi][1], 1);
        lsum[mi][1] += __shfl_xor_sync(0xffffffffu, lsum[mi][1], 2);
        const int r = qr + mi * 16;
        #pragma unroll
        for (int j = 0; j < 8; j++) {
            const int c = h * 64 + j * 8 + lk * 2;
            *(float2*)&opz[(size_t)r * EMB + c] =
                make_float2(o[mi][j][0], o[mi][j][1]);
            *(float2*)&opz[(size_t)(r + 8) * EMB + c] =
                make_float2(o[mi][j][2], o[mi][j][3]);
        }
        if (lk == 0) {
            lpart[((size_t)z * NHEAD + h) * S_LEN + r]     = lsum[mi][0];
            lpart[((size_t)z * NHEAD + h) * S_LEN + r + 8] = lsum[mi][1];
        }
    }
}

// ---- combine: out = (o0+o1+o2)/(l0+l1+l2), emit fp16 ----
__global__ __launch_bounds__(256) void combine_kernel(
    const float* __restrict__ op, const float* __restrict__ lp,
    __half* __restrict__ Ohi)
{
    const int i = blockIdx.x * 256 + threadIdx.x;   // float4 index
    if (i >= S_LEN * EMB / 4) return;
    const int e4 = i * 4;
    const int q = e4 / EMB;
    const int c = e4 % EMB;
    const int h = c >> 6;
    const float l = lp[(size_t)h * S_LEN + q]
                  + lp[((size_t)NHEAD + h) * S_LEN + q]
                  + lp[((size_t)2 * NHEAD + h) * S_LEN + q];
    const float inv = 1.0f / l;
    float4 o0 = ((const float4*)op)[i];
    float4 o1 = ((const float4*)(op + (size_t)S_LEN * EMB))[i];
    float4 o2 = ((const float4*)(op + 2 * (size_t)S_LEN * EMB))[i];
    const float v0 = (o0.x + o1.x + o2.x) * inv;
    const float v1 = (o0.y + o1.y + o2.y) * inv;
    const float v2 = (o0.z + o1.z + o2.z) * inv;
    const float v3 = (o0.w + o1.w + o2.w) * inv;
    ((__half2*)Ohi)[i * 2]     = __floats2half2_rn(v0, v1);
    ((__half2*)Ohi)[i * 2 + 1] = __floats2half2_rn(v2, v3);
}

// ---------------- launch ----------------
extern "C" void kernel_launch(void* const* d_in, const int* in_sizes, int n_in,
                              void* d_out, int out_size)
{
    const float* x  = (const float*)d_in[0];
    const unsigned char* mask = (const unsigned char*)d_in[1];
    const float* Wq = (const float*)d_in[2];
    const float* bq = (const float*)d_in[3];
    const float* Wk = (const float*)d_in[4];
    const float* bk = (const float*)d_in[5];
    const float* Wv = (const float*)d_in[6];
    const float* bv = (const float*)d_in[7];
    const float* Wo = (const float*)d_in[8];
    const float* bo = (const float*)d_in[9];
    float* out = (float*)d_out;

    __half *xf, *wf, *Qh, *Kh, *Vh, *ath;
    float *opart, *lpart;
    cudaGetSymbolAddress((void**)&xf,  g_xf);
    cudaGetSymbolAddress((void**)&wf,  g_wf);
    cudaGetSymbolAddress((void**)&Qh, g_Qhf);
    cudaGetSymbolAddress((void**)&Kh, g_Khf);
    cudaGetSymbolAddress((void**)&Vh, g_Vhf);
    cudaGetSymbolAddress((void**)&opart, g_opart);
    cudaGetSymbolAddress((void**)&lpart, g_lpart);
    cudaGetSymbolAddress((void**)&ath, g_ath);

    cudaFuncSetAttribute(gemm_qkv, cudaFuncAttributeMaxDynamicSharedMemorySize, P_SMEM);
    cudaFuncSetAttribute(gemm_out, cudaFuncAttributeMaxDynamicSharedMemorySize, P_SMEM);
    cudaFuncSetAttribute(attn_mma, cudaFuncAttributeMaxDynamicSharedMemorySize, A_SMEM);

    const int nx4 = S_LEN * EMB / 4;
    const int nw4 = WW / 4;
    split_x_kernel<<<(nx4 + 255) / 256, 256>>>(x, xf, nx4);
    dim3 wgrid((nw4 + 255) / 256, 4);
    split_w_kernel<<<wgrid, 256>>>(Wq, Wk, Wv, Wo, wf, nw4);

    dim3 qgrid(EMB / 64, S_LEN / 128, 3);      // (12, 32, 3)
    gemm_qkv<<<qgrid, 128, P_SMEM>>>(xf, wf, bq, bk, bv, Qh, Kh, Vh);

    dim3 agrid(S_LEN / 128, NHEAD, NSPLIT);    // (32, 12, 3)
    attn_mma<<<agrid, 128, A_SMEM>>>(Qh, Kh, Vh, mask, opart, lpart);

    const int nc = S_LEN * EMB / 4;
    combine_kernel<<<(nc + 255) / 256, 256>>>(opart, lpart, ath);

    dim3 ogrid(EMB / 64, S_LEN / 128);         // (12, 32)
    gemm_out<<<ogrid, 128, P_SMEM>>>(ath, wf + 3 * WW, bo, out);
}